// round 8
// baseline (speedup 1.0000x reference)
#include <cuda_runtime.h>
#include <cuda_bf16.h>
#include <cstdint>

#define NB   2
#define NC   256
#define NPIX 4096
#define CI   128
#define EPSV 1e-5f

typedef __nv_bfloat16 bf16;

__device__ bf16 g_Ehi [(size_t)NB * NPIX * NPIX];
__device__ bf16 g_Elo [(size_t)NB * NPIX * NPIX];
__device__ bf16 g_EThi[(size_t)NB * NPIX * NPIX];
__device__ bf16 g_ETlo[(size_t)NB * NPIX * NPIX];
__device__ bf16 g_VQhi[(size_t)NB * CI * NPIX];
__device__ bf16 g_VQlo[(size_t)NB * CI * NPIX];
__device__ bf16 g_VShi[(size_t)NB * CI * NPIX];
__device__ bf16 g_VSlo[(size_t)NB * CI * NPIX];
__device__ bf16 g_KThi[(size_t)NB * NPIX * CI];
__device__ bf16 g_KTlo[(size_t)NB * NPIX * CI];
__device__ bf16 g_QThi[(size_t)NB * NPIX * CI];
__device__ bf16 g_QTlo[(size_t)NB * NPIX * CI];
__device__ float g_ST [(size_t)NB * CI * NPIX];
__device__ float g_TQ [(size_t)NB * CI * NPIX];
__device__ float g_rowsum[NB * NPIX];
__device__ float g_colsum[NB * NPIX];
__device__ bf16 g_EQhi[(size_t)NB * CI * NPIX];
__device__ bf16 g_EQlo[(size_t)NB * CI * NPIX];
__device__ bf16 g_EShi[(size_t)NB * CI * NPIX];
__device__ bf16 g_ESlo[(size_t)NB * CI * NPIX];
__device__ bf16 g_W3hi[9 * 128 * 256];
__device__ bf16 g_W3lo[9 * 128 * 256];

// ---------------- helpers ----------------
__device__ __forceinline__ uint32_t smem_u32(const void* p) {
    uint32_t a;
    asm("{ .reg .u64 t; cvta.to.shared.u64 t, %1; cvt.u32.u64 %0, t; }" : "=r"(a) : "l"(p));
    return a;
}
__device__ __forceinline__ void cp16(uint32_t dst, const void* src) {
    asm volatile("cp.async.cg.shared.global [%0], [%1], 16;" :: "r"(dst), "l"(src));
}
#define CP_COMMIT() asm volatile("cp.async.commit_group;" ::: "memory")
#define CP_WAIT(n)  asm volatile("cp.async.wait_group %0;" :: "n"(n) : "memory")

__device__ __forceinline__ void mma_bf16(float* c, const uint32_t* a, uint32_t b0, uint32_t b1) {
    asm("mma.sync.aligned.m16n8k16.row.col.f32.bf16.bf16.f32 "
        "{%0,%1,%2,%3},{%4,%5,%6,%7},{%8,%9},{%0,%1,%2,%3};"
        : "+f"(c[0]), "+f"(c[1]), "+f"(c[2]), "+f"(c[3])
        : "r"(a[0]), "r"(a[1]), "r"(a[2]), "r"(a[3]), "r"(b0), "r"(b1));
}
__device__ __forceinline__ uint32_t split2(float x, float y, uint32_t& lo) {
    bf16 hx = __float2bfloat16(x), hy = __float2bfloat16(y);
    uint32_t hi = (uint32_t)__bfloat16_as_ushort(hx) | ((uint32_t)__bfloat16_as_ushort(hy) << 16);
    bf16 lx = __float2bfloat16(x - __bfloat162float(hx));
    bf16 ly = __float2bfloat16(y - __bfloat162float(hy));
    lo = (uint32_t)__bfloat16_as_ushort(lx) | ((uint32_t)__bfloat16_as_ushort(ly) << 16);
    return hi;
}

template<int ST>
__device__ __forceinline__ void mma_step(const uint32_t* Ahi, const uint32_t* Alo,
                                         const uint32_t* Bhi, const uint32_t* Blo,
                                         int kb, int wr, int wc, int g, int tg, float c[2][8][4])
{
    uint32_t ah[2][4], al[2][4];
    #pragma unroll
    for (int mt = 0; mt < 2; mt++) {
        int base = (wr + mt * 16 + g) * ST + kb + tg;
        ah[mt][0] = Ahi[base];          ah[mt][1] = Ahi[base + 8 * ST];
        ah[mt][2] = Ahi[base + 4];      ah[mt][3] = Ahi[base + 8 * ST + 4];
        al[mt][0] = Alo[base];          al[mt][1] = Alo[base + 8 * ST];
        al[mt][2] = Alo[base + 4];      al[mt][3] = Alo[base + 8 * ST + 4];
    }
    #pragma unroll
    for (int nt = 0; nt < 8; nt++) {
        int bb = (wc + nt * 8 + g) * ST + kb + tg;
        uint32_t bh0 = Bhi[bb], bh1 = Bhi[bb + 4];
        uint32_t bl0 = Blo[bb], bl1 = Blo[bb + 4];
        #pragma unroll
        for (int mt = 0; mt < 2; mt++) {
            mma_bf16(c[mt][nt], ah[mt], bh0, bh1);
            mma_bf16(c[mt][nt], al[mt], bh0, bh1);
            mma_bf16(c[mt][nt], ah[mt], bl0, bl1);
        }
    }
}

__global__ void zero_sums() {
    int i = blockIdx.x * 256 + threadIdx.x;
    if (i < NB * NPIX) { g_rowsum[i] = 0.f; g_colsum[i] = 0.f; }
}

__global__ void w3prep(const float* __restrict__ Wc) {
    int i = blockIdx.x * 256 + threadIdx.x;
    if (i >= 9 * 128 * 256) return;
    int tap = i >> 15, oc = (i >> 8) & 127, ic = i & 255;
    float v = Wc[(size_t)oc * 2304 + ic * 9 + tap];
    bf16 h = __float2bfloat16(v);
    g_W3hi[i] = h;
    g_W3lo[i] = __float2bfloat16(v - __bfloat162float(h));
}

// ============ gemmA: chunked K (occ 2/SM), shuffle sums ============
// per chunk: 4 planes x [128][36 u32] = 4 x 18432 = 73728 B; Tb[128][132] f32 aliases
#define GA_SMEM 73728
__global__ __launch_bounds__(256) void gemmA_mma()
{
    extern __shared__ char sm[];
    const int t = threadIdx.x, lane = t & 31, wid = t >> 5;
    const int g = lane >> 2, tg = lane & 3;
    const int b = blockIdx.z, n0 = blockIdx.x * 128, m0 = blockIdx.y * 128;
    const int wr = (wid & 3) * 32, wc = (wid >> 2) * 64;
    const bf16* A_hi = g_KThi + (size_t)b * NPIX * CI + (size_t)n0 * CI;
    const bf16* A_lo = g_KTlo + (size_t)b * NPIX * CI + (size_t)n0 * CI;
    const bf16* B_hi = g_QThi + (size_t)b * NPIX * CI + (size_t)m0 * CI;
    const bf16* B_lo = g_QTlo + (size_t)b * NPIX * CI + (size_t)m0 * CI;
    uint32_t sb = smem_u32(sm);

    float c[2][8][4] = {};
    #pragma unroll
    for (int kc = 0; kc < 2; kc++) {
        #pragma unroll
        for (int p = 0; p < 4; p++) {
            int i = t + p * 256;              // 0..1023
            int row = i >> 3, seg = i & 7;    // 8 x 16B = 128B = 64 bf16 per row
            size_t go = (size_t)row * CI + kc * 64 + seg * 8;
            uint32_t so = row * 144 + seg * 16;
            cp16(sb + so,         A_hi + go);
            cp16(sb + 18432 + so, A_lo + go);
            cp16(sb + 36864 + so, B_hi + go);
            cp16(sb + 55296 + so, B_lo + go);
        }
        CP_COMMIT();
        CP_WAIT(0);
        __syncthreads();
        const uint32_t* Ahi = (const uint32_t*)sm;
        const uint32_t* Alo = (const uint32_t*)(sm + 18432);
        const uint32_t* Bhi = (const uint32_t*)(sm + 36864);
        const uint32_t* Blo = (const uint32_t*)(sm + 55296);
        #pragma unroll
        for (int kb = 0; kb < 32; kb += 8)
            mma_step<36>(Ahi, Alo, Bhi, Blo, kb, wr, wc, g, tg, c);
        __syncthreads();
    }

    // exp in place
    #pragma unroll
    for (int mt = 0; mt < 2; mt++)
        #pragma unroll
        for (int nt = 0; nt < 8; nt++)
            #pragma unroll
            for (int i = 0; i < 4; i++)
                c[mt][nt][i] = __expf(c[mt][nt][i]);

    // row sums: reduce over tg (warp's 64 cols), atomic per row
    #pragma unroll
    for (int mt = 0; mt < 2; mt++)
        #pragma unroll
        for (int h = 0; h < 2; h++) {
            float v = 0.f;
            #pragma unroll
            for (int nt = 0; nt < 8; nt++) v += c[mt][nt][2 * h] + c[mt][nt][2 * h + 1];
            v += __shfl_xor_sync(0xffffffffu, v, 1);
            v += __shfl_xor_sync(0xffffffffu, v, 2);
            if (tg == 0) atomicAdd(g_rowsum + b * NPIX + n0 + wr + mt * 16 + g + 8 * h, v);
        }
    // col sums: reduce over g (warp's 32 rows), atomic per col
    #pragma unroll
    for (int nt = 0; nt < 8; nt++)
        #pragma unroll
        for (int jj = 0; jj < 2; jj++) {
            float v = c[0][nt][jj] + c[0][nt][2 + jj] + c[1][nt][jj] + c[1][nt][2 + jj];
            v += __shfl_xor_sync(0xffffffffu, v, 4);
            v += __shfl_xor_sync(0xffffffffu, v, 8);
            v += __shfl_xor_sync(0xffffffffu, v, 16);
            if (g == 0) atomicAdd(g_colsum + b * NPIX + m0 + wc + nt * 8 + tg * 2 + jj, v);
        }

    float* Tb = (float*)sm;    // [128][132]
    #pragma unroll
    for (int mt = 0; mt < 2; mt++)
        #pragma unroll
        for (int nt = 0; nt < 8; nt++)
            #pragma unroll
            for (int i = 0; i < 4; i++) {
                int row = wr + mt * 16 + g + (i >> 1) * 8;
                int col = wc + nt * 8 + tg * 2 + (i & 1);
                Tb[row * 132 + col] = c[mt][nt][i];
            }
    __syncthreads();

    bf16* Ehi  = g_Ehi  + (size_t)b * NPIX * NPIX;
    bf16* Elo  = g_Elo  + (size_t)b * NPIX * NPIX;
    bf16* EThi = g_EThi + (size_t)b * NPIX * NPIX;
    bf16* ETlo = g_ETlo + (size_t)b * NPIX * NPIX;

    for (int i = t; i < 2048; i += 256) {
        int r = i >> 4, cg = (i & 15) * 8;
        uint4 hv, lv;
        hv.x = split2(Tb[r * 132 + cg + 0], Tb[r * 132 + cg + 1], lv.x);
        hv.y = split2(Tb[r * 132 + cg + 2], Tb[r * 132 + cg + 3], lv.y);
        hv.z = split2(Tb[r * 132 + cg + 4], Tb[r * 132 + cg + 5], lv.z);
        hv.w = split2(Tb[r * 132 + cg + 6], Tb[r * 132 + cg + 7], lv.w);
        size_t gi = (size_t)(n0 + r) * NPIX + m0 + cg;
        *(uint4*)(Ehi + gi) = hv;
        *(uint4*)(Elo + gi) = lv;
    }
    for (int i = t; i < 2048; i += 256) {
        int cl = i >> 4, rq = (i & 15) * 8;
        uint4 hv, lv;
        hv.x = split2(Tb[(rq + 0) * 132 + cl], Tb[(rq + 1) * 132 + cl], lv.x);
        hv.y = split2(Tb[(rq + 2) * 132 + cl], Tb[(rq + 3) * 132 + cl], lv.y);
        hv.z = split2(Tb[(rq + 4) * 132 + cl], Tb[(rq + 5) * 132 + cl], lv.z);
        hv.w = split2(Tb[(rq + 6) * 132 + cl], Tb[(rq + 7) * 132 + cl], lv.w);
        size_t gi = (size_t)(m0 + cl) * NPIX + n0 + rq;
        *(uint4*)(EThi + gi) = hv;
        *(uint4*)(ETlo + gi) = lv;
    }
}

// ============ pv ============
#define PV_SMEM 147968
__global__ __launch_bounds__(256) void pv_mma(const float* __restrict__ scale_p,
                                              float* __restrict__ outEq,
                                              float* __restrict__ outEs)
{
    extern __shared__ char sm[];
    const int t = threadIdx.x, lane = t & 31, wid = t >> 5;
    const int g = lane >> 2, tg = lane & 3;
    const int r0 = blockIdx.x * 128, b = blockIdx.y, mode = blockIdx.z;
    const int wr = (wid & 3) * 32, wc = (wid >> 2) * 64;
    const bf16* A_hi = (mode ? g_EThi : g_Ehi) + (size_t)b * NPIX * NPIX + (size_t)r0 * NPIX;
    const bf16* A_lo = (mode ? g_ETlo : g_Elo) + (size_t)b * NPIX * NPIX + (size_t)r0 * NPIX;
    const bf16* B_hi = (mode ? g_VQhi : g_VShi) + (size_t)b * CI * NPIX;
    const bf16* B_lo = (mode ? g_VQlo : g_VSlo) + (size_t)b * CI * NPIX;
    const float* sums = (mode ? g_colsum : g_rowsum) + (size_t)b * NPIX + r0;
    const float* T = (mode ? g_TQ : g_ST) + (size_t)b * CI * NPIX;
    float* outp = (mode ? outEq : outEs) + (size_t)b * CI * NPIX;
    bf16* Fh = (mode ? g_EQhi : g_EShi) + (size_t)b * CI * NPIX;
    bf16* Fl = (mode ? g_EQlo : g_ESlo) + (size_t)b * CI * NPIX;
    uint32_t sb = smem_u32(sm);
    float* RS = (float*)(sm + 147456);
    if (t < 128) RS[t] = scale_p[0] / sums[t];

    #pragma unroll
    for (int p = 0; p < 4; p++) {
        int i = t + p * 256;
        int row = i >> 3, seg = i & 7;
        size_t go = (size_t)row * NPIX + seg * 8;
        uint32_t so = row * 144 + seg * 16;
        cp16(sb + so,         A_hi + go);
        cp16(sb + 18432 + so, A_lo + go);
        cp16(sb + 36864 + so, B_hi + go);
        cp16(sb + 55296 + so, B_lo + go);
    }
    CP_COMMIT();

    float c[2][8][4] = {};
    for (int kc = 0; kc < 64; kc++) {
        const int st = kc & 1;
        if (kc + 1 < 64) {
            const int st2 = (kc + 1) & 1;
            #pragma unroll
            for (int p = 0; p < 4; p++) {
                int i = t + p * 256;
                int row = i >> 3, seg = i & 7;
                size_t go = (size_t)row * NPIX + (kc + 1) * 64 + seg * 8;
                uint32_t so = st2 * 73728 + row * 144 + seg * 16;
                cp16(sb + so,         A_hi + go);
                cp16(sb + 18432 + so, A_lo + go);
                cp16(sb + 36864 + so, B_hi + go);
                cp16(sb + 55296 + so, B_lo + go);
            }
            CP_COMMIT();
            CP_WAIT(1);
        } else {
            CP_WAIT(0);
        }
        __syncthreads();
        const uint32_t* Ahi = (const uint32_t*)(sm + st * 73728);
        const uint32_t* Alo = (const uint32_t*)(sm + st * 73728 + 18432);
        const uint32_t* Bhi = (const uint32_t*)(sm + st * 73728 + 36864);
        const uint32_t* Blo = (const uint32_t*)(sm + st * 73728 + 55296);
        #pragma unroll
        for (int kb = 0; kb < 32; kb += 8)
            mma_step<36>(Ahi, Alo, Bhi, Blo, kb, wr, wc, g, tg, c);
        __syncthreads();
    }

    float* Tb = (float*)sm;
    #pragma unroll
    for (int mt = 0; mt < 2; mt++)
        #pragma unroll
        for (int nt = 0; nt < 8; nt++)
            #pragma unroll
            for (int i = 0; i < 4; i++) {
                int row = wr + mt * 16 + g + (i >> 1) * 8;
                int col = wc + nt * 8 + tg * 2 + (i & 1);
                Tb[row * 132 + col] = c[mt][nt][i] * RS[row];
            }
    __syncthreads();
    for (int i = t; i < 16384; i += 256) {
        int cl = i >> 7, r = i & 127;
        size_t gi = (size_t)cl * NPIX + r0 + r;
        float v = Tb[r * 132 + cl] + T[gi];
        outp[gi] = v;
        bf16 h = __float2bfloat16(v);
        Fh[gi] = h;
        Fl[gi] = __float2bfloat16(v - __bfloat162float(h));
    }
}

// ---------------- fused conv1x1: 12 jobs ----------------
__global__ __launch_bounds__(256) void convs_kernel(
    const float* __restrict__ q, const float* __restrict__ s,
    const float* __restrict__ w_v,  const float* __restrict__ b_v,
    const float* __restrict__ w_k1, const float* __restrict__ b_k1,
    const float* __restrict__ w_q1, const float* __restrict__ b_q1,
    const float* __restrict__ w_k2, const float* __restrict__ b_k2,
    const float* __restrict__ w_q2, const float* __restrict__ b_q2,
    const float* __restrict__ w_ts, const float* __restrict__ b_ts,
    const float* __restrict__ gts,  const float* __restrict__ bets,
    const float* __restrict__ mts,  const float* __restrict__ vts,
    const float* __restrict__ w_tq, const float* __restrict__ b_tq,
    const float* __restrict__ gtq,  const float* __restrict__ betq,
    const float* __restrict__ mtq,  const float* __restrict__ vtq)
{
    const int j = blockIdx.z, b = blockIdx.y, n0 = blockIdx.x * 128;
    const float *X, *W, *Bi, *bg = nullptr, *bb = nullptr, *bm = nullptr, *bv = nullptr;
    bf16 *dh = nullptr, *dl = nullptr;
    float* df = nullptr;
    int ocb = 0, co = 0; bool chanmaj = true, hasbn = false;
    switch (j) {
        case 0:  X = q; W = w_v;  Bi = b_v;  dh = g_VQhi; dl = g_VQlo; ocb = 0;  co = 0;  break;
        case 1:  X = q; W = w_v;  Bi = b_v;  dh = g_VQhi; dl = g_VQlo; ocb = 64; co = 64; break;
        case 2:  X = s; W = w_v;  Bi = b_v;  dh = g_VShi; dl = g_VSlo; ocb = 0;  co = 0;  break;
        case 3:  X = s; W = w_v;  Bi = b_v;  dh = g_VShi; dl = g_VSlo; ocb = 64; co = 64; break;
        case 4:  X = q; W = w_k1; Bi = b_k1; dh = g_KThi; dl = g_KTlo; chanmaj = false; co = 0;  break;
        case 5:  X = s; W = w_k2; Bi = b_k2; dh = g_KThi; dl = g_KTlo; chanmaj = false; co = 64; break;
        case 6:  X = q; W = w_q1; Bi = b_q1; dh = g_QThi; dl = g_QTlo; chanmaj = false; co = 0;  break;
        case 7:  X = s; W = w_q2; Bi = b_q2; dh = g_QThi; dl = g_QTlo; chanmaj = false; co = 64; break;
        case 8:  X = s; W = w_ts; Bi = b_ts; df = g_ST; ocb = 0;  co = 0;  hasbn = true; bg = gts; bb = bets; bm = mts; bv = vts; break;
        case 9:  X = s; W = w_ts; Bi = b_ts; df = g_ST; ocb = 64; co = 64; hasbn = true; bg = gts; bb = bets; bm = mts; bv = vts; break;
        case 10: X = q; W = w_tq; Bi = b_tq; df = g_TQ; ocb = 0;  co = 0;  hasbn = true; bg = gtq; bb = betq; bm = mtq; bv = vtq; break;
        default: X = q; W = w_tq; Bi = b_tq; df = g_TQ; ocb = 64; co = 64; hasbn = true; bg = gtq; bb = betq; bm = mtq; bv = vtq; break;
    }
    const float* Xb = X + (size_t)b * NC * NPIX;
    __shared__ float Ws[16][64];
    __shared__ float Xs[16][128];
    float acc[4][8] = {};
    const int t = threadIdx.x, rg = t >> 4, cg = t & 15;

    for (int k0 = 0; k0 < NC; k0 += 16) {
        for (int i = t; i < 1024; i += 256) {
            int oc = i >> 4, kk = i & 15;
            Ws[kk][oc] = W[(ocb + oc) * NC + k0 + kk];
        }
        for (int i = t; i < 2048; i += 256) {
            int kk = i >> 7, px = i & 127;
            Xs[kk][px] = Xb[(size_t)(k0 + kk) * NPIX + n0 + px];
        }
        __syncthreads();
        #pragma unroll
        for (int kk = 0; kk < 16; kk++) {
            float a[4], xv[8];
            #pragma unroll
            for (int i = 0; i < 4; i++) a[i] = Ws[kk][rg * 4 + i];
            #pragma unroll
            for (int jx = 0; jx < 8; jx++) xv[jx] = Xs[kk][cg * 8 + jx];
            #pragma unroll
            for (int i = 0; i < 4; i++)
                #pragma unroll
                for (int jx = 0; jx < 8; jx++) acc[i][jx] += a[i] * xv[jx];
        }
        __syncthreads();
    }
    #pragma unroll
    for (int i = 0; i < 4; i++) {
        int oc = rg * 4 + i, gi = ocb + oc;
        float sc = 1.f, off = Bi[gi];
        if (hasbn) {
            float inv = bg[gi] * rsqrtf(bv[gi] + EPSV);
            sc = inv; off = (Bi[gi] - bm[gi]) * inv + bb[gi];
        }
        #pragma unroll
        for (int jx = 0; jx < 8; jx++) {
            int px = cg * 8 + jx;
            float v = acc[i][jx] * sc + off;
            if (df) {
                df[((size_t)b * CI + co + oc) * NPIX + n0 + px] = v;
            } else {
                size_t idx = chanmaj
                    ? ((size_t)b * CI + co + oc) * NPIX + n0 + px
                    : ((size_t)b * NPIX + n0 + px) * CI + co + oc;
                bf16 h = __float2bfloat16(v);
                dh[idx] = h;
                dl[idx] = __float2bfloat16(v - __bfloat162float(h));
            }
        }
    }
}

// ---------------- conv3x3 via bf16x3 mma ----------------
#define C3_SMEM 52160
__global__ __launch_bounds__(256) void conv3x3_mma(
    const float* __restrict__ bng, const float* __restrict__ bnb,
    const float* __restrict__ bnm, const float* __restrict__ bnv,
    float* __restrict__ outp_all)
{
    extern __shared__ char sm[];
    const int t = threadIdx.x, lane = t & 31, wid = t >> 5;
    const int g = lane >> 2, tg = lane & 3;
    const int y = blockIdx.x, b = blockIdx.y;
    const int wr = (wid & 3) * 32, wc = (wid >> 2) * 32;
    const bf16* EQh = g_EQhi + (size_t)b * CI * NPIX;
    const bf16* EQl = g_EQlo + (size_t)b * CI * NPIX;
    const bf16* ESh = g_EShi + (size_t)b * CI * NPIX;
    const bf16* ESl = g_ESlo + (size_t)b * CI * NPIX;
    float* outp = outp_all + (size_t)b * CI * NPIX;
    bf16* XH = (bf16*)(sm);
    bf16* XL = (bf16*)(sm + 15840);
    bf16* WHp = (bf16*)(sm + 31680);
    bf16* WLp = (bf16*)(sm + 41920);

    float c[2][4][4] = {};
    for (int icc = 0; icc < 8; icc++) {
        for (int i = t; i < 32 * 198; i += 256) {
            int icl = i / 198, np = i - icl * 198;
            int r = np / 66, px = np - r * 66;
            int icg = icc * 32 + icl;
            int rg = y + r - 1, x = px - 1;
            bf16 vh = __ushort_as_bfloat16(0), vl = __ushort_as_bfloat16(0);
            if (rg >= 0 && rg < 64 && x >= 0 && x < 64) {
                size_t gi = (size_t)(icg & 127) * NPIX + rg * 64 + x;
                if (icg < 128) { vh = EQh[gi]; vl = EQl[gi]; }
                else           { vh = ESh[gi]; vl = ESl[gi]; }
            }
            XH[np * 40 + icl] = vh;
            XL[np * 40 + icl] = vl;
        }
        __syncthreads();
        for (int tap = 0; tap < 9; tap++) {
            const int dy = tap / 3, dx = tap - dy * 3;
            for (int i = t; i < 4096; i += 256) {
                int oc = i >> 5, icl = i & 31;
                size_t wi = (size_t)tap * 32768 + oc * 256 + icc * 32 + icl;
                WHp[oc * 40 + icl] = g_W3hi[wi];
                WLp[oc * 40 + icl] = g_W3lo[wi];
            }
            __syncthreads();
            const uint32_t* Whi = (const uint32_t*)WHp;
            const uint32_t* Wlo = (const uint32_t*)WLp;
            const uint32_t* Xhi = (const uint32_t*)XH;
            const uint32_t* Xlo = (const uint32_t*)XL;
            #pragma unroll
            for (int kb = 0; kb < 16; kb += 8) {
                uint32_t ah[2][4], al[2][4];
                #pragma unroll
                for (int mt = 0; mt < 2; mt++) {
                    int base = (wr + mt * 16 + g) * 20 + kb + tg;
                    ah[mt][0] = Whi[base];       ah[mt][1] = Whi[base + 160];
                    ah[mt][2] = Whi[base + 4];   ah[mt][3] = Whi[base + 164];
                    al[mt][0] = Wlo[base];       al[mt][1] = Wlo[base + 160];
                    al[mt][2] = Wlo[base + 4];   al[mt][3] = Wlo[base + 164];
                }
                #pragma unroll
                for (int nt = 0; nt < 4; nt++) {
                    int px = wc + nt * 8 + g;
                    int bb = (dy * 66 + px + dx) * 20 + kb + tg;
                    uint32_t bh0 = Xhi[bb], bh1 = Xhi[bb + 4];
                    uint32_t bl0 = Xlo[bb], bl1 = Xlo[bb + 4];
                    #pragma unroll
                    for (int mt = 0; mt < 2; mt++) {
                        mma_bf16(c[mt][nt], ah[mt], bh0, bh1);
                        mma_bf16(c[mt][nt], al[mt], bh0, bh1);
                        mma_bf16(c[mt][nt], ah[mt], bl0, bl1);
                    }
                }
            }
            __syncthreads();
        }
    }

    float* Tb = (float*)sm;
    #pragma unroll
    for (int mt = 0; mt < 2; mt++)
        #pragma unroll
        for (int nt = 0; nt < 4; nt++)
            #pragma unroll
            for (int i = 0; i < 4; i++) {
                int row = wr + mt * 16 + g + (i >> 1) * 8;
                int col = wc + nt * 8 + tg * 2 + (i & 1);
                Tb[row * 68 + col] = c[mt][nt][i];
            }
    __syncthreads();
    for (int i = t; i < 8192; i += 256) {
        int oc = i >> 6, n = i & 63;
        float inv = bng[oc] * rsqrtf(bnv[oc] + EPSV);
        float off = bnb[oc] - bnm[oc] * inv;
        outp[(size_t)oc * NPIX + y * 64 + n] = fmaxf(Tb[oc * 68 + n] * inv + off, 0.f);
    }
}

// ---------------- launch ----------------
extern "C" void kernel_launch(void* const* d_in, const int* in_sizes, int n_in,
                              void* d_out, int out_size)
{
    (void)in_sizes; (void)n_in; (void)out_size;
    const float* q     = (const float*)d_in[0];
    const float* s     = (const float*)d_in[1];
    const float* scale = (const float*)d_in[2];
    const float* w_v   = (const float*)d_in[3];  const float* b_v  = (const float*)d_in[4];
    const float* w_k1  = (const float*)d_in[5];  const float* b_k1 = (const float*)d_in[6];
    const float* w_q1  = (const float*)d_in[7];  const float* b_q1 = (const float*)d_in[8];
    const float* w_k2  = (const float*)d_in[9];  const float* b_k2 = (const float*)d_in[10];
    const float* w_q2  = (const float*)d_in[11]; const float* b_q2 = (const float*)d_in[12];
    const float* w_ts  = (const float*)d_in[13]; const float* b_ts = (const float*)d_in[14];
    const float* gts   = (const float*)d_in[15]; const float* bets = (const float*)d_in[16];
    const float* mts   = (const float*)d_in[17]; const float* vts  = (const float*)d_in[18];
    const float* w_tq  = (const float*)d_in[19]; const float* b_tq = (const float*)d_in[20];
    const float* gtq   = (const float*)d_in[21]; const float* betq = (const float*)d_in[22];
    const float* mtq   = (const float*)d_in[23]; const float* vtq  = (const float*)d_in[24];
    const float* w_cat = (const float*)d_in[25];
    const float* gcat  = (const float*)d_in[26]; const float* becat= (const float*)d_in[27];
    const float* mcat  = (const float*)d_in[28]; const float* vcat = (const float*)d_in[29];

    float* out  = (float*)d_out;
    float* cpam = out;
    float* Eq   = out + (size_t)NB * CI * NPIX;
    float* Es   = out + 2 * (size_t)NB * CI * NPIX;

    cudaFuncSetAttribute(gemmA_mma,   cudaFuncAttributeMaxDynamicSharedMemorySize, GA_SMEM);
    cudaFuncSetAttribute(pv_mma,      cudaFuncAttributeMaxDynamicSharedMemorySize, PV_SMEM);
    cudaFuncSetAttribute(conv3x3_mma, cudaFuncAttributeMaxDynamicSharedMemorySize, C3_SMEM);

    zero_sums<<<(NB * NPIX + 255) / 256, 256>>>();
    w3prep<<<(9 * 128 * 256 + 255) / 256, 256>>>(w_cat);
    convs_kernel<<<dim3(32, NB, 12), 256>>>(q, s, w_v, b_v, w_k1, b_k1, w_q1, b_q1,
                                            w_k2, b_k2, w_q2, b_q2, w_ts, b_ts,
                                            gts, bets, mts, vts, w_tq, b_tq,
                                            gtq, betq, mtq, vtq);
    gemmA_mma<<<dim3(32, 32, NB), 256, GA_SMEM>>>();
    pv_mma<<<dim3(32, NB, 2), 256, PV_SMEM>>>(scale, Eq, Es);
    conv3x3_mma<<<dim3(64, NB), 256, C3_SMEM>>>(gcat, becat, mcat, vcat, cpam);
}

// round 9
// speedup vs baseline: 1.0101x; 1.0101x over previous
#include <cuda_runtime.h>
#include <cuda_bf16.h>
#include <cstdint>

#define NB   2
#define NC   256
#define NPIX 4096
#define CI   128
#define EPSV 1e-5f

typedef __nv_bfloat16 bf16;

__device__ bf16 g_Ehi [(size_t)NB * NPIX * NPIX];
__device__ bf16 g_Elo [(size_t)NB * NPIX * NPIX];
__device__ bf16 g_EThi[(size_t)NB * NPIX * NPIX];
__device__ bf16 g_ETlo[(size_t)NB * NPIX * NPIX];
__device__ bf16 g_VQhi[(size_t)NB * CI * NPIX];
__device__ bf16 g_VQlo[(size_t)NB * CI * NPIX];
__device__ bf16 g_VShi[(size_t)NB * CI * NPIX];
__device__ bf16 g_VSlo[(size_t)NB * CI * NPIX];
__device__ bf16 g_KThi[(size_t)NB * NPIX * CI];
__device__ bf16 g_KTlo[(size_t)NB * NPIX * CI];
__device__ bf16 g_QThi[(size_t)NB * NPIX * CI];
__device__ bf16 g_QTlo[(size_t)NB * NPIX * CI];
__device__ float g_ST [(size_t)NB * CI * NPIX];
__device__ float g_TQ [(size_t)NB * CI * NPIX];
__device__ float g_rowsum[NB * NPIX];
__device__ float g_colsum[NB * NPIX];
__device__ bf16 g_EQhi[(size_t)NB * CI * NPIX];
__device__ bf16 g_EQlo[(size_t)NB * CI * NPIX];
__device__ bf16 g_EShi[(size_t)NB * CI * NPIX];
__device__ bf16 g_ESlo[(size_t)NB * CI * NPIX];
__device__ bf16 g_W3hi[9 * 128 * 256];
__device__ bf16 g_W3lo[9 * 128 * 256];

// ---------------- helpers ----------------
__device__ __forceinline__ uint32_t smem_u32(const void* p) {
    uint32_t a;
    asm("{ .reg .u64 t; cvta.to.shared.u64 t, %1; cvt.u32.u64 %0, t; }" : "=r"(a) : "l"(p));
    return a;
}
__device__ __forceinline__ void cp16(uint32_t dst, const void* src) {
    asm volatile("cp.async.cg.shared.global [%0], [%1], 16;" :: "r"(dst), "l"(src));
}
#define CP_COMMIT() asm volatile("cp.async.commit_group;" ::: "memory")
#define CP_WAIT(n)  asm volatile("cp.async.wait_group %0;" :: "n"(n) : "memory")

__device__ __forceinline__ void mma_bf16(float* c, const uint32_t* a, uint32_t b0, uint32_t b1) {
    asm("mma.sync.aligned.m16n8k16.row.col.f32.bf16.bf16.f32 "
        "{%0,%1,%2,%3},{%4,%5,%6,%7},{%8,%9},{%0,%1,%2,%3};"
        : "+f"(c[0]), "+f"(c[1]), "+f"(c[2]), "+f"(c[3])
        : "r"(a[0]), "r"(a[1]), "r"(a[2]), "r"(a[3]), "r"(b0), "r"(b1));
}
__device__ __forceinline__ uint32_t split2(float x, float y, uint32_t& lo) {
    bf16 hx = __float2bfloat16(x), hy = __float2bfloat16(y);
    uint32_t hi = (uint32_t)__bfloat16_as_ushort(hx) | ((uint32_t)__bfloat16_as_ushort(hy) << 16);
    bf16 lx = __float2bfloat16(x - __bfloat162float(hx));
    bf16 ly = __float2bfloat16(y - __bfloat162float(hy));
    lo = (uint32_t)__bfloat16_as_ushort(lx) | ((uint32_t)__bfloat16_as_ushort(ly) << 16);
    return hi;
}

template<int ST>
__device__ __forceinline__ void mma_step(const uint32_t* Ahi, const uint32_t* Alo,
                                         const uint32_t* Bhi, const uint32_t* Blo,
                                         int kb, int wr, int wc, int g, int tg, float c[2][8][4])
{
    uint32_t ah[2][4], al[2][4];
    #pragma unroll
    for (int mt = 0; mt < 2; mt++) {
        int base = (wr + mt * 16 + g) * ST + kb + tg;
        ah[mt][0] = Ahi[base];          ah[mt][1] = Ahi[base + 8 * ST];
        ah[mt][2] = Ahi[base + 4];      ah[mt][3] = Ahi[base + 8 * ST + 4];
        al[mt][0] = Alo[base];          al[mt][1] = Alo[base + 8 * ST];
        al[mt][2] = Alo[base + 4];      al[mt][3] = Alo[base + 8 * ST + 4];
    }
    #pragma unroll
    for (int nt = 0; nt < 8; nt++) {
        int bb = (wc + nt * 8 + g) * ST + kb + tg;
        uint32_t bh0 = Bhi[bb], bh1 = Bhi[bb + 4];
        uint32_t bl0 = Blo[bb], bl1 = Blo[bb + 4];
        #pragma unroll
        for (int mt = 0; mt < 2; mt++) {
            mma_bf16(c[mt][nt], ah[mt], bh0, bh1);
            mma_bf16(c[mt][nt], al[mt], bh0, bh1);
            mma_bf16(c[mt][nt], ah[mt], bl0, bl1);
        }
    }
}

__global__ void zero_sums() {
    int i = blockIdx.x * 256 + threadIdx.x;
    if (i < NB * NPIX) { g_rowsum[i] = 0.f; g_colsum[i] = 0.f; }
}

__global__ void w3prep(const float* __restrict__ Wc) {
    int i = blockIdx.x * 256 + threadIdx.x;
    if (i >= 9 * 128 * 256) return;
    int tap = i >> 15, oc = (i >> 8) & 127, ic = i & 255;
    float v = Wc[(size_t)oc * 2304 + ic * 9 + tap];
    bf16 h = __float2bfloat16(v);
    g_W3hi[i] = h;
    g_W3lo[i] = __float2bfloat16(v - __bfloat162float(h));
}

// ============ gemmA: 2 blocks/SM enforced, chunked K, shuffle sums ============
#define GA_SMEM 73728
__global__ __launch_bounds__(256, 2) void gemmA_mma()
{
    extern __shared__ char sm[];
    const int t = threadIdx.x, lane = t & 31, wid = t >> 5;
    const int g = lane >> 2, tg = lane & 3;
    const int b = blockIdx.z, n0 = blockIdx.x * 128, m0 = blockIdx.y * 128;
    const int wr = (wid & 3) * 32, wc = (wid >> 2) * 64;
    const bf16* A_hi = g_KThi + (size_t)b * NPIX * CI + (size_t)n0 * CI;
    const bf16* A_lo = g_KTlo + (size_t)b * NPIX * CI + (size_t)n0 * CI;
    const bf16* B_hi = g_QThi + (size_t)b * NPIX * CI + (size_t)m0 * CI;
    const bf16* B_lo = g_QTlo + (size_t)b * NPIX * CI + (size_t)m0 * CI;
    uint32_t sb = smem_u32(sm);

    float c[2][8][4] = {};
    #pragma unroll
    for (int kc = 0; kc < 2; kc++) {
        #pragma unroll
        for (int p = 0; p < 4; p++) {
            int i = t + p * 256;
            int row = i >> 3, seg = i & 7;
            size_t go = (size_t)row * CI + kc * 64 + seg * 8;
            uint32_t so = row * 144 + seg * 16;
            cp16(sb + so,         A_hi + go);
            cp16(sb + 18432 + so, A_lo + go);
            cp16(sb + 36864 + so, B_hi + go);
            cp16(sb + 55296 + so, B_lo + go);
        }
        CP_COMMIT();
        CP_WAIT(0);
        __syncthreads();
        const uint32_t* Ahi = (const uint32_t*)sm;
        const uint32_t* Alo = (const uint32_t*)(sm + 18432);
        const uint32_t* Bhi = (const uint32_t*)(sm + 36864);
        const uint32_t* Blo = (const uint32_t*)(sm + 55296);
        #pragma unroll
        for (int kb = 0; kb < 32; kb += 8)
            mma_step<36>(Ahi, Alo, Bhi, Blo, kb, wr, wc, g, tg, c);
        __syncthreads();
    }

    #pragma unroll
    for (int mt = 0; mt < 2; mt++)
        #pragma unroll
        for (int nt = 0; nt < 8; nt++)
            #pragma unroll
            for (int i = 0; i < 4; i++)
                c[mt][nt][i] = __expf(c[mt][nt][i]);

    // row sums
    #pragma unroll
    for (int mt = 0; mt < 2; mt++)
        #pragma unroll
        for (int h = 0; h < 2; h++) {
            float v = 0.f;
            #pragma unroll
            for (int nt = 0; nt < 8; nt++) v += c[mt][nt][2 * h] + c[mt][nt][2 * h + 1];
            v += __shfl_xor_sync(0xffffffffu, v, 1);
            v += __shfl_xor_sync(0xffffffffu, v, 2);
            if (tg == 0) atomicAdd(g_rowsum + b * NPIX + n0 + wr + mt * 16 + g + 8 * h, v);
        }
    // col sums
    #pragma unroll
    for (int nt = 0; nt < 8; nt++)
        #pragma unroll
        for (int jj = 0; jj < 2; jj++) {
            float v = c[0][nt][jj] + c[0][nt][2 + jj] + c[1][nt][jj] + c[1][nt][2 + jj];
            v += __shfl_xor_sync(0xffffffffu, v, 4);
            v += __shfl_xor_sync(0xffffffffu, v, 8);
            v += __shfl_xor_sync(0xffffffffu, v, 16);
            if (g == 0) atomicAdd(g_colsum + b * NPIX + m0 + wc + nt * 8 + tg * 2 + jj, v);
        }

    float* Tb = (float*)sm;    // [128][132] (67584B <= 73728)
    #pragma unroll
    for (int mt = 0; mt < 2; mt++)
        #pragma unroll
        for (int nt = 0; nt < 8; nt++)
            #pragma unroll
            for (int i = 0; i < 4; i++) {
                int row = wr + mt * 16 + g + (i >> 1) * 8;
                int col = wc + nt * 8 + tg * 2 + (i & 1);
                Tb[row * 132 + col] = c[mt][nt][i];
            }
    __syncthreads();

    bf16* Ehi  = g_Ehi  + (size_t)b * NPIX * NPIX;
    bf16* Elo  = g_Elo  + (size_t)b * NPIX * NPIX;
    bf16* EThi = g_EThi + (size_t)b * NPIX * NPIX;
    bf16* ETlo = g_ETlo + (size_t)b * NPIX * NPIX;

    for (int i = t; i < 2048; i += 256) {
        int r = i >> 4, cg = (i & 15) * 8;
        uint4 hv, lv;
        hv.x = split2(Tb[r * 132 + cg + 0], Tb[r * 132 + cg + 1], lv.x);
        hv.y = split2(Tb[r * 132 + cg + 2], Tb[r * 132 + cg + 3], lv.y);
        hv.z = split2(Tb[r * 132 + cg + 4], Tb[r * 132 + cg + 5], lv.z);
        hv.w = split2(Tb[r * 132 + cg + 6], Tb[r * 132 + cg + 7], lv.w);
        size_t gi = (size_t)(n0 + r) * NPIX + m0 + cg;
        *(uint4*)(Ehi + gi) = hv;
        *(uint4*)(Elo + gi) = lv;
    }
    for (int i = t; i < 2048; i += 256) {
        int cl = i >> 4, rq = (i & 15) * 8;
        uint4 hv, lv;
        hv.x = split2(Tb[(rq + 0) * 132 + cl], Tb[(rq + 1) * 132 + cl], lv.x);
        hv.y = split2(Tb[(rq + 2) * 132 + cl], Tb[(rq + 3) * 132 + cl], lv.y);
        hv.z = split2(Tb[(rq + 4) * 132 + cl], Tb[(rq + 5) * 132 + cl], lv.z);
        hv.w = split2(Tb[(rq + 6) * 132 + cl], Tb[(rq + 7) * 132 + cl], lv.w);
        size_t gi = (size_t)(m0 + cl) * NPIX + n0 + rq;
        *(uint4*)(EThi + gi) = hv;
        *(uint4*)(ETlo + gi) = lv;
    }
}

// ============ pv: K=32 stages (40960B/stage), 2 blocks/SM ============
// stage: Ahi@0 Alo@10240 Bhi@20480 Blo@30720 (stride 20 u32); 2 stages; RS@81920
#define PV_SMEM 82432
__global__ __launch_bounds__(256, 2) void pv_mma(const float* __restrict__ scale_p,
                                                 float* __restrict__ outEq,
                                                 float* __restrict__ outEs)
{
    extern __shared__ char sm[];
    const int t = threadIdx.x, lane = t & 31, wid = t >> 5;
    const int g = lane >> 2, tg = lane & 3;
    const int r0 = blockIdx.x * 128, b = blockIdx.y, mode = blockIdx.z;
    const int wr = (wid & 3) * 32, wc = (wid >> 2) * 64;
    const bf16* A_hi = (mode ? g_EThi : g_Ehi) + (size_t)b * NPIX * NPIX + (size_t)r0 * NPIX;
    const bf16* A_lo = (mode ? g_ETlo : g_Elo) + (size_t)b * NPIX * NPIX + (size_t)r0 * NPIX;
    const bf16* B_hi = (mode ? g_VQhi : g_VShi) + (size_t)b * CI * NPIX;
    const bf16* B_lo = (mode ? g_VQlo : g_VSlo) + (size_t)b * CI * NPIX;
    const float* sums = (mode ? g_colsum : g_rowsum) + (size_t)b * NPIX + r0;
    const float* T = (mode ? g_TQ : g_ST) + (size_t)b * CI * NPIX;
    float* outp = (mode ? outEq : outEs) + (size_t)b * CI * NPIX;
    bf16* Fh = (mode ? g_EQhi : g_EShi) + (size_t)b * CI * NPIX;
    bf16* Fl = (mode ? g_EQlo : g_ESlo) + (size_t)b * CI * NPIX;
    uint32_t sb = smem_u32(sm);
    float* RS = (float*)(sm + 81920);
    if (t < 128) RS[t] = scale_p[0] / sums[t];

    // preload chunk 0 (K=32) -> stage 0: per plane 512 cp16
    #pragma unroll
    for (int p = 0; p < 2; p++) {
        int i = t + p * 256;               // 0..511
        int row = i >> 2, seg = i & 3;     // 4 x 16B = 64B = 32 bf16 per row
        size_t go = (size_t)row * NPIX + seg * 8;
        uint32_t so = row * 80 + seg * 16;
        cp16(sb + so,         A_hi + go);
        cp16(sb + 10240 + so, A_lo + go);
        cp16(sb + 20480 + so, B_hi + go);
        cp16(sb + 30720 + so, B_lo + go);
    }
    CP_COMMIT();

    float c[2][8][4] = {};
    for (int kc = 0; kc < 128; kc++) {
        const int st = kc & 1;
        if (kc + 1 < 128) {
            const int st2 = (kc + 1) & 1;
            #pragma unroll
            for (int p = 0; p < 2; p++) {
                int i = t + p * 256;
                int row = i >> 2, seg = i & 3;
                size_t go = (size_t)row * NPIX + (kc + 1) * 32 + seg * 8;
                uint32_t so = st2 * 40960 + row * 80 + seg * 16;
                cp16(sb + so,         A_hi + go);
                cp16(sb + 10240 + so, A_lo + go);
                cp16(sb + 20480 + so, B_hi + go);
                cp16(sb + 30720 + so, B_lo + go);
            }
            CP_COMMIT();
            CP_WAIT(1);
        } else {
            CP_WAIT(0);
        }
        __syncthreads();
        const uint32_t* Ahi = (const uint32_t*)(sm + st * 40960);
        const uint32_t* Alo = (const uint32_t*)(sm + st * 40960 + 10240);
        const uint32_t* Bhi = (const uint32_t*)(sm + st * 40960 + 20480);
        const uint32_t* Blo = (const uint32_t*)(sm + st * 40960 + 30720);
        #pragma unroll
        for (int kb = 0; kb < 16; kb += 8)
            mma_step<20>(Ahi, Alo, Bhi, Blo, kb, wr, wc, g, tg, c);
        __syncthreads();
    }

    float* Tb = (float*)sm;   // [128][132] (67584B <= 82432)
    #pragma unroll
    for (int mt = 0; mt < 2; mt++)
        #pragma unroll
        for (int nt = 0; nt < 8; nt++)
            #pragma unroll
            for (int i = 0; i < 4; i++) {
                int row = wr + mt * 16 + g + (i >> 1) * 8;
                int col = wc + nt * 8 + tg * 2 + (i & 1);
                Tb[row * 132 + col] = c[mt][nt][i] * RS[row];
            }
    __syncthreads();
    for (int i = t; i < 16384; i += 256) {
        int cl = i >> 7, r = i & 127;
        size_t gi = (size_t)cl * NPIX + r0 + r;
        float v = Tb[r * 132 + cl] + T[gi];
        outp[gi] = v;
        bf16 h = __float2bfloat16(v);
        Fh[gi] = h;
        Fl[gi] = __float2bfloat16(v - __bfloat162float(h));
    }
}

// ---------------- fused conv1x1: 12 jobs ----------------
__global__ __launch_bounds__(256) void convs_kernel(
    const float* __restrict__ q, const float* __restrict__ s,
    const float* __restrict__ w_v,  const float* __restrict__ b_v,
    const float* __restrict__ w_k1, const float* __restrict__ b_k1,
    const float* __restrict__ w_q1, const float* __restrict__ b_q1,
    const float* __restrict__ w_k2, const float* __restrict__ b_k2,
    const float* __restrict__ w_q2, const float* __restrict__ b_q2,
    const float* __restrict__ w_ts, const float* __restrict__ b_ts,
    const float* __restrict__ gts,  const float* __restrict__ bets,
    const float* __restrict__ mts,  const float* __restrict__ vts,
    const float* __restrict__ w_tq, const float* __restrict__ b_tq,
    const float* __restrict__ gtq,  const float* __restrict__ betq,
    const float* __restrict__ mtq,  const float* __restrict__ vtq)
{
    const int j = blockIdx.z, b = blockIdx.y, n0 = blockIdx.x * 128;
    const float *X, *W, *Bi, *bg = nullptr, *bb = nullptr, *bm = nullptr, *bv = nullptr;
    bf16 *dh = nullptr, *dl = nullptr;
    float* df = nullptr;
    int ocb = 0, co = 0; bool chanmaj = true, hasbn = false;
    switch (j) {
        case 0:  X = q; W = w_v;  Bi = b_v;  dh = g_VQhi; dl = g_VQlo; ocb = 0;  co = 0;  break;
        case 1:  X = q; W = w_v;  Bi = b_v;  dh = g_VQhi; dl = g_VQlo; ocb = 64; co = 64; break;
        case 2:  X = s; W = w_v;  Bi = b_v;  dh = g_VShi; dl = g_VSlo; ocb = 0;  co = 0;  break;
        case 3:  X = s; W = w_v;  Bi = b_v;  dh = g_VShi; dl = g_VSlo; ocb = 64; co = 64; break;
        case 4:  X = q; W = w_k1; Bi = b_k1; dh = g_KThi; dl = g_KTlo; chanmaj = false; co = 0;  break;
        case 5:  X = s; W = w_k2; Bi = b_k2; dh = g_KThi; dl = g_KTlo; chanmaj = false; co = 64; break;
        case 6:  X = q; W = w_q1; Bi = b_q1; dh = g_QThi; dl = g_QTlo; chanmaj = false; co = 0;  break;
        case 7:  X = s; W = w_q2; Bi = b_q2; dh = g_QThi; dl = g_QTlo; chanmaj = false; co = 64; break;
        case 8:  X = s; W = w_ts; Bi = b_ts; df = g_ST; ocb = 0;  co = 0;  hasbn = true; bg = gts; bb = bets; bm = mts; bv = vts; break;
        case 9:  X = s; W = w_ts; Bi = b_ts; df = g_ST; ocb = 64; co = 64; hasbn = true; bg = gts; bb = bets; bm = mts; bv = vts; break;
        case 10: X = q; W = w_tq; Bi = b_tq; df = g_TQ; ocb = 0;  co = 0;  hasbn = true; bg = gtq; bb = betq; bm = mtq; bv = vtq; break;
        default: X = q; W = w_tq; Bi = b_tq; df = g_TQ; ocb = 64; co = 64; hasbn = true; bg = gtq; bb = betq; bm = mtq; bv = vtq; break;
    }
    const float* Xb = X + (size_t)b * NC * NPIX;
    __shared__ float Ws[16][64];
    __shared__ float Xs[16][128];
    float acc[4][8] = {};
    const int t = threadIdx.x, rg = t >> 4, cg = t & 15;

    for (int k0 = 0; k0 < NC; k0 += 16) {
        for (int i = t; i < 1024; i += 256) {
            int oc = i >> 4, kk = i & 15;
            Ws[kk][oc] = W[(ocb + oc) * NC + k0 + kk];
        }
        for (int i = t; i < 2048; i += 256) {
            int kk = i >> 7, px = i & 127;
            Xs[kk][px] = Xb[(size_t)(k0 + kk) * NPIX + n0 + px];
        }
        __syncthreads();
        #pragma unroll
        for (int kk = 0; kk < 16; kk++) {
            float a[4], xv[8];
            #pragma unroll
            for (int i = 0; i < 4; i++) a[i] = Ws[kk][rg * 4 + i];
            #pragma unroll
            for (int jx = 0; jx < 8; jx++) xv[jx] = Xs[kk][cg * 8 + jx];
            #pragma unroll
            for (int i = 0; i < 4; i++)
                #pragma unroll
                for (int jx = 0; jx < 8; jx++) acc[i][jx] += a[i] * xv[jx];
        }
        __syncthreads();
    }
    #pragma unroll
    for (int i = 0; i < 4; i++) {
        int oc = rg * 4 + i, gi = ocb + oc;
        float sc = 1.f, off = Bi[gi];
        if (hasbn) {
            float inv = bg[gi] * rsqrtf(bv[gi] + EPSV);
            sc = inv; off = (Bi[gi] - bm[gi]) * inv + bb[gi];
        }
        #pragma unroll
        for (int jx = 0; jx < 8; jx++) {
            int px = cg * 8 + jx;
            float v = acc[i][jx] * sc + off;
            if (df) {
                df[((size_t)b * CI + co + oc) * NPIX + n0 + px] = v;
            } else {
                size_t idx = chanmaj
                    ? ((size_t)b * CI + co + oc) * NPIX + n0 + px
                    : ((size_t)b * NPIX + n0 + px) * CI + co + oc;
                bf16 h = __float2bfloat16(v);
                dh[idx] = h;
                dl[idx] = __float2bfloat16(v - __bfloat162float(h));
            }
        }
    }
}

// ---------------- conv3x3 via bf16x3 mma ----------------
#define C3_SMEM 52160
__global__ __launch_bounds__(256) void conv3x3_mma(
    const float* __restrict__ bng, const float* __restrict__ bnb,
    const float* __restrict__ bnm, const float* __restrict__ bnv,
    float* __restrict__ outp_all)
{
    extern __shared__ char sm[];
    const int t = threadIdx.x, lane = t & 31, wid = t >> 5;
    const int g = lane >> 2, tg = lane & 3;
    const int y = blockIdx.x, b = blockIdx.y;
    const int wr = (wid & 3) * 32, wc = (wid >> 2) * 32;
    const bf16* EQh = g_EQhi + (size_t)b * CI * NPIX;
    const bf16* EQl = g_EQlo + (size_t)b * CI * NPIX;
    const bf16* ESh = g_EShi + (size_t)b * CI * NPIX;
    const bf16* ESl = g_ESlo + (size_t)b * CI * NPIX;
    float* outp = outp_all + (size_t)b * CI * NPIX;
    bf16* XH = (bf16*)(sm);
    bf16* XL = (bf16*)(sm + 15840);
    bf16* WHp = (bf16*)(sm + 31680);
    bf16* WLp = (bf16*)(sm + 41920);

    float c[2][4][4] = {};
    for (int icc = 0; icc < 8; icc++) {
        for (int i = t; i < 32 * 198; i += 256) {
            int icl = i / 198, np = i - icl * 198;
            int r = np / 66, px = np - r * 66;
            int icg = icc * 32 + icl;
            int rg = y + r - 1, x = px - 1;
            bf16 vh = __ushort_as_bfloat16(0), vl = __ushort_as_bfloat16(0);
            if (rg >= 0 && rg < 64 && x >= 0 && x < 64) {
                size_t gi = (size_t)(icg & 127) * NPIX + rg * 64 + x;
                if (icg < 128) { vh = EQh[gi]; vl = EQl[gi]; }
                else           { vh = ESh[gi]; vl = ESl[gi]; }
            }
            XH[np * 40 + icl] = vh;
            XL[np * 40 + icl] = vl;
        }
        __syncthreads();
        for (int tap = 0; tap < 9; tap++) {
            const int dy = tap / 3, dx = tap - dy * 3;
            for (int i = t; i < 4096; i += 256) {
                int oc = i >> 5, icl = i & 31;
                size_t wi = (size_t)tap * 32768 + oc * 256 + icc * 32 + icl;
                WHp[oc * 40 + icl] = g_W3hi[wi];
                WLp[oc * 40 + icl] = g_W3lo[wi];
            }
            __syncthreads();
            const uint32_t* Whi = (const uint32_t*)WHp;
            const uint32_t* Wlo = (const uint32_t*)WLp;
            const uint32_t* Xhi = (const uint32_t*)XH;
            const uint32_t* Xlo = (const uint32_t*)XL;
            #pragma unroll
            for (int kb = 0; kb < 16; kb += 8) {
                uint32_t ah[2][4], al[2][4];
                #pragma unroll
                for (int mt = 0; mt < 2; mt++) {
                    int base = (wr + mt * 16 + g) * 20 + kb + tg;
                    ah[mt][0] = Whi[base];       ah[mt][1] = Whi[base + 160];
                    ah[mt][2] = Whi[base + 4];   ah[mt][3] = Whi[base + 164];
                    al[mt][0] = Wlo[base];       al[mt][1] = Wlo[base + 160];
                    al[mt][2] = Wlo[base + 4];   al[mt][3] = Wlo[base + 164];
                }
                #pragma unroll
                for (int nt = 0; nt < 4; nt++) {
                    int px = wc + nt * 8 + g;
                    int bb = (dy * 66 + px + dx) * 20 + kb + tg;
                    uint32_t bh0 = Xhi[bb], bh1 = Xhi[bb + 4];
                    uint32_t bl0 = Xlo[bb], bl1 = Xlo[bb + 4];
                    #pragma unroll
                    for (int mt = 0; mt < 2; mt++) {
                        mma_bf16(c[mt][nt], ah[mt], bh0, bh1);
                        mma_bf16(c[mt][nt], al[mt], bh0, bh1);
                        mma_bf16(c[mt][nt], ah[mt], bl0, bl1);
                    }
                }
            }
            __syncthreads();
        }
    }

    float* Tb = (float*)sm;
    #pragma unroll
    for (int mt = 0; mt < 2; mt++)
        #pragma unroll
        for (int nt = 0; nt < 4; nt++)
            #pragma unroll
            for (int i = 0; i < 4; i++) {
                int row = wr + mt * 16 + g + (i >> 1) * 8;
                int col = wc + nt * 8 + tg * 2 + (i & 1);
                Tb[row * 68 + col] = c[mt][nt][i];
            }
    __syncthreads();
    for (int i = t; i < 8192; i += 256) {
        int oc = i >> 6, n = i & 63;
        float inv = bng[oc] * rsqrtf(bnv[oc] + EPSV);
        float off = bnb[oc] - bnm[oc] * inv;
        outp[(size_t)oc * NPIX + y * 64 + n] = fmaxf(Tb[oc * 68 + n] * inv + off, 0.f);
    }
}

// ---------------- launch ----------------
extern "C" void kernel_launch(void* const* d_in, const int* in_sizes, int n_in,
                              void* d_out, int out_size)
{
    (void)in_sizes; (void)n_in; (void)out_size;
    const float* q     = (const float*)d_in[0];
    const float* s     = (const float*)d_in[1];
    const float* scale = (const float*)d_in[2];
    const float* w_v   = (const float*)d_in[3];  const float* b_v  = (const float*)d_in[4];
    const float* w_k1  = (const float*)d_in[5];  const float* b_k1 = (const float*)d_in[6];
    const float* w_q1  = (const float*)d_in[7];  const float* b_q1 = (const float*)d_in[8];
    const float* w_k2  = (const float*)d_in[9];  const float* b_k2 = (const float*)d_in[10];
    const float* w_q2  = (const float*)d_in[11]; const float* b_q2 = (const float*)d_in[12];
    const float* w_ts  = (const float*)d_in[13]; const float* b_ts = (const float*)d_in[14];
    const float* gts   = (const float*)d_in[15]; const float* bets = (const float*)d_in[16];
    const float* mts   = (const float*)d_in[17]; const float* vts  = (const float*)d_in[18];
    const float* w_tq  = (const float*)d_in[19]; const float* b_tq = (const float*)d_in[20];
    const float* gtq   = (const float*)d_in[21]; const float* betq = (const float*)d_in[22];
    const float* mtq   = (const float*)d_in[23]; const float* vtq  = (const float*)d_in[24];
    const float* w_cat = (const float*)d_in[25];
    const float* gcat  = (const float*)d_in[26]; const float* becat= (const float*)d_in[27];
    const float* mcat  = (const float*)d_in[28]; const float* vcat = (const float*)d_in[29];

    float* out  = (float*)d_out;
    float* cpam = out;
    float* Eq   = out + (size_t)NB * CI * NPIX;
    float* Es   = out + 2 * (size_t)NB * CI * NPIX;

    cudaFuncSetAttribute(gemmA_mma,   cudaFuncAttributeMaxDynamicSharedMemorySize, GA_SMEM);
    cudaFuncSetAttribute(pv_mma,      cudaFuncAttributeMaxDynamicSharedMemorySize, PV_SMEM);
    cudaFuncSetAttribute(conv3x3_mma, cudaFuncAttributeMaxDynamicSharedMemorySize, C3_SMEM);

    zero_sums<<<(NB * NPIX + 255) / 256, 256>>>();
    w3prep<<<(9 * 128 * 256 + 255) / 256, 256>>>(w_cat);
    convs_kernel<<<dim3(32, NB, 12), 256>>>(q, s, w_v, b_v, w_k1, b_k1, w_q1, b_q1,
                                            w_k2, b_k2, w_q2, b_q2, w_ts, b_ts,
                                            gts, bets, mts, vts, w_tq, b_tq,
                                            gtq, betq, mtq, vtq);
    gemmA_mma<<<dim3(32, 32, NB), 256, GA_SMEM>>>();
    pv_mma<<<dim3(32, NB, 2), 256, PV_SMEM>>>(scale, Eq, Es);
    conv3x3_mma<<<dim3(64, NB), 256, C3_SMEM>>>(gcat, becat, mcat, vcat, cpam);
}

// round 10
// speedup vs baseline: 1.0650x; 1.0543x over previous
#include <cuda_runtime.h>
#include <cuda_bf16.h>
#include <cstdint>

#define NB   2
#define NC   256
#define NPIX 4096
#define CI   128
#define EPSV 1e-5f

typedef __nv_bfloat16 bf16;

__device__ bf16 g_Ehi [(size_t)NB * NPIX * NPIX];
__device__ bf16 g_Elo [(size_t)NB * NPIX * NPIX];
__device__ bf16 g_EThi[(size_t)NB * NPIX * NPIX];
__device__ bf16 g_ETlo[(size_t)NB * NPIX * NPIX];
__device__ bf16 g_VQhi[(size_t)NB * CI * NPIX];
__device__ bf16 g_VQlo[(size_t)NB * CI * NPIX];
__device__ bf16 g_VShi[(size_t)NB * CI * NPIX];
__device__ bf16 g_VSlo[(size_t)NB * CI * NPIX];
__device__ bf16 g_KThi[(size_t)NB * NPIX * CI];
__device__ bf16 g_KTlo[(size_t)NB * NPIX * CI];
__device__ bf16 g_QThi[(size_t)NB * NPIX * CI];
__device__ bf16 g_QTlo[(size_t)NB * NPIX * CI];
__device__ float g_ST [(size_t)NB * CI * NPIX];
__device__ float g_TQ [(size_t)NB * CI * NPIX];
__device__ float g_rowsum[NB * NPIX];
__device__ float g_colsum[NB * NPIX];
__device__ bf16 g_EQhi[(size_t)NB * CI * NPIX];
__device__ bf16 g_EQlo[(size_t)NB * CI * NPIX];
__device__ bf16 g_EShi[(size_t)NB * CI * NPIX];
__device__ bf16 g_ESlo[(size_t)NB * CI * NPIX];
__device__ bf16 g_W3hi[9 * 128 * 256];
__device__ bf16 g_W3lo[9 * 128 * 256];

// ---------------- helpers ----------------
__device__ __forceinline__ uint32_t smem_u32(const void* p) {
    uint32_t a;
    asm("{ .reg .u64 t; cvta.to.shared.u64 t, %1; cvt.u32.u64 %0, t; }" : "=r"(a) : "l"(p));
    return a;
}
__device__ __forceinline__ void cp16(uint32_t dst, const void* src) {
    asm volatile("cp.async.cg.shared.global [%0], [%1], 16;" :: "r"(dst), "l"(src));
}
#define CP_COMMIT() asm volatile("cp.async.commit_group;" ::: "memory")
#define CP_WAIT(n)  asm volatile("cp.async.wait_group %0;" :: "n"(n) : "memory")

__device__ __forceinline__ void mma_bf16(float* c, const uint32_t* a, uint32_t b0, uint32_t b1) {
    asm("mma.sync.aligned.m16n8k16.row.col.f32.bf16.bf16.f32 "
        "{%0,%1,%2,%3},{%4,%5,%6,%7},{%8,%9},{%0,%1,%2,%3};"
        : "+f"(c[0]), "+f"(c[1]), "+f"(c[2]), "+f"(c[3])
        : "r"(a[0]), "r"(a[1]), "r"(a[2]), "r"(a[3]), "r"(b0), "r"(b1));
}
__device__ __forceinline__ void ldsm_x4(uint32_t* r, uint32_t addr) {
    asm volatile("ldmatrix.sync.aligned.m8n8.x4.shared.b16 {%0,%1,%2,%3}, [%4];"
        : "=r"(r[0]), "=r"(r[1]), "=r"(r[2]), "=r"(r[3]) : "r"(addr));
}
__device__ __forceinline__ void ldsm_x2(uint32_t& r0, uint32_t& r1, uint32_t addr) {
    asm volatile("ldmatrix.sync.aligned.m8n8.x2.shared.b16 {%0,%1}, [%2];"
        : "=r"(r0), "=r"(r1) : "r"(addr));
}
__device__ __forceinline__ uint32_t split2(float x, float y, uint32_t& lo) {
    bf16 hx = __float2bfloat16(x), hy = __float2bfloat16(y);
    uint32_t hi = (uint32_t)__bfloat16_as_ushort(hx) | ((uint32_t)__bfloat16_as_ushort(hy) << 16);
    bf16 lx = __float2bfloat16(x - __bfloat162float(hx));
    bf16 ly = __float2bfloat16(y - __bfloat162float(hy));
    lo = (uint32_t)__bfloat16_as_ushort(lx) | ((uint32_t)__bfloat16_as_ushort(ly) << 16);
    return hi;
}

// one k16 step via ldmatrix; ST = row stride in u32; addrs are smem byte addresses
template<int ST>
__device__ __forceinline__ void mma_step_l(uint32_t Ahi, uint32_t Alo,
                                           uint32_t Bhi, uint32_t Blo,
                                           int kb, int wr, int wc, int lane, float c[2][8][4])
{
    const int arow = lane & 15, asel = lane >> 4;
    const int brow = lane & 7,  bsel = (lane >> 3) & 1;
    uint32_t ah[2][4], al[2][4];
    #pragma unroll
    for (int mt = 0; mt < 2; mt++) {
        uint32_t aoff = ((wr + mt * 16 + arow) * ST + kb + asel * 4) * 4;
        ldsm_x4(ah[mt], Ahi + aoff);
        ldsm_x4(al[mt], Alo + aoff);
    }
    #pragma unroll
    for (int nt = 0; nt < 8; nt++) {
        uint32_t boff = ((wc + nt * 8 + brow) * ST + kb + bsel * 4) * 4;
        uint32_t bh0, bh1, bl0, bl1;
        ldsm_x2(bh0, bh1, Bhi + boff);
        ldsm_x2(bl0, bl1, Blo + boff);
        #pragma unroll
        for (int mt = 0; mt < 2; mt++) {
            mma_bf16(c[mt][nt], ah[mt], bh0, bh1);
            mma_bf16(c[mt][nt], al[mt], bh0, bh1);
            mma_bf16(c[mt][nt], ah[mt], bl0, bl1);
        }
    }
}

__global__ void zero_sums() {
    int i = blockIdx.x * 256 + threadIdx.x;
    if (i < NB * NPIX) { g_rowsum[i] = 0.f; g_colsum[i] = 0.f; }
}

__global__ void w3prep(const float* __restrict__ Wc) {
    int i = blockIdx.x * 256 + threadIdx.x;
    if (i >= 9 * 128 * 256) return;
    int tap = i >> 15, oc = (i >> 8) & 127, ic = i & 255;
    float v = Wc[(size_t)oc * 2304 + ic * 9 + tap];
    bf16 h = __float2bfloat16(v);
    g_W3hi[i] = h;
    g_W3lo[i] = __float2bfloat16(v - __bfloat162float(h));
}

// ============ gemmA: 2 blocks/SM, ldmatrix fragments, shuffle sums ============
#define GA_SMEM 73728
__global__ __launch_bounds__(256, 2) void gemmA_mma()
{
    extern __shared__ char sm[];
    const int t = threadIdx.x, lane = t & 31, wid = t >> 5;
    const int g = lane >> 2, tg = lane & 3;
    const int b = blockIdx.z, n0 = blockIdx.x * 128, m0 = blockIdx.y * 128;
    const int wr = (wid & 3) * 32, wc = (wid >> 2) * 64;
    const bf16* A_hi = g_KThi + (size_t)b * NPIX * CI + (size_t)n0 * CI;
    const bf16* A_lo = g_KTlo + (size_t)b * NPIX * CI + (size_t)n0 * CI;
    const bf16* B_hi = g_QThi + (size_t)b * NPIX * CI + (size_t)m0 * CI;
    const bf16* B_lo = g_QTlo + (size_t)b * NPIX * CI + (size_t)m0 * CI;
    uint32_t sb = smem_u32(sm);

    float c[2][8][4] = {};
    #pragma unroll
    for (int kc = 0; kc < 2; kc++) {
        #pragma unroll
        for (int p = 0; p < 4; p++) {
            int i = t + p * 256;
            int row = i >> 3, seg = i & 7;
            size_t go = (size_t)row * CI + kc * 64 + seg * 8;
            uint32_t so = row * 144 + seg * 16;
            cp16(sb + so,         A_hi + go);
            cp16(sb + 18432 + so, A_lo + go);
            cp16(sb + 36864 + so, B_hi + go);
            cp16(sb + 55296 + so, B_lo + go);
        }
        CP_COMMIT();
        CP_WAIT(0);
        __syncthreads();
        #pragma unroll
        for (int kb = 0; kb < 32; kb += 8)
            mma_step_l<36>(sb, sb + 18432, sb + 36864, sb + 55296, kb, wr, wc, lane, c);
        __syncthreads();
    }

    #pragma unroll
    for (int mt = 0; mt < 2; mt++)
        #pragma unroll
        for (int nt = 0; nt < 8; nt++)
            #pragma unroll
            for (int i = 0; i < 4; i++)
                c[mt][nt][i] = __expf(c[mt][nt][i]);

    // row sums
    #pragma unroll
    for (int mt = 0; mt < 2; mt++)
        #pragma unroll
        for (int h = 0; h < 2; h++) {
            float v = 0.f;
            #pragma unroll
            for (int nt = 0; nt < 8; nt++) v += c[mt][nt][2 * h] + c[mt][nt][2 * h + 1];
            v += __shfl_xor_sync(0xffffffffu, v, 1);
            v += __shfl_xor_sync(0xffffffffu, v, 2);
            if (tg == 0) atomicAdd(g_rowsum + b * NPIX + n0 + wr + mt * 16 + g + 8 * h, v);
        }
    // col sums
    #pragma unroll
    for (int nt = 0; nt < 8; nt++)
        #pragma unroll
        for (int jj = 0; jj < 2; jj++) {
            float v = c[0][nt][jj] + c[0][nt][2 + jj] + c[1][nt][jj] + c[1][nt][2 + jj];
            v += __shfl_xor_sync(0xffffffffu, v, 4);
            v += __shfl_xor_sync(0xffffffffu, v, 8);
            v += __shfl_xor_sync(0xffffffffu, v, 16);
            if (g == 0) atomicAdd(g_colsum + b * NPIX + m0 + wc + nt * 8 + tg * 2 + jj, v);
        }

    float* Tb = (float*)sm;    // [128][132]
    #pragma unroll
    for (int mt = 0; mt < 2; mt++)
        #pragma unroll
        for (int nt = 0; nt < 8; nt++)
            #pragma unroll
            for (int i = 0; i < 4; i++) {
                int row = wr + mt * 16 + g + (i >> 1) * 8;
                int col = wc + nt * 8 + tg * 2 + (i & 1);
                Tb[row * 132 + col] = c[mt][nt][i];
            }
    __syncthreads();

    bf16* Ehi  = g_Ehi  + (size_t)b * NPIX * NPIX;
    bf16* Elo  = g_Elo  + (size_t)b * NPIX * NPIX;
    bf16* EThi = g_EThi + (size_t)b * NPIX * NPIX;
    bf16* ETlo = g_ETlo + (size_t)b * NPIX * NPIX;

    for (int i = t; i < 2048; i += 256) {
        int r = i >> 4, cg = (i & 15) * 8;
        uint4 hv, lv;
        hv.x = split2(Tb[r * 132 + cg + 0], Tb[r * 132 + cg + 1], lv.x);
        hv.y = split2(Tb[r * 132 + cg + 2], Tb[r * 132 + cg + 3], lv.y);
        hv.z = split2(Tb[r * 132 + cg + 4], Tb[r * 132 + cg + 5], lv.z);
        hv.w = split2(Tb[r * 132 + cg + 6], Tb[r * 132 + cg + 7], lv.w);
        size_t gi = (size_t)(n0 + r) * NPIX + m0 + cg;
        *(uint4*)(Ehi + gi) = hv;
        *(uint4*)(Elo + gi) = lv;
    }
    for (int i = t; i < 2048; i += 256) {
        int cl = i >> 4, rq = (i & 15) * 8;
        uint4 hv, lv;
        hv.x = split2(Tb[(rq + 0) * 132 + cl], Tb[(rq + 1) * 132 + cl], lv.x);
        hv.y = split2(Tb[(rq + 2) * 132 + cl], Tb[(rq + 3) * 132 + cl], lv.y);
        hv.z = split2(Tb[(rq + 4) * 132 + cl], Tb[(rq + 5) * 132 + cl], lv.z);
        hv.w = split2(Tb[(rq + 6) * 132 + cl], Tb[(rq + 7) * 132 + cl], lv.w);
        size_t gi = (size_t)(m0 + cl) * NPIX + n0 + rq;
        *(uint4*)(EThi + gi) = hv;
        *(uint4*)(ETlo + gi) = lv;
    }
}

// ============ pv: R7 staging (K=64, 2 stages) + ldmatrix ============
#define PV_SMEM 147968
__global__ __launch_bounds__(256) void pv_mma(const float* __restrict__ scale_p,
                                              float* __restrict__ outEq,
                                              float* __restrict__ outEs)
{
    extern __shared__ char sm[];
    const int t = threadIdx.x, lane = t & 31, wid = t >> 5;
    const int g = lane >> 2, tg = lane & 3;
    const int r0 = blockIdx.x * 128, b = blockIdx.y, mode = blockIdx.z;
    const int wr = (wid & 3) * 32, wc = (wid >> 2) * 64;
    const bf16* A_hi = (mode ? g_EThi : g_Ehi) + (size_t)b * NPIX * NPIX + (size_t)r0 * NPIX;
    const bf16* A_lo = (mode ? g_ETlo : g_Elo) + (size_t)b * NPIX * NPIX + (size_t)r0 * NPIX;
    const bf16* B_hi = (mode ? g_VQhi : g_VShi) + (size_t)b * CI * NPIX;
    const bf16* B_lo = (mode ? g_VQlo : g_VSlo) + (size_t)b * CI * NPIX;
    const float* sums = (mode ? g_colsum : g_rowsum) + (size_t)b * NPIX + r0;
    const float* T = (mode ? g_TQ : g_ST) + (size_t)b * CI * NPIX;
    float* outp = (mode ? outEq : outEs) + (size_t)b * CI * NPIX;
    bf16* Fh = (mode ? g_EQhi : g_EShi) + (size_t)b * CI * NPIX;
    bf16* Fl = (mode ? g_EQlo : g_ESlo) + (size_t)b * CI * NPIX;
    uint32_t sb = smem_u32(sm);
    float* RS = (float*)(sm + 147456);
    if (t < 128) RS[t] = scale_p[0] / sums[t];

    #pragma unroll
    for (int p = 0; p < 4; p++) {
        int i = t + p * 256;
        int row = i >> 3, seg = i & 7;
        size_t go = (size_t)row * NPIX + seg * 8;
        uint32_t so = row * 144 + seg * 16;
        cp16(sb + so,         A_hi + go);
        cp16(sb + 18432 + so, A_lo + go);
        cp16(sb + 36864 + so, B_hi + go);
        cp16(sb + 55296 + so, B_lo + go);
    }
    CP_COMMIT();

    float c[2][8][4] = {};
    for (int kc = 0; kc < 64; kc++) {
        const int st = kc & 1;
        if (kc + 1 < 64) {
            const int st2 = (kc + 1) & 1;
            #pragma unroll
            for (int p = 0; p < 4; p++) {
                int i = t + p * 256;
                int row = i >> 3, seg = i & 7;
                size_t go = (size_t)row * NPIX + (kc + 1) * 64 + seg * 8;
                uint32_t so = st2 * 73728 + row * 144 + seg * 16;
                cp16(sb + so,         A_hi + go);
                cp16(sb + 18432 + so, A_lo + go);
                cp16(sb + 36864 + so, B_hi + go);
                cp16(sb + 55296 + so, B_lo + go);
            }
            CP_COMMIT();
            CP_WAIT(1);
        } else {
            CP_WAIT(0);
        }
        __syncthreads();
        uint32_t base = sb + st * 73728;
        #pragma unroll
        for (int kb = 0; kb < 32; kb += 8)
            mma_step_l<36>(base, base + 18432, base + 36864, base + 55296, kb, wr, wc, lane, c);
        __syncthreads();
    }

    float* Tb = (float*)sm;
    #pragma unroll
    for (int mt = 0; mt < 2; mt++)
        #pragma unroll
        for (int nt = 0; nt < 8; nt++)
            #pragma unroll
            for (int i = 0; i < 4; i++) {
                int row = wr + mt * 16 + g + (i >> 1) * 8;
                int col = wc + nt * 8 + tg * 2 + (i & 1);
                Tb[row * 132 + col] = c[mt][nt][i] * RS[row];
            }
    __syncthreads();
    for (int i = t; i < 16384; i += 256) {
        int cl = i >> 7, r = i & 127;
        size_t gi = (size_t)cl * NPIX + r0 + r;
        float v = Tb[r * 132 + cl] + T[gi];
        outp[gi] = v;
        bf16 h = __float2bfloat16(v);
        Fh[gi] = h;
        Fl[gi] = __float2bfloat16(v - __bfloat162float(h));
    }
}

// ---------------- fused conv1x1: 12 jobs ----------------
__global__ __launch_bounds__(256) void convs_kernel(
    const float* __restrict__ q, const float* __restrict__ s,
    const float* __restrict__ w_v,  const float* __restrict__ b_v,
    const float* __restrict__ w_k1, const float* __restrict__ b_k1,
    const float* __restrict__ w_q1, const float* __restrict__ b_q1,
    const float* __restrict__ w_k2, const float* __restrict__ b_k2,
    const float* __restrict__ w_q2, const float* __restrict__ b_q2,
    const float* __restrict__ w_ts, const float* __restrict__ b_ts,
    const float* __restrict__ gts,  const float* __restrict__ bets,
    const float* __restrict__ mts,  const float* __restrict__ vts,
    const float* __restrict__ w_tq, const float* __restrict__ b_tq,
    const float* __restrict__ gtq,  const float* __restrict__ betq,
    const float* __restrict__ mtq,  const float* __restrict__ vtq)
{
    const int j = blockIdx.z, b = blockIdx.y, n0 = blockIdx.x * 128;
    const float *X, *W, *Bi, *bg = nullptr, *bb = nullptr, *bm = nullptr, *bv = nullptr;
    bf16 *dh = nullptr, *dl = nullptr;
    float* df = nullptr;
    int ocb = 0, co = 0; bool chanmaj = true, hasbn = false;
    switch (j) {
        case 0:  X = q; W = w_v;  Bi = b_v;  dh = g_VQhi; dl = g_VQlo; ocb = 0;  co = 0;  break;
        case 1:  X = q; W = w_v;  Bi = b_v;  dh = g_VQhi; dl = g_VQlo; ocb = 64; co = 64; break;
        case 2:  X = s; W = w_v;  Bi = b_v;  dh = g_VShi; dl = g_VSlo; ocb = 0;  co = 0;  break;
        case 3:  X = s; W = w_v;  Bi = b_v;  dh = g_VShi; dl = g_VSlo; ocb = 64; co = 64; break;
        case 4:  X = q; W = w_k1; Bi = b_k1; dh = g_KThi; dl = g_KTlo; chanmaj = false; co = 0;  break;
        case 5:  X = s; W = w_k2; Bi = b_k2; dh = g_KThi; dl = g_KTlo; chanmaj = false; co = 64; break;
        case 6:  X = q; W = w_q1; Bi = b_q1; dh = g_QThi; dl = g_QTlo; chanmaj = false; co = 0;  break;
        case 7:  X = s; W = w_q2; Bi = b_q2; dh = g_QThi; dl = g_QTlo; chanmaj = false; co = 64; break;
        case 8:  X = s; W = w_ts; Bi = b_ts; df = g_ST; ocb = 0;  co = 0;  hasbn = true; bg = gts; bb = bets; bm = mts; bv = vts; break;
        case 9:  X = s; W = w_ts; Bi = b_ts; df = g_ST; ocb = 64; co = 64; hasbn = true; bg = gts; bb = bets; bm = mts; bv = vts; break;
        case 10: X = q; W = w_tq; Bi = b_tq; df = g_TQ; ocb = 0;  co = 0;  hasbn = true; bg = gtq; bb = betq; bm = mtq; bv = vtq; break;
        default: X = q; W = w_tq; Bi = b_tq; df = g_TQ; ocb = 64; co = 64; hasbn = true; bg = gtq; bb = betq; bm = mtq; bv = vtq; break;
    }
    const float* Xb = X + (size_t)b * NC * NPIX;
    __shared__ float Ws[16][64];
    __shared__ float Xs[16][128];
    float acc[4][8] = {};
    const int t = threadIdx.x, rg = t >> 4, cg = t & 15;

    for (int k0 = 0; k0 < NC; k0 += 16) {
        for (int i = t; i < 1024; i += 256) {
            int oc = i >> 4, kk = i & 15;
            Ws[kk][oc] = W[(ocb + oc) * NC + k0 + kk];
        }
        for (int i = t; i < 2048; i += 256) {
            int kk = i >> 7, px = i & 127;
            Xs[kk][px] = Xb[(size_t)(k0 + kk) * NPIX + n0 + px];
        }
        __syncthreads();
        #pragma unroll
        for (int kk = 0; kk < 16; kk++) {
            float a[4], xv[8];
            #pragma unroll
            for (int i = 0; i < 4; i++) a[i] = Ws[kk][rg * 4 + i];
            #pragma unroll
            for (int jx = 0; jx < 8; jx++) xv[jx] = Xs[kk][cg * 8 + jx];
            #pragma unroll
            for (int i = 0; i < 4; i++)
                #pragma unroll
                for (int jx = 0; jx < 8; jx++) acc[i][jx] += a[i] * xv[jx];
        }
        __syncthreads();
    }
    #pragma unroll
    for (int i = 0; i < 4; i++) {
        int oc = rg * 4 + i, gi = ocb + oc;
        float sc = 1.f, off = Bi[gi];
        if (hasbn) {
            float inv = bg[gi] * rsqrtf(bv[gi] + EPSV);
            sc = inv; off = (Bi[gi] - bm[gi]) * inv + bb[gi];
        }
        #pragma unroll
        for (int jx = 0; jx < 8; jx++) {
            int px = cg * 8 + jx;
            float v = acc[i][jx] * sc + off;
            if (df) {
                df[((size_t)b * CI + co + oc) * NPIX + n0 + px] = v;
            } else {
                size_t idx = chanmaj
                    ? ((size_t)b * CI + co + oc) * NPIX + n0 + px
                    : ((size_t)b * NPIX + n0 + px) * CI + co + oc;
                bf16 h = __float2bfloat16(v);
                dh[idx] = h;
                dl[idx] = __float2bfloat16(v - __bfloat162float(h));
            }
        }
    }
}

// ---------------- conv3x3 via bf16x3 mma + ldmatrix ----------------
#define C3_SMEM 52160
__global__ __launch_bounds__(256) void conv3x3_mma(
    const float* __restrict__ bng, const float* __restrict__ bnb,
    const float* __restrict__ bnm, const float* __restrict__ bnv,
    float* __restrict__ outp_all)
{
    extern __shared__ char sm[];
    const int t = threadIdx.x, lane = t & 31, wid = t >> 5;
    const int g = lane >> 2, tg = lane & 3;
    const int y = blockIdx.x, b = blockIdx.y;
    const int wr = (wid & 3) * 32, wc = (wid >> 2) * 32;
    const bf16* EQh = g_EQhi + (size_t)b * CI * NPIX;
    const bf16* EQl = g_EQlo + (size_t)b * CI * NPIX;
    const bf16* ESh = g_EShi + (size_t)b * CI * NPIX;
    const bf16* ESl = g_ESlo + (size_t)b * CI * NPIX;
    float* outp = outp_all + (size_t)b * CI * NPIX;
    bf16* XH = (bf16*)(sm);
    bf16* XL = (bf16*)(sm + 15840);
    bf16* WHp = (bf16*)(sm + 31680);
    bf16* WLp = (bf16*)(sm + 41920);
    uint32_t sb = smem_u32(sm);
    const uint32_t aXH = sb, aXL = sb + 15840, aWH = sb + 31680, aWL = sb + 41920;

    float c[2][4][4] = {};
    for (int icc = 0; icc < 8; icc++) {
        for (int i = t; i < 32 * 198; i += 256) {
            int icl = i / 198, np = i - icl * 198;
            int r = np / 66, px = np - r * 66;
            int icg = icc * 32 + icl;
            int rg = y + r - 1, x = px - 1;
            bf16 vh = __ushort_as_bfloat16(0), vl = __ushort_as_bfloat16(0);
            if (rg >= 0 && rg < 64 && x >= 0 && x < 64) {
                size_t gi = (size_t)(icg & 127) * NPIX + rg * 64 + x;
                if (icg < 128) { vh = EQh[gi]; vl = EQl[gi]; }
                else           { vh = ESh[gi]; vl = ESl[gi]; }
            }
            XH[np * 40 + icl] = vh;
            XL[np * 40 + icl] = vl;
        }
        __syncthreads();
        for (int tap = 0; tap < 9; tap++) {
            const int dy = tap / 3, dx = tap - dy * 3;
            for (int i = t; i < 4096; i += 256) {
                int oc = i >> 5, icl = i & 31;
                size_t wi = (size_t)tap * 32768 + oc * 256 + icc * 32 + icl;
                WHp[oc * 40 + icl] = g_W3hi[wi];
                WLp[oc * 40 + icl] = g_W3lo[wi];
            }
            __syncthreads();
            const int arow = lane & 15, asel = lane >> 4;
            const int brow = lane & 7,  bsel = (lane >> 3) & 1;
            #pragma unroll
            for (int kb = 0; kb < 16; kb += 8) {
                uint32_t ah[2][4], al[2][4];
                #pragma unroll
                for (int mt = 0; mt < 2; mt++) {
                    uint32_t aoff = ((wr + mt * 16 + arow) * 20 + kb + asel * 4) * 4;
                    ldsm_x4(ah[mt], aWH + aoff);
                    ldsm_x4(al[mt], aWL + aoff);
                }
                #pragma unroll
                for (int nt = 0; nt < 4; nt++) {
                    uint32_t boff = ((dy * 66 + wc + nt * 8 + brow + dx) * 20 + kb + bsel * 4) * 4;
                    uint32_t bh0, bh1, bl0, bl1;
                    ldsm_x2(bh0, bh1, aXH + boff);
                    ldsm_x2(bl0, bl1, aXL + boff);
                    #pragma unroll
                    for (int mt = 0; mt < 2; mt++) {
                        mma_bf16(c[mt][nt], ah[mt], bh0, bh1);
                        mma_bf16(c[mt][nt], al[mt], bh0, bh1);
                        mma_bf16(c[mt][nt], ah[mt], bl0, bl1);
                    }
                }
            }
            __syncthreads();
        }
    }

    float* Tb = (float*)sm;
    #pragma unroll
    for (int mt = 0; mt < 2; mt++)
        #pragma unroll
        for (int nt = 0; nt < 4; nt++)
            #pragma unroll
            for (int i = 0; i < 4; i++) {
                int row = wr + mt * 16 + g + (i >> 1) * 8;
                int col = wc + nt * 8 + tg * 2 + (i & 1);
                Tb[row * 68 + col] = c[mt][nt][i];
            }
    __syncthreads();
    for (int i = t; i < 8192; i += 256) {
        int oc = i >> 6, n = i & 63;
        float inv = bng[oc] * rsqrtf(bnv[oc] + EPSV);
        float off = bnb[oc] - bnm[oc] * inv;
        outp[(size_t)oc * NPIX + y * 64 + n] = fmaxf(Tb[oc * 68 + n] * inv + off, 0.f);
    }
}

// ---------------- launch ----------------
extern "C" void kernel_launch(void* const* d_in, const int* in_sizes, int n_in,
                              void* d_out, int out_size)
{
    (void)in_sizes; (void)n_in; (void)out_size;
    const float* q     = (const float*)d_in[0];
    const float* s     = (const float*)d_in[1];
    const float* scale = (const float*)d_in[2];
    const float* w_v   = (const float*)d_in[3];  const float* b_v  = (const float*)d_in[4];
    const float* w_k1  = (const float*)d_in[5];  const float* b_k1 = (const float*)d_in[6];
    const float* w_q1  = (const float*)d_in[7];  const float* b_q1 = (const float*)d_in[8];
    const float* w_k2  = (const float*)d_in[9];  const float* b_k2 = (const float*)d_in[10];
    const float* w_q2  = (const float*)d_in[11]; const float* b_q2 = (const float*)d_in[12];
    const float* w_ts  = (const float*)d_in[13]; const float* b_ts = (const float*)d_in[14];
    const float* gts   = (const float*)d_in[15]; const float* bets = (const float*)d_in[16];
    const float* mts   = (const float*)d_in[17]; const float* vts  = (const float*)d_in[18];
    const float* w_tq  = (const float*)d_in[19]; const float* b_tq = (const float*)d_in[20];
    const float* gtq   = (const float*)d_in[21]; const float* betq = (const float*)d_in[22];
    const float* mtq   = (const float*)d_in[23]; const float* vtq  = (const float*)d_in[24];
    const float* w_cat = (const float*)d_in[25];
    const float* gcat  = (const float*)d_in[26]; const float* becat= (const float*)d_in[27];
    const float* mcat  = (const float*)d_in[28]; const float* vcat = (const float*)d_in[29];

    float* out  = (float*)d_out;
    float* cpam = out;
    float* Eq   = out + (size_t)NB * CI * NPIX;
    float* Es   = out + 2 * (size_t)NB * CI * NPIX;

    cudaFuncSetAttribute(gemmA_mma,   cudaFuncAttributeMaxDynamicSharedMemorySize, GA_SMEM);
    cudaFuncSetAttribute(pv_mma,      cudaFuncAttributeMaxDynamicSharedMemorySize, PV_SMEM);
    cudaFuncSetAttribute(conv3x3_mma, cudaFuncAttributeMaxDynamicSharedMemorySize, C3_SMEM);

    zero_sums<<<(NB * NPIX + 255) / 256, 256>>>();
    w3prep<<<(9 * 128 * 256 + 255) / 256, 256>>>(w_cat);
    convs_kernel<<<dim3(32, NB, 12), 256>>>(q, s, w_v, b_v, w_k1, b_k1, w_q1, b_q1,
                                            w_k2, b_k2, w_q2, b_q2, w_ts, b_ts,
                                            gts, bets, mts, vts, w_tq, b_tq,
                                            gtq, betq, mtq, vtq);
    gemmA_mma<<<dim3(32, 32, NB), 256, GA_SMEM>>>();
    pv_mma<<<dim3(32, NB, 2), 256, PV_SMEM>>>(scale, Eq, Es);
    conv3x3_mma<<<dim3(64, NB), 256, C3_SMEM>>>(gcat, becat, mcat, vcat, cpam);
}

// round 11
// speedup vs baseline: 1.0792x; 1.0133x over previous
#include <cuda_runtime.h>
#include <cuda_bf16.h>
#include <cstdint>

#define NB   2
#define NC   256
#define NPIX 4096
#define CI   128
#define EPSV 1e-5f

typedef __nv_bfloat16 bf16;

__device__ bf16 g_Ehi [(size_t)NB * NPIX * NPIX];
__device__ bf16 g_Elo [(size_t)NB * NPIX * NPIX];
__device__ bf16 g_EThi[(size_t)NB * NPIX * NPIX];
__device__ bf16 g_ETlo[(size_t)NB * NPIX * NPIX];
__device__ bf16 g_VQhi[(size_t)NB * CI * NPIX];
__device__ bf16 g_VQlo[(size_t)NB * CI * NPIX];
__device__ bf16 g_VShi[(size_t)NB * CI * NPIX];
__device__ bf16 g_VSlo[(size_t)NB * CI * NPIX];
__device__ bf16 g_KThi[(size_t)NB * NPIX * CI];
__device__ bf16 g_KTlo[(size_t)NB * NPIX * CI];
__device__ bf16 g_QThi[(size_t)NB * NPIX * CI];
__device__ bf16 g_QTlo[(size_t)NB * NPIX * CI];
__device__ float g_ST [(size_t)NB * CI * NPIX];
__device__ float g_TQ [(size_t)NB * CI * NPIX];
__device__ float g_rowsum[NB * NPIX];
__device__ float g_colsum[NB * NPIX];
__device__ bf16 g_EQhi[(size_t)NB * CI * NPIX];
__device__ bf16 g_EQlo[(size_t)NB * CI * NPIX];
__device__ bf16 g_EShi[(size_t)NB * CI * NPIX];
__device__ bf16 g_ESlo[(size_t)NB * CI * NPIX];
__device__ bf16 g_W3hi[9 * 128 * 256];
__device__ bf16 g_W3lo[9 * 128 * 256];

// ---------------- helpers ----------------
__device__ __forceinline__ uint32_t smem_u32(const void* p) {
    uint32_t a;
    asm("{ .reg .u64 t; cvta.to.shared.u64 t, %1; cvt.u32.u64 %0, t; }" : "=r"(a) : "l"(p));
    return a;
}
__device__ __forceinline__ void cp16(uint32_t dst, const void* src) {
    asm volatile("cp.async.cg.shared.global [%0], [%1], 16;" :: "r"(dst), "l"(src));
}
#define CP_COMMIT() asm volatile("cp.async.commit_group;" ::: "memory")
#define CP_WAIT(n)  asm volatile("cp.async.wait_group %0;" :: "n"(n) : "memory")

__device__ __forceinline__ void mma_bf16(float* c, const uint32_t* a, uint32_t b0, uint32_t b1) {
    asm("mma.sync.aligned.m16n8k16.row.col.f32.bf16.bf16.f32 "
        "{%0,%1,%2,%3},{%4,%5,%6,%7},{%8,%9},{%0,%1,%2,%3};"
        : "+f"(c[0]), "+f"(c[1]), "+f"(c[2]), "+f"(c[3])
        : "r"(a[0]), "r"(a[1]), "r"(a[2]), "r"(a[3]), "r"(b0), "r"(b1));
}
__device__ __forceinline__ void ldsm_x4(uint32_t* r, uint32_t addr) {
    asm volatile("ldmatrix.sync.aligned.m8n8.x4.shared.b16 {%0,%1,%2,%3}, [%4];"
        : "=r"(r[0]), "=r"(r[1]), "=r"(r[2]), "=r"(r[3]) : "r"(addr));
}
__device__ __forceinline__ void ldsm_x2(uint32_t& r0, uint32_t& r1, uint32_t addr) {
    asm volatile("ldmatrix.sync.aligned.m8n8.x2.shared.b16 {%0,%1}, [%2];"
        : "=r"(r0), "=r"(r1) : "r"(addr));
}
__device__ __forceinline__ bf16 hi_of(float x) { return __float2bfloat16(x); }
__device__ __forceinline__ bf16 lo_of(float x, bf16 h) {
    return __float2bfloat16(x - __bfloat162float(h));
}

// one k16 step via ldmatrix; ST = row stride in u32; addrs are smem byte addresses
template<int ST>
__device__ __forceinline__ void mma_step_l(uint32_t Ahi, uint32_t Alo,
                                           uint32_t Bhi, uint32_t Blo,
                                           int kb, int wr, int wc, int lane, float c[2][8][4])
{
    const int arow = lane & 15, asel = lane >> 4;
    const int brow = lane & 7,  bsel = (lane >> 3) & 1;
    uint32_t ah[2][4], al[2][4];
    #pragma unroll
    for (int mt = 0; mt < 2; mt++) {
        uint32_t aoff = ((wr + mt * 16 + arow) * ST + kb + asel * 4) * 4;
        ldsm_x4(ah[mt], Ahi + aoff);
        ldsm_x4(al[mt], Alo + aoff);
    }
    #pragma unroll
    for (int nt = 0; nt < 8; nt++) {
        uint32_t boff = ((wc + nt * 8 + brow) * ST + kb + bsel * 4) * 4;
        uint32_t bh0, bh1, bl0, bl1;
        ldsm_x2(bh0, bh1, Bhi + boff);
        ldsm_x2(bl0, bl1, Blo + boff);
        #pragma unroll
        for (int mt = 0; mt < 2; mt++) {
            mma_bf16(c[mt][nt], ah[mt], bh0, bh1);
            mma_bf16(c[mt][nt], al[mt], bh0, bh1);
            mma_bf16(c[mt][nt], ah[mt], bl0, bl1);
        }
    }
}

__global__ void zero_sums() {
    int i = blockIdx.x * 256 + threadIdx.x;
    if (i < NB * NPIX) { g_rowsum[i] = 0.f; g_colsum[i] = 0.f; }
}

__global__ void w3prep(const float* __restrict__ Wc) {
    int i = blockIdx.x * 256 + threadIdx.x;
    if (i >= 9 * 128 * 256) return;
    int tap = i >> 15, oc = (i >> 8) & 127, ic = i & 255;
    float v = Wc[(size_t)oc * 2304 + ic * 9 + tap];
    bf16 h = __float2bfloat16(v);
    g_W3hi[i] = h;
    g_W3lo[i] = __float2bfloat16(v - __bfloat162float(h));
}

// ============ gemmA: 2 blocks/SM, ldmatrix, rotated conflict-free epilogue ============
#define GA_SMEM 73728
__global__ __launch_bounds__(256, 2) void gemmA_mma()
{
    extern __shared__ char sm[];
    const int t = threadIdx.x, lane = t & 31, wid = t >> 5;
    const int g = lane >> 2, tg = lane & 3;
    const int b = blockIdx.z, n0 = blockIdx.x * 128, m0 = blockIdx.y * 128;
    const int wr = (wid & 3) * 32, wc = (wid >> 2) * 64;
    const bf16* A_hi = g_KThi + (size_t)b * NPIX * CI + (size_t)n0 * CI;
    const bf16* A_lo = g_KTlo + (size_t)b * NPIX * CI + (size_t)n0 * CI;
    const bf16* B_hi = g_QThi + (size_t)b * NPIX * CI + (size_t)m0 * CI;
    const bf16* B_lo = g_QTlo + (size_t)b * NPIX * CI + (size_t)m0 * CI;
    uint32_t sb = smem_u32(sm);

    float c[2][8][4] = {};
    #pragma unroll
    for (int kc = 0; kc < 2; kc++) {
        #pragma unroll
        for (int p = 0; p < 4; p++) {
            int i = t + p * 256;
            int row = i >> 3, seg = i & 7;
            size_t go = (size_t)row * CI + kc * 64 + seg * 8;
            uint32_t so = row * 144 + seg * 16;
            cp16(sb + so,         A_hi + go);
            cp16(sb + 18432 + so, A_lo + go);
            cp16(sb + 36864 + so, B_hi + go);
            cp16(sb + 55296 + so, B_lo + go);
        }
        CP_COMMIT();
        CP_WAIT(0);
        __syncthreads();
        #pragma unroll
        for (int kb = 0; kb < 32; kb += 8)
            mma_step_l<36>(sb, sb + 18432, sb + 36864, sb + 55296, kb, wr, wc, lane, c);
        __syncthreads();
    }

    #pragma unroll
    for (int mt = 0; mt < 2; mt++)
        #pragma unroll
        for (int nt = 0; nt < 8; nt++)
            #pragma unroll
            for (int i = 0; i < 4; i++)
                c[mt][nt][i] = __expf(c[mt][nt][i]);

    // row sums
    #pragma unroll
    for (int mt = 0; mt < 2; mt++)
        #pragma unroll
        for (int h = 0; h < 2; h++) {
            float v = 0.f;
            #pragma unroll
            for (int nt = 0; nt < 8; nt++) v += c[mt][nt][2 * h] + c[mt][nt][2 * h + 1];
            v += __shfl_xor_sync(0xffffffffu, v, 1);
            v += __shfl_xor_sync(0xffffffffu, v, 2);
            if (tg == 0) atomicAdd(g_rowsum + b * NPIX + n0 + wr + mt * 16 + g + 8 * h, v);
        }
    // col sums
    #pragma unroll
    for (int nt = 0; nt < 8; nt++)
        #pragma unroll
        for (int jj = 0; jj < 2; jj++) {
            float v = c[0][nt][jj] + c[0][nt][2 + jj] + c[1][nt][jj] + c[1][nt][2 + jj];
            v += __shfl_xor_sync(0xffffffffu, v, 4);
            v += __shfl_xor_sync(0xffffffffu, v, 8);
            v += __shfl_xor_sync(0xffffffffu, v, 16);
            if (g == 0) atomicAdd(g_colsum + b * NPIX + m0 + wc + nt * 8 + tg * 2 + jj, v);
        }

    // rotated staging: phys = row*128 + ((col+row)&127)
    float* Tb = (float*)sm;    // 65536 B
    #pragma unroll
    for (int mt = 0; mt < 2; mt++)
        #pragma unroll
        for (int nt = 0; nt < 8; nt++)
            #pragma unroll
            for (int i = 0; i < 4; i++) {
                int row = wr + mt * 16 + g + (i >> 1) * 8;
                int col = wc + nt * 8 + tg * 2 + (i & 1);
                Tb[row * 128 + ((col + row) & 127)] = c[mt][nt][i];
            }
    __syncthreads();

    bf16* Ehi  = g_Ehi  + (size_t)b * NPIX * NPIX;
    bf16* Elo  = g_Elo  + (size_t)b * NPIX * NPIX;
    bf16* EThi = g_EThi + (size_t)b * NPIX * NPIX;
    bf16* ETlo = g_ETlo + (size_t)b * NPIX * NPIX;

    for (int i = t; i < 16384; i += 256) {       // E: lanes on consecutive cols
        int r = i >> 7, col = i & 127;
        float v = Tb[r * 128 + ((col + r) & 127)];
        size_t gi = (size_t)(n0 + r) * NPIX + m0 + col;
        bf16 h = hi_of(v);
        Ehi[gi] = h;
        Elo[gi] = lo_of(v, h);
    }
    for (int i = t; i < 16384; i += 256) {       // ET: lanes on consecutive rows
        int cl = i >> 7, r = i & 127;
        float v = Tb[r * 128 + ((cl + r) & 127)];
        size_t gi = (size_t)(m0 + cl) * NPIX + n0 + r;
        bf16 h = hi_of(v);
        EThi[gi] = h;
        ETlo[gi] = lo_of(v, h);
    }
}

// ============ pv: K=64 double-buffer + ldmatrix + rotated epilogue ============
#define PV_SMEM 147968
__global__ __launch_bounds__(256) void pv_mma(const float* __restrict__ scale_p,
                                              float* __restrict__ outEq,
                                              float* __restrict__ outEs)
{
    extern __shared__ char sm[];
    const int t = threadIdx.x, lane = t & 31, wid = t >> 5;
    const int g = lane >> 2, tg = lane & 3;
    const int r0 = blockIdx.x * 128, b = blockIdx.y, mode = blockIdx.z;
    const int wr = (wid & 3) * 32, wc = (wid >> 2) * 64;
    const bf16* A_hi = (mode ? g_EThi : g_Ehi) + (size_t)b * NPIX * NPIX + (size_t)r0 * NPIX;
    const bf16* A_lo = (mode ? g_ETlo : g_Elo) + (size_t)b * NPIX * NPIX + (size_t)r0 * NPIX;
    const bf16* B_hi = (mode ? g_VQhi : g_VShi) + (size_t)b * CI * NPIX;
    const bf16* B_lo = (mode ? g_VQlo : g_VSlo) + (size_t)b * CI * NPIX;
    const float* sums = (mode ? g_colsum : g_rowsum) + (size_t)b * NPIX + r0;
    const float* T = (mode ? g_TQ : g_ST) + (size_t)b * CI * NPIX;
    float* outp = (mode ? outEq : outEs) + (size_t)b * CI * NPIX;
    bf16* Fh = (mode ? g_EQhi : g_EShi) + (size_t)b * CI * NPIX;
    bf16* Fl = (mode ? g_EQlo : g_ESlo) + (size_t)b * CI * NPIX;
    uint32_t sb = smem_u32(sm);
    float* RS = (float*)(sm + 147456);
    if (t < 128) RS[t] = scale_p[0] / sums[t];

    #pragma unroll
    for (int p = 0; p < 4; p++) {
        int i = t + p * 256;
        int row = i >> 3, seg = i & 7;
        size_t go = (size_t)row * NPIX + seg * 8;
        uint32_t so = row * 144 + seg * 16;
        cp16(sb + so,         A_hi + go);
        cp16(sb + 18432 + so, A_lo + go);
        cp16(sb + 36864 + so, B_hi + go);
        cp16(sb + 55296 + so, B_lo + go);
    }
    CP_COMMIT();

    float c[2][8][4] = {};
    for (int kc = 0; kc < 64; kc++) {
        const int st = kc & 1;
        if (kc + 1 < 64) {
            const int st2 = (kc + 1) & 1;
            #pragma unroll
            for (int p = 0; p < 4; p++) {
                int i = t + p * 256;
                int row = i >> 3, seg = i & 7;
                size_t go = (size_t)row * NPIX + (kc + 1) * 64 + seg * 8;
                uint32_t so = st2 * 73728 + row * 144 + seg * 16;
                cp16(sb + so,         A_hi + go);
                cp16(sb + 18432 + so, A_lo + go);
                cp16(sb + 36864 + so, B_hi + go);
                cp16(sb + 55296 + so, B_lo + go);
            }
            CP_COMMIT();
            CP_WAIT(1);
        } else {
            CP_WAIT(0);
        }
        __syncthreads();
        uint32_t base = sb + st * 73728;
        #pragma unroll
        for (int kb = 0; kb < 32; kb += 8)
            mma_step_l<36>(base, base + 18432, base + 36864, base + 55296, kb, wr, wc, lane, c);
        __syncthreads();
    }

    float* Tb = (float*)sm;    // rotated [128][128]
    #pragma unroll
    for (int mt = 0; mt < 2; mt++)
        #pragma unroll
        for (int nt = 0; nt < 8; nt++)
            #pragma unroll
            for (int i = 0; i < 4; i++) {
                int row = wr + mt * 16 + g + (i >> 1) * 8;
                int col = wc + nt * 8 + tg * 2 + (i & 1);
                Tb[row * 128 + ((col + row) & 127)] = c[mt][nt][i] * RS[row];
            }
    __syncthreads();
    for (int i = t; i < 16384; i += 256) {   // lanes on consecutive rows: conflict-free
        int cl = i >> 7, r = i & 127;
        float v = Tb[r * 128 + ((cl + r) & 127)];
        size_t gi = (size_t)cl * NPIX + r0 + r;
        float o = v + T[gi];
        outp[gi] = o;
        bf16 h = hi_of(o);
        Fh[gi] = h;
        Fl[gi] = lo_of(o, h);
    }
}

// ---------------- fused conv1x1: 12 jobs ----------------
__global__ __launch_bounds__(256) void convs_kernel(
    const float* __restrict__ q, const float* __restrict__ s,
    const float* __restrict__ w_v,  const float* __restrict__ b_v,
    const float* __restrict__ w_k1, const float* __restrict__ b_k1,
    const float* __restrict__ w_q1, const float* __restrict__ b_q1,
    const float* __restrict__ w_k2, const float* __restrict__ b_k2,
    const float* __restrict__ w_q2, const float* __restrict__ b_q2,
    const float* __restrict__ w_ts, const float* __restrict__ b_ts,
    const float* __restrict__ gts,  const float* __restrict__ bets,
    const float* __restrict__ mts,  const float* __restrict__ vts,
    const float* __restrict__ w_tq, const float* __restrict__ b_tq,
    const float* __restrict__ gtq,  const float* __restrict__ betq,
    const float* __restrict__ mtq,  const float* __restrict__ vtq)
{
    const int j = blockIdx.z, b = blockIdx.y, n0 = blockIdx.x * 128;
    const float *X, *W, *Bi, *bg = nullptr, *bb = nullptr, *bm = nullptr, *bv = nullptr;
    bf16 *dh = nullptr, *dl = nullptr;
    float* df = nullptr;
    int ocb = 0, co = 0; bool chanmaj = true, hasbn = false;
    switch (j) {
        case 0:  X = q; W = w_v;  Bi = b_v;  dh = g_VQhi; dl = g_VQlo; ocb = 0;  co = 0;  break;
        case 1:  X = q; W = w_v;  Bi = b_v;  dh = g_VQhi; dl = g_VQlo; ocb = 64; co = 64; break;
        case 2:  X = s; W = w_v;  Bi = b_v;  dh = g_VShi; dl = g_VSlo; ocb = 0;  co = 0;  break;
        case 3:  X = s; W = w_v;  Bi = b_v;  dh = g_VShi; dl = g_VSlo; ocb = 64; co = 64; break;
        case 4:  X = q; W = w_k1; Bi = b_k1; dh = g_KThi; dl = g_KTlo; chanmaj = false; co = 0;  break;
        case 5:  X = s; W = w_k2; Bi = b_k2; dh = g_KThi; dl = g_KTlo; chanmaj = false; co = 64; break;
        case 6:  X = q; W = w_q1; Bi = b_q1; dh = g_QThi; dl = g_QTlo; chanmaj = false; co = 0;  break;
        case 7:  X = s; W = w_q2; Bi = b_q2; dh = g_QThi; dl = g_QTlo; chanmaj = false; co = 64; break;
        case 8:  X = s; W = w_ts; Bi = b_ts; df = g_ST; ocb = 0;  co = 0;  hasbn = true; bg = gts; bb = bets; bm = mts; bv = vts; break;
        case 9:  X = s; W = w_ts; Bi = b_ts; df = g_ST; ocb = 64; co = 64; hasbn = true; bg = gts; bb = bets; bm = mts; bv = vts; break;
        case 10: X = q; W = w_tq; Bi = b_tq; df = g_TQ; ocb = 0;  co = 0;  hasbn = true; bg = gtq; bb = betq; bm = mtq; bv = vtq; break;
        default: X = q; W = w_tq; Bi = b_tq; df = g_TQ; ocb = 64; co = 64; hasbn = true; bg = gtq; bb = betq; bm = mtq; bv = vtq; break;
    }
    const float* Xb = X + (size_t)b * NC * NPIX;
    __shared__ float Ws[16][64];
    __shared__ float Xs[16][128];
    float acc[4][8] = {};
    const int t = threadIdx.x, rg = t >> 4, cg = t & 15;

    for (int k0 = 0; k0 < NC; k0 += 16) {
        for (int i = t; i < 1024; i += 256) {
            int oc = i >> 4, kk = i & 15;
            Ws[kk][oc] = W[(ocb + oc) * NC + k0 + kk];
        }
        for (int i = t; i < 2048; i += 256) {
            int kk = i >> 7, px = i & 127;
            Xs[kk][px] = Xb[(size_t)(k0 + kk) * NPIX + n0 + px];
        }
        __syncthreads();
        #pragma unroll
        for (int kk = 0; kk < 16; kk++) {
            float a[4], xv[8];
            #pragma unroll
            for (int i = 0; i < 4; i++) a[i] = Ws[kk][rg * 4 + i];
            #pragma unroll
            for (int jx = 0; jx < 8; jx++) xv[jx] = Xs[kk][cg * 8 + jx];
            #pragma unroll
            for (int i = 0; i < 4; i++)
                #pragma unroll
                for (int jx = 0; jx < 8; jx++) acc[i][jx] += a[i] * xv[jx];
        }
        __syncthreads();
    }
    #pragma unroll
    for (int i = 0; i < 4; i++) {
        int oc = rg * 4 + i, gi = ocb + oc;
        float sc = 1.f, off = Bi[gi];
        if (hasbn) {
            float inv = bg[gi] * rsqrtf(bv[gi] + EPSV);
            sc = inv; off = (Bi[gi] - bm[gi]) * inv + bb[gi];
        }
        #pragma unroll
        for (int jx = 0; jx < 8; jx++) {
            int px = cg * 8 + jx;
            float v = acc[i][jx] * sc + off;
            if (df) {
                df[((size_t)b * CI + co + oc) * NPIX + n0 + px] = v;
            } else {
                size_t idx = chanmaj
                    ? ((size_t)b * CI + co + oc) * NPIX + n0 + px
                    : ((size_t)b * NPIX + n0 + px) * CI + co + oc;
                bf16 h = __float2bfloat16(v);
                dh[idx] = h;
                dl[idx] = __float2bfloat16(v - __bfloat162float(h));
            }
        }
    }
}

// ---------------- conv3x3 via bf16x3 mma + ldmatrix ----------------
#define C3_SMEM 52160
__global__ __launch_bounds__(256) void conv3x3_mma(
    const float* __restrict__ bng, const float* __restrict__ bnb,
    const float* __restrict__ bnm, const float* __restrict__ bnv,
    float* __restrict__ outp_all)
{
    extern __shared__ char sm[];
    const int t = threadIdx.x, lane = t & 31, wid = t >> 5;
    const int g = lane >> 2, tg = lane & 3;
    const int y = blockIdx.x, b = blockIdx.y;
    const int wr = (wid & 3) * 32, wc = (wid >> 2) * 32;
    const bf16* EQh = g_EQhi + (size_t)b * CI * NPIX;
    const bf16* EQl = g_EQlo + (size_t)b * CI * NPIX;
    const bf16* ESh = g_EShi + (size_t)b * CI * NPIX;
    const bf16* ESl = g_ESlo + (size_t)b * CI * NPIX;
    float* outp = outp_all + (size_t)b * CI * NPIX;
    bf16* XH = (bf16*)(sm);
    bf16* XL = (bf16*)(sm + 15840);
    bf16* WHp = (bf16*)(sm + 31680);
    bf16* WLp = (bf16*)(sm + 41920);
    uint32_t sb = smem_u32(sm);
    const uint32_t aXH = sb, aXL = sb + 15840, aWH = sb + 31680, aWL = sb + 41920;

    float c[2][4][4] = {};
    for (int icc = 0; icc < 8; icc++) {
        for (int i = t; i < 32 * 198; i += 256) {
            int icl = i / 198, np = i - icl * 198;
            int r = np / 66, px = np - r * 66;
            int icg = icc * 32 + icl;
            int rg = y + r - 1, x = px - 1;
            bf16 vh = __ushort_as_bfloat16(0), vl = __ushort_as_bfloat16(0);
            if (rg >= 0 && rg < 64 && x >= 0 && x < 64) {
                size_t gi = (size_t)(icg & 127) * NPIX + rg * 64 + x;
                if (icg < 128) { vh = EQh[gi]; vl = EQl[gi]; }
                else           { vh = ESh[gi]; vl = ESl[gi]; }
            }
            XH[np * 40 + icl] = vh;
            XL[np * 40 + icl] = vl;
        }
        __syncthreads();
        for (int tap = 0; tap < 9; tap++) {
            const int dy = tap / 3, dx = tap - dy * 3;
            for (int i = t; i < 4096; i += 256) {
                int oc = i >> 5, icl = i & 31;
                size_t wi = (size_t)tap * 32768 + oc * 256 + icc * 32 + icl;
                WHp[oc * 40 + icl] = g_W3hi[wi];
                WLp[oc * 40 + icl] = g_W3lo[wi];
            }
            __syncthreads();
            const int arow = lane & 15, asel = lane >> 4;
            const int brow = lane & 7,  bsel = (lane >> 3) & 1;
            #pragma unroll
            for (int kb = 0; kb < 16; kb += 8) {
                uint32_t ah[2][4], al[2][4];
                #pragma unroll
                for (int mt = 0; mt < 2; mt++) {
                    uint32_t aoff = ((wr + mt * 16 + arow) * 20 + kb + asel * 4) * 4;
                    ldsm_x4(ah[mt], aWH + aoff);
                    ldsm_x4(al[mt], aWL + aoff);
                }
                #pragma unroll
                for (int nt = 0; nt < 4; nt++) {
                    uint32_t boff = ((dy * 66 + wc + nt * 8 + brow + dx) * 20 + kb + bsel * 4) * 4;
                    uint32_t bh0, bh1, bl0, bl1;
                    ldsm_x2(bh0, bh1, aXH + boff);
                    ldsm_x2(bl0, bl1, aXL + boff);
                    #pragma unroll
                    for (int mt = 0; mt < 2; mt++) {
                        mma_bf16(c[mt][nt], ah[mt], bh0, bh1);
                        mma_bf16(c[mt][nt], al[mt], bh0, bh1);
                        mma_bf16(c[mt][nt], ah[mt], bl0, bl1);
                    }
                }
            }
            __syncthreads();
        }
    }

    float* Tb = (float*)sm;
    #pragma unroll
    for (int mt = 0; mt < 2; mt++)
        #pragma unroll
        for (int nt = 0; nt < 4; nt++)
            #pragma unroll
            for (int i = 0; i < 4; i++) {
                int row = wr + mt * 16 + g + (i >> 1) * 8;
                int col = wc + nt * 8 + tg * 2 + (i & 1);
                Tb[row * 68 + col] = c[mt][nt][i];
            }
    __syncthreads();
    for (int i = t; i < 8192; i += 256) {
        int oc = i >> 6, n = i & 63;
        float inv = bng[oc] * rsqrtf(bnv[oc] + EPSV);
        float off = bnb[oc] - bnm[oc] * inv;
        outp[(size_t)oc * NPIX + y * 64 + n] = fmaxf(Tb[oc * 68 + n] * inv + off, 0.f);
    }
}

// ---------------- launch ----------------
extern "C" void kernel_launch(void* const* d_in, const int* in_sizes, int n_in,
                              void* d_out, int out_size)
{
    (void)in_sizes; (void)n_in; (void)out_size;
    const float* q     = (const float*)d_in[0];
    const float* s     = (const float*)d_in[1];
    const float* scale = (const float*)d_in[2];
    const float* w_v   = (const float*)d_in[3];  const float* b_v  = (const float*)d_in[4];
    const float* w_k1  = (const float*)d_in[5];  const float* b_k1 = (const float*)d_in[6];
    const float* w_q1  = (const float*)d_in[7];  const float* b_q1 = (const float*)d_in[8];
    const float* w_k2  = (const float*)d_in[9];  const float* b_k2 = (const float*)d_in[10];
    const float* w_q2  = (const float*)d_in[11]; const float* b_q2 = (const float*)d_in[12];
    const float* w_ts  = (const float*)d_in[13]; const float* b_ts = (const float*)d_in[14];
    const float* gts   = (const float*)d_in[15]; const float* bets = (const float*)d_in[16];
    const float* mts   = (const float*)d_in[17]; const float* vts  = (const float*)d_in[18];
    const float* w_tq  = (const float*)d_in[19]; const float* b_tq = (const float*)d_in[20];
    const float* gtq   = (const float*)d_in[21]; const float* betq = (const float*)d_in[22];
    const float* mtq   = (const float*)d_in[23]; const float* vtq  = (const float*)d_in[24];
    const float* w_cat = (const float*)d_in[25];
    const float* gcat  = (const float*)d_in[26]; const float* becat= (const float*)d_in[27];
    const float* mcat  = (const float*)d_in[28]; const float* vcat = (const float*)d_in[29];

    float* out  = (float*)d_out;
    float* cpam = out;
    float* Eq   = out + (size_t)NB * CI * NPIX;
    float* Es   = out + 2 * (size_t)NB * CI * NPIX;

    cudaFuncSetAttribute(gemmA_mma,   cudaFuncAttributeMaxDynamicSharedMemorySize, GA_SMEM);
    cudaFuncSetAttribute(pv_mma,      cudaFuncAttributeMaxDynamicSharedMemorySize, PV_SMEM);
    cudaFuncSetAttribute(conv3x3_mma, cudaFuncAttributeMaxDynamicSharedMemorySize, C3_SMEM);

    zero_sums<<<(NB * NPIX + 255) / 256, 256>>>();
    w3prep<<<(9 * 128 * 256 + 255) / 256, 256>>>(w_cat);
    convs_kernel<<<dim3(32, NB, 12), 256>>>(q, s, w_v, b_v, w_k1, b_k1, w_q1, b_q1,
                                            w_k2, b_k2, w_q2, b_q2, w_ts, b_ts,
                                            gts, bets, mts, vts, w_tq, b_tq,
                                            gtq, betq, mtq, vtq);
    gemmA_mma<<<dim3(32, 32, NB), 256, GA_SMEM>>>();
    pv_mma<<<dim3(32, NB, 2), 256, PV_SMEM>>>(scale, Eq, Es);
    conv3x3_mma<<<dim3(64, NB), 256, C3_SMEM>>>(gcat, becat, mcat, vcat, cpam);
}

// round 12
// speedup vs baseline: 1.2042x; 1.1158x over previous
#include <cuda_runtime.h>
#include <cuda_bf16.h>
#include <cstdint>

#define NB   2
#define NC   256
#define NPIX 4096
#define CI   128
#define EPSV 1e-5f

typedef __nv_bfloat16 bf16;

__device__ bf16 g_Ehi [(size_t)NB * NPIX * NPIX];
__device__ bf16 g_EThi[(size_t)NB * NPIX * NPIX];
__device__ bf16 g_VQhi[(size_t)NB * CI * NPIX];
__device__ bf16 g_VQlo[(size_t)NB * CI * NPIX];
__device__ bf16 g_VShi[(size_t)NB * CI * NPIX];
__device__ bf16 g_VSlo[(size_t)NB * CI * NPIX];
__device__ bf16 g_KThi[(size_t)NB * NPIX * CI];
__device__ bf16 g_KTlo[(size_t)NB * NPIX * CI];
__device__ bf16 g_QThi[(size_t)NB * NPIX * CI];
__device__ bf16 g_QTlo[(size_t)NB * NPIX * CI];
__device__ float g_ST [(size_t)NB * CI * NPIX];
__device__ float g_TQ [(size_t)NB * CI * NPIX];
__device__ float g_rowsum[NB * NPIX];
__device__ float g_colsum[NB * NPIX];
__device__ bf16 g_EQhi[(size_t)NB * CI * NPIX];
__device__ bf16 g_EQlo[(size_t)NB * CI * NPIX];
__device__ bf16 g_EShi[(size_t)NB * CI * NPIX];
__device__ bf16 g_ESlo[(size_t)NB * CI * NPIX];
__device__ bf16 g_W3hi[9 * 128 * 256];
__device__ bf16 g_W3lo[9 * 128 * 256];

// ---------------- helpers ----------------
__device__ __forceinline__ uint32_t smem_u32(const void* p) {
    uint32_t a;
    asm("{ .reg .u64 t; cvta.to.shared.u64 t, %1; cvt.u32.u64 %0, t; }" : "=r"(a) : "l"(p));
    return a;
}
__device__ __forceinline__ void cp16(uint32_t dst, const void* src) {
    asm volatile("cp.async.cg.shared.global [%0], [%1], 16;" :: "r"(dst), "l"(src));
}
#define CP_COMMIT() asm volatile("cp.async.commit_group;" ::: "memory")
#define CP_WAIT(n)  asm volatile("cp.async.wait_group %0;" :: "n"(n) : "memory")

__device__ __forceinline__ void mma_bf16(float* c, const uint32_t* a, uint32_t b0, uint32_t b1) {
    asm("mma.sync.aligned.m16n8k16.row.col.f32.bf16.bf16.f32 "
        "{%0,%1,%2,%3},{%4,%5,%6,%7},{%8,%9},{%0,%1,%2,%3};"
        : "+f"(c[0]), "+f"(c[1]), "+f"(c[2]), "+f"(c[3])
        : "r"(a[0]), "r"(a[1]), "r"(a[2]), "r"(a[3]), "r"(b0), "r"(b1));
}
__device__ __forceinline__ void ldsm_x4(uint32_t* r, uint32_t addr) {
    asm volatile("ldmatrix.sync.aligned.m8n8.x4.shared.b16 {%0,%1,%2,%3}, [%4];"
        : "=r"(r[0]), "=r"(r[1]), "=r"(r[2]), "=r"(r[3]) : "r"(addr));
}
__device__ __forceinline__ void ldsm_x2(uint32_t& r0, uint32_t& r1, uint32_t addr) {
    asm volatile("ldmatrix.sync.aligned.m8n8.x2.shared.b16 {%0,%1}, [%2];"
        : "=r"(r0), "=r"(r1) : "r"(addr));
}
__device__ __forceinline__ uint32_t pack2(float x, float y) {
    bf16 hx = __float2bfloat16(x), hy = __float2bfloat16(y);
    return (uint32_t)__bfloat16_as_ushort(hx) | ((uint32_t)__bfloat16_as_ushort(hy) << 16);
}
__device__ __forceinline__ bf16 hi_of(float x) { return __float2bfloat16(x); }
__device__ __forceinline__ bf16 lo_of(float x, bf16 h) {
    return __float2bfloat16(x - __bfloat162float(h));
}

// bf16x3 step (gemmA): A hi/lo, B hi/lo, 3 MMAs per mt/nt
template<int ST>
__device__ __forceinline__ void mma_step_l(uint32_t Ahi, uint32_t Alo,
                                           uint32_t Bhi, uint32_t Blo,
                                           int kb, int wr, int wc, int lane, float c[2][8][4])
{
    const int arow = lane & 15, asel = lane >> 4;
    const int brow = lane & 7,  bsel = (lane >> 3) & 1;
    uint32_t ah[2][4], al[2][4];
    #pragma unroll
    for (int mt = 0; mt < 2; mt++) {
        uint32_t aoff = ((wr + mt * 16 + arow) * ST + kb + asel * 4) * 4;
        ldsm_x4(ah[mt], Ahi + aoff);
        ldsm_x4(al[mt], Alo + aoff);
    }
    #pragma unroll
    for (int nt = 0; nt < 8; nt++) {
        uint32_t boff = ((wc + nt * 8 + brow) * ST + kb + bsel * 4) * 4;
        uint32_t bh0, bh1, bl0, bl1;
        ldsm_x2(bh0, bh1, Bhi + boff);
        ldsm_x2(bl0, bl1, Blo + boff);
        #pragma unroll
        for (int mt = 0; mt < 2; mt++) {
            mma_bf16(c[mt][nt], ah[mt], bh0, bh1);
            mma_bf16(c[mt][nt], al[mt], bh0, bh1);
            mma_bf16(c[mt][nt], ah[mt], bl0, bl1);
        }
    }
}

// bf16x2 step (pv): A single plane, B hi/lo, 2 MMAs per mt/nt
template<int ST>
__device__ __forceinline__ void mma_step_2(uint32_t Ahi, uint32_t Bhi, uint32_t Blo,
                                           int kb, int wr, int wc, int lane, float c[2][8][4])
{
    const int arow = lane & 15, asel = lane >> 4;
    const int brow = lane & 7,  bsel = (lane >> 3) & 1;
    uint32_t ah[2][4];
    #pragma unroll
    for (int mt = 0; mt < 2; mt++) {
        uint32_t aoff = ((wr + mt * 16 + arow) * ST + kb + asel * 4) * 4;
        ldsm_x4(ah[mt], Ahi + aoff);
    }
    #pragma unroll
    for (int nt = 0; nt < 8; nt++) {
        uint32_t boff = ((wc + nt * 8 + brow) * ST + kb + bsel * 4) * 4;
        uint32_t bh0, bh1, bl0, bl1;
        ldsm_x2(bh0, bh1, Bhi + boff);
        ldsm_x2(bl0, bl1, Blo + boff);
        #pragma unroll
        for (int mt = 0; mt < 2; mt++) {
            mma_bf16(c[mt][nt], ah[mt], bh0, bh1);
            mma_bf16(c[mt][nt], ah[mt], bl0, bl1);
        }
    }
}

__global__ void zero_sums() {
    int i = blockIdx.x * 256 + threadIdx.x;
    if (i < NB * NPIX) { g_rowsum[i] = 0.f; g_colsum[i] = 0.f; }
}

__global__ void w3prep(const float* __restrict__ Wc) {
    int i = blockIdx.x * 256 + threadIdx.x;
    if (i >= 9 * 128 * 256) return;
    int tap = i >> 15, oc = (i >> 8) & 127, ic = i & 255;
    float v = Wc[(size_t)oc * 2304 + ic * 9 + tap];
    bf16 h = __float2bfloat16(v);
    g_W3hi[i] = h;
    g_W3lo[i] = __float2bfloat16(v - __bfloat162float(h));
}

// ============ gemmA: 2/SM, ldmatrix x3, hi-only packed epilogue ============
#define GA_SMEM 73728
__global__ __launch_bounds__(256, 2) void gemmA_mma()
{
    extern __shared__ char sm[];
    const int t = threadIdx.x, lane = t & 31, wid = t >> 5;
    const int g = lane >> 2, tg = lane & 3;
    const int b = blockIdx.z, n0 = blockIdx.x * 128, m0 = blockIdx.y * 128;
    const int wr = (wid & 3) * 32, wc = (wid >> 2) * 64;
    const bf16* A_hi = g_KThi + (size_t)b * NPIX * CI + (size_t)n0 * CI;
    const bf16* A_lo = g_KTlo + (size_t)b * NPIX * CI + (size_t)n0 * CI;
    const bf16* B_hi = g_QThi + (size_t)b * NPIX * CI + (size_t)m0 * CI;
    const bf16* B_lo = g_QTlo + (size_t)b * NPIX * CI + (size_t)m0 * CI;
    uint32_t sb = smem_u32(sm);

    float c[2][8][4] = {};
    #pragma unroll
    for (int kc = 0; kc < 2; kc++) {
        #pragma unroll
        for (int p = 0; p < 4; p++) {
            int i = t + p * 256;
            int row = i >> 3, seg = i & 7;
            size_t go = (size_t)row * CI + kc * 64 + seg * 8;
            uint32_t so = row * 144 + seg * 16;
            cp16(sb + so,         A_hi + go);
            cp16(sb + 18432 + so, A_lo + go);
            cp16(sb + 36864 + so, B_hi + go);
            cp16(sb + 55296 + so, B_lo + go);
        }
        CP_COMMIT();
        CP_WAIT(0);
        __syncthreads();
        #pragma unroll
        for (int kb = 0; kb < 32; kb += 8)
            mma_step_l<36>(sb, sb + 18432, sb + 36864, sb + 55296, kb, wr, wc, lane, c);
        __syncthreads();
    }

    #pragma unroll
    for (int mt = 0; mt < 2; mt++)
        #pragma unroll
        for (int nt = 0; nt < 8; nt++)
            #pragma unroll
            for (int i = 0; i < 4; i++)
                c[mt][nt][i] = __expf(c[mt][nt][i]);

    // row sums
    #pragma unroll
    for (int mt = 0; mt < 2; mt++)
        #pragma unroll
        for (int h = 0; h < 2; h++) {
            float v = 0.f;
            #pragma unroll
            for (int nt = 0; nt < 8; nt++) v += c[mt][nt][2 * h] + c[mt][nt][2 * h + 1];
            v += __shfl_xor_sync(0xffffffffu, v, 1);
            v += __shfl_xor_sync(0xffffffffu, v, 2);
            if (tg == 0) atomicAdd(g_rowsum + b * NPIX + n0 + wr + mt * 16 + g + 8 * h, v);
        }
    // col sums
    #pragma unroll
    for (int nt = 0; nt < 8; nt++)
        #pragma unroll
        for (int jj = 0; jj < 2; jj++) {
            float v = c[0][nt][jj] + c[0][nt][2 + jj] + c[1][nt][jj] + c[1][nt][2 + jj];
            v += __shfl_xor_sync(0xffffffffu, v, 4);
            v += __shfl_xor_sync(0xffffffffu, v, 8);
            v += __shfl_xor_sync(0xffffffffu, v, 16);
            if (g == 0) atomicAdd(g_colsum + b * NPIX + m0 + wc + nt * 8 + tg * 2 + jj, v);
        }

    // rotated staging: phys = row*128 + ((col+row)&127)
    float* Tb = (float*)sm;
    #pragma unroll
    for (int mt = 0; mt < 2; mt++)
        #pragma unroll
        for (int nt = 0; nt < 8; nt++)
            #pragma unroll
            for (int i = 0; i < 4; i++) {
                int row = wr + mt * 16 + g + (i >> 1) * 8;
                int col = wc + nt * 8 + tg * 2 + (i & 1);
                Tb[row * 128 + ((col + row) & 127)] = c[mt][nt][i];
            }
    __syncthreads();

    bf16* Ehi  = g_Ehi  + (size_t)b * NPIX * NPIX;
    bf16* EThi = g_EThi + (size_t)b * NPIX * NPIX;

    for (int i = t; i < 8192; i += 256) {         // E hi: 2 cols packed per u32
        int r = i >> 6, c2 = (i & 63) * 2;
        float v0 = Tb[r * 128 + ((c2 + r) & 127)];
        float v1 = Tb[r * 128 + ((c2 + 1 + r) & 127)];
        *(uint32_t*)(Ehi + (size_t)(n0 + r) * NPIX + m0 + c2) = pack2(v0, v1);
    }
    for (int i = t; i < 8192; i += 256) {         // ET hi: 2 rows packed per u32
        int cl = i >> 6, r2 = (i & 63) * 2;
        float v0 = Tb[(r2) * 128 + ((cl + r2) & 127)];
        float v1 = Tb[(r2 + 1) * 128 + ((cl + r2 + 1) & 127)];
        *(uint32_t*)(EThi + (size_t)(m0 + cl) * NPIX + n0 + r2) = pack2(v0, v1);
    }
}

// ============ pv: A single-plane, 2-term MMA, 2 blocks/SM ============
// stage: Ahi@0, Bhi@18432, Blo@36864 (stride 36 u32); 2 stages @55296; RS@110592
#define PV_SMEM 111104
__global__ __launch_bounds__(256, 2) void pv_mma(const float* __restrict__ scale_p,
                                                 float* __restrict__ outEq,
                                                 float* __restrict__ outEs)
{
    extern __shared__ char sm[];
    const int t = threadIdx.x, lane = t & 31, wid = t >> 5;
    const int g = lane >> 2, tg = lane & 3;
    const int r0 = blockIdx.x * 128, b = blockIdx.y, mode = blockIdx.z;
    const int wr = (wid & 3) * 32, wc = (wid >> 2) * 64;
    const bf16* A_hi = (mode ? g_EThi : g_Ehi) + (size_t)b * NPIX * NPIX + (size_t)r0 * NPIX;
    const bf16* B_hi = (mode ? g_VQhi : g_VShi) + (size_t)b * CI * NPIX;
    const bf16* B_lo = (mode ? g_VQlo : g_VSlo) + (size_t)b * CI * NPIX;
    const float* sums = (mode ? g_colsum : g_rowsum) + (size_t)b * NPIX + r0;
    const float* T = (mode ? g_TQ : g_ST) + (size_t)b * CI * NPIX;
    float* outp = (mode ? outEq : outEs) + (size_t)b * CI * NPIX;
    bf16* Fh = (mode ? g_EQhi : g_EShi) + (size_t)b * CI * NPIX;
    bf16* Fl = (mode ? g_EQlo : g_ESlo) + (size_t)b * CI * NPIX;
    uint32_t sb = smem_u32(sm);
    float* RS = (float*)(sm + 110592);
    if (t < 128) RS[t] = scale_p[0] / sums[t];

    #pragma unroll
    for (int p = 0; p < 4; p++) {
        int i = t + p * 256;
        int row = i >> 3, seg = i & 7;
        size_t go = (size_t)row * NPIX + seg * 8;
        uint32_t so = row * 144 + seg * 16;
        cp16(sb + so,         A_hi + go);
        cp16(sb + 18432 + so, B_hi + go);
        cp16(sb + 36864 + so, B_lo + go);
    }
    CP_COMMIT();

    float c[2][8][4] = {};
    for (int kc = 0; kc < 64; kc++) {
        const int st = kc & 1;
        if (kc + 1 < 64) {
            const int st2 = (kc + 1) & 1;
            #pragma unroll
            for (int p = 0; p < 4; p++) {
                int i = t + p * 256;
                int row = i >> 3, seg = i & 7;
                size_t go = (size_t)row * NPIX + (kc + 1) * 64 + seg * 8;
                uint32_t so = st2 * 55296 + row * 144 + seg * 16;
                cp16(sb + so,         A_hi + go);
                cp16(sb + 18432 + so, B_hi + go);
                cp16(sb + 36864 + so, B_lo + go);
            }
            CP_COMMIT();
            CP_WAIT(1);
        } else {
            CP_WAIT(0);
        }
        __syncthreads();
        uint32_t base = sb + st * 55296;
        #pragma unroll
        for (int kb = 0; kb < 32; kb += 8)
            mma_step_2<36>(base, base + 18432, base + 36864, kb, wr, wc, lane, c);
        __syncthreads();
    }

    float* Tb = (float*)sm;    // rotated [128][128]
    #pragma unroll
    for (int mt = 0; mt < 2; mt++)
        #pragma unroll
        for (int nt = 0; nt < 8; nt++)
            #pragma unroll
            for (int i = 0; i < 4; i++) {
                int row = wr + mt * 16 + g + (i >> 1) * 8;
                int col = wc + nt * 8 + tg * 2 + (i & 1);
                Tb[row * 128 + ((col + row) & 127)] = c[mt][nt][i] * RS[row];
            }
    __syncthreads();
    for (int i = t; i < 16384; i += 256) {
        int cl = i >> 7, r = i & 127;
        float v = Tb[r * 128 + ((cl + r) & 127)];
        size_t gi = (size_t)cl * NPIX + r0 + r;
        float o = v + T[gi];
        outp[gi] = o;
        bf16 h = hi_of(o);
        Fh[gi] = h;
        Fl[gi] = lo_of(o, h);
    }
}

// ---------------- fused conv1x1: 12 jobs ----------------
__global__ __launch_bounds__(256) void convs_kernel(
    const float* __restrict__ q, const float* __restrict__ s,
    const float* __restrict__ w_v,  const float* __restrict__ b_v,
    const float* __restrict__ w_k1, const float* __restrict__ b_k1,
    const float* __restrict__ w_q1, const float* __restrict__ b_q1,
    const float* __restrict__ w_k2, const float* __restrict__ b_k2,
    const float* __restrict__ w_q2, const float* __restrict__ b_q2,
    const float* __restrict__ w_ts, const float* __restrict__ b_ts,
    const float* __restrict__ gts,  const float* __restrict__ bets,
    const float* __restrict__ mts,  const float* __restrict__ vts,
    const float* __restrict__ w_tq, const float* __restrict__ b_tq,
    const float* __restrict__ gtq,  const float* __restrict__ betq,
    const float* __restrict__ mtq,  const float* __restrict__ vtq)
{
    const int j = blockIdx.z, b = blockIdx.y, n0 = blockIdx.x * 128;
    const float *X, *W, *Bi, *bg = nullptr, *bb = nullptr, *bm = nullptr, *bv = nullptr;
    bf16 *dh = nullptr, *dl = nullptr;
    float* df = nullptr;
    int ocb = 0, co = 0; bool chanmaj = true, hasbn = false;
    switch (j) {
        case 0:  X = q; W = w_v;  Bi = b_v;  dh = g_VQhi; dl = g_VQlo; ocb = 0;  co = 0;  break;
        case 1:  X = q; W = w_v;  Bi = b_v;  dh = g_VQhi; dl = g_VQlo; ocb = 64; co = 64; break;
        case 2:  X = s; W = w_v;  Bi = b_v;  dh = g_VShi; dl = g_VSlo; ocb = 0;  co = 0;  break;
        case 3:  X = s; W = w_v;  Bi = b_v;  dh = g_VShi; dl = g_VSlo; ocb = 64; co = 64; break;
        case 4:  X = q; W = w_k1; Bi = b_k1; dh = g_KThi; dl = g_KTlo; chanmaj = false; co = 0;  break;
        case 5:  X = s; W = w_k2; Bi = b_k2; dh = g_KThi; dl = g_KTlo; chanmaj = false; co = 64; break;
        case 6:  X = q; W = w_q1; Bi = b_q1; dh = g_QThi; dl = g_QTlo; chanmaj = false; co = 0;  break;
        case 7:  X = s; W = w_q2; Bi = b_q2; dh = g_QThi; dl = g_QTlo; chanmaj = false; co = 64; break;
        case 8:  X = s; W = w_ts; Bi = b_ts; df = g_ST; ocb = 0;  co = 0;  hasbn = true; bg = gts; bb = bets; bm = mts; bv = vts; break;
        case 9:  X = s; W = w_ts; Bi = b_ts; df = g_ST; ocb = 64; co = 64; hasbn = true; bg = gts; bb = bets; bm = mts; bv = vts; break;
        case 10: X = q; W = w_tq; Bi = b_tq; df = g_TQ; ocb = 0;  co = 0;  hasbn = true; bg = gtq; bb = betq; bm = mtq; bv = vtq; break;
        default: X = q; W = w_tq; Bi = b_tq; df = g_TQ; ocb = 64; co = 64; hasbn = true; bg = gtq; bb = betq; bm = mtq; bv = vtq; break;
    }
    const float* Xb = X + (size_t)b * NC * NPIX;
    __shared__ float Ws[16][64];
    __shared__ float Xs[16][128];
    float acc[4][8] = {};
    const int t = threadIdx.x, rg = t >> 4, cg = t & 15;

    for (int k0 = 0; k0 < NC; k0 += 16) {
        for (int i = t; i < 1024; i += 256) {
            int oc = i >> 4, kk = i & 15;
            Ws[kk][oc] = W[(ocb + oc) * NC + k0 + kk];
        }
        for (int i = t; i < 2048; i += 256) {
            int kk = i >> 7, px = i & 127;
            Xs[kk][px] = Xb[(size_t)(k0 + kk) * NPIX + n0 + px];
        }
        __syncthreads();
        #pragma unroll
        for (int kk = 0; kk < 16; kk++) {
            float a[4], xv[8];
            #pragma unroll
            for (int i = 0; i < 4; i++) a[i] = Ws[kk][rg * 4 + i];
            #pragma unroll
            for (int jx = 0; jx < 8; jx++) xv[jx] = Xs[kk][cg * 8 + jx];
            #pragma unroll
            for (int i = 0; i < 4; i++)
                #pragma unroll
                for (int jx = 0; jx < 8; jx++) acc[i][jx] += a[i] * xv[jx];
        }
        __syncthreads();
    }
    #pragma unroll
    for (int i = 0; i < 4; i++) {
        int oc = rg * 4 + i, gi = ocb + oc;
        float sc = 1.f, off = Bi[gi];
        if (hasbn) {
            float inv = bg[gi] * rsqrtf(bv[gi] + EPSV);
            sc = inv; off = (Bi[gi] - bm[gi]) * inv + bb[gi];
        }
        #pragma unroll
        for (int jx = 0; jx < 8; jx++) {
            int px = cg * 8 + jx;
            float v = acc[i][jx] * sc + off;
            if (df) {
                df[((size_t)b * CI + co + oc) * NPIX + n0 + px] = v;
            } else {
                size_t idx = chanmaj
                    ? ((size_t)b * CI + co + oc) * NPIX + n0 + px
                    : ((size_t)b * NPIX + n0 + px) * CI + co + oc;
                bf16 h = __float2bfloat16(v);
                dh[idx] = h;
                dl[idx] = __float2bfloat16(v - __bfloat162float(h));
            }
        }
    }
}

// ---------------- conv3x3 via bf16x3 mma + ldmatrix ----------------
#define C3_SMEM 52160
__global__ __launch_bounds__(256) void conv3x3_mma(
    const float* __restrict__ bng, const float* __restrict__ bnb,
    const float* __restrict__ bnm, const float* __restrict__ bnv,
    float* __restrict__ outp_all)
{
    extern __shared__ char sm[];
    const int t = threadIdx.x, lane = t & 31, wid = t >> 5;
    const int g = lane >> 2, tg = lane & 3;
    const int y = blockIdx.x, b = blockIdx.y;
    const int wr = (wid & 3) * 32, wc = (wid >> 2) * 32;
    const bf16* EQh = g_EQhi + (size_t)b * CI * NPIX;
    const bf16* EQl = g_EQlo + (size_t)b * CI * NPIX;
    const bf16* ESh = g_EShi + (size_t)b * CI * NPIX;
    const bf16* ESl = g_ESlo + (size_t)b * CI * NPIX;
    float* outp = outp_all + (size_t)b * CI * NPIX;
    bf16* XH = (bf16*)(sm);
    bf16* XL = (bf16*)(sm + 15840);
    bf16* WHp = (bf16*)(sm + 31680);
    bf16* WLp = (bf16*)(sm + 41920);
    uint32_t sb = smem_u32(sm);
    const uint32_t aXH = sb, aXL = sb + 15840, aWH = sb + 31680, aWL = sb + 41920;

    float c[2][4][4] = {};
    for (int icc = 0; icc < 8; icc++) {
        for (int i = t; i < 32 * 198; i += 256) {
            int icl = i / 198, np = i - icl * 198;
            int r = np / 66, px = np - r * 66;
            int icg = icc * 32 + icl;
            int rg = y + r - 1, x = px - 1;
            bf16 vh = __ushort_as_bfloat16(0), vl = __ushort_as_bfloat16(0);
            if (rg >= 0 && rg < 64 && x >= 0 && x < 64) {
                size_t gi = (size_t)(icg & 127) * NPIX + rg * 64 + x;
                if (icg < 128) { vh = EQh[gi]; vl = EQl[gi]; }
                else           { vh = ESh[gi]; vl = ESl[gi]; }
            }
            XH[np * 40 + icl] = vh;
            XL[np * 40 + icl] = vl;
        }
        __syncthreads();
        for (int tap = 0; tap < 9; tap++) {
            const int dy = tap / 3, dx = tap - dy * 3;
            for (int i = t; i < 4096; i += 256) {
                int oc = i >> 5, icl = i & 31;
                size_t wi = (size_t)tap * 32768 + oc * 256 + icc * 32 + icl;
                WHp[oc * 40 + icl] = g_W3hi[wi];
                WLp[oc * 40 + icl] = g_W3lo[wi];
            }
            __syncthreads();
            const int arow = lane & 15, asel = lane >> 4;
            const int brow = lane & 7,  bsel = (lane >> 3) & 1;
            #pragma unroll
            for (int kb = 0; kb < 16; kb += 8) {
                uint32_t ah[2][4], al[2][4];
                #pragma unroll
                for (int mt = 0; mt < 2; mt++) {
                    uint32_t aoff = ((wr + mt * 16 + arow) * 20 + kb + asel * 4) * 4;
                    ldsm_x4(ah[mt], aWH + aoff);
                    ldsm_x4(al[mt], aWL + aoff);
                }
                #pragma unroll
                for (int nt = 0; nt < 4; nt++) {
                    uint32_t boff = ((dy * 66 + wc + nt * 8 + brow + dx) * 20 + kb + bsel * 4) * 4;
                    uint32_t bh0, bh1, bl0, bl1;
                    ldsm_x2(bh0, bh1, aXH + boff);
                    ldsm_x2(bl0, bl1, aXL + boff);
                    #pragma unroll
                    for (int mt = 0; mt < 2; mt++) {
                        mma_bf16(c[mt][nt], ah[mt], bh0, bh1);
                        mma_bf16(c[mt][nt], al[mt], bh0, bh1);
                        mma_bf16(c[mt][nt], ah[mt], bl0, bl1);
                    }
                }
            }
            __syncthreads();
        }
    }

    float* Tb = (float*)sm;
    #pragma unroll
    for (int mt = 0; mt < 2; mt++)
        #pragma unroll
        for (int nt = 0; nt < 4; nt++)
            #pragma unroll
            for (int i = 0; i < 4; i++) {
                int row = wr + mt * 16 + g + (i >> 1) * 8;
                int col = wc + nt * 8 + tg * 2 + (i & 1);
                Tb[row * 68 + col] = c[mt][nt][i];
            }
    __syncthreads();
    for (int i = t; i < 8192; i += 256) {
        int oc = i >> 6, n = i & 63;
        float inv = bng[oc] * rsqrtf(bnv[oc] + EPSV);
        float off = bnb[oc] - bnm[oc] * inv;
        outp[(size_t)oc * NPIX + y * 64 + n] = fmaxf(Tb[oc * 68 + n] * inv + off, 0.f);
    }
}

// ---------------- launch ----------------
extern "C" void kernel_launch(void* const* d_in, const int* in_sizes, int n_in,
                              void* d_out, int out_size)
{
    (void)in_sizes; (void)n_in; (void)out_size;
    const float* q     = (const float*)d_in[0];
    const float* s     = (const float*)d_in[1];
    const float* scale = (const float*)d_in[2];
    const float* w_v   = (const float*)d_in[3];  const float* b_v  = (const float*)d_in[4];
    const float* w_k1  = (const float*)d_in[5];  const float* b_k1 = (const float*)d_in[6];
    const float* w_q1  = (const float*)d_in[7];  const float* b_q1 = (const float*)d_in[8];
    const float* w_k2  = (const float*)d_in[9];  const float* b_k2 = (const float*)d_in[10];
    const float* w_q2  = (const float*)d_in[11]; const float* b_q2 = (const float*)d_in[12];
    const float* w_ts  = (const float*)d_in[13]; const float* b_ts = (const float*)d_in[14];
    const float* gts   = (const float*)d_in[15]; const float* bets = (const float*)d_in[16];
    const float* mts   = (const float*)d_in[17]; const float* vts  = (const float*)d_in[18];
    const float* w_tq  = (const float*)d_in[19]; const float* b_tq = (const float*)d_in[20];
    const float* gtq   = (const float*)d_in[21]; const float* betq = (const float*)d_in[22];
    const float* mtq   = (const float*)d_in[23]; const float* vtq  = (const float*)d_in[24];
    const float* w_cat = (const float*)d_in[25];
    const float* gcat  = (const float*)d_in[26]; const float* becat= (const float*)d_in[27];
    const float* mcat  = (const float*)d_in[28]; const float* vcat = (const float*)d_in[29];

    float* out  = (float*)d_out;
    float* cpam = out;
    float* Eq   = out + (size_t)NB * CI * NPIX;
    float* Es   = out + 2 * (size_t)NB * CI * NPIX;

    cudaFuncSetAttribute(gemmA_mma,   cudaFuncAttributeMaxDynamicSharedMemorySize, GA_SMEM);
    cudaFuncSetAttribute(pv_mma,      cudaFuncAttributeMaxDynamicSharedMemorySize, PV_SMEM);
    cudaFuncSetAttribute(conv3x3_mma, cudaFuncAttributeMaxDynamicSharedMemorySize, C3_SMEM);

    zero_sums<<<(NB * NPIX + 255) / 256, 256>>>();
    w3prep<<<(9 * 128 * 256 + 255) / 256, 256>>>(w_cat);
    convs_kernel<<<dim3(32, NB, 12), 256>>>(q, s, w_v, b_v, w_k1, b_k1, w_q1, b_q1,
                                            w_k2, b_k2, w_q2, b_q2, w_ts, b_ts,
                                            gts, bets, mts, vts, w_tq, b_tq,
                                            gtq, betq, mtq, vtq);
    gemmA_mma<<<dim3(32, 32, NB), 256, GA_SMEM>>>();
    pv_mma<<<dim3(32, NB, 2), 256, PV_SMEM>>>(scale, Eq, Es);
    conv3x3_mma<<<dim3(64, NB), 256, C3_SMEM>>>(gcat, becat, mcat, vcat, cpam);
}

// round 14
// speedup vs baseline: 1.3056x; 1.0842x over previous
#include <cuda_runtime.h>
#include <cuda_bf16.h>
#include <cstdint>

#define NB   2
#define NC   256
#define NPIX 4096
#define CI   128
#define EPSV 1e-5f

typedef __nv_bfloat16 bf16;

__device__ bf16 g_Ehi [(size_t)NB * NPIX * NPIX];
__device__ bf16 g_EThi[(size_t)NB * NPIX * NPIX];
__device__ bf16 g_VQhi[(size_t)NB * CI * NPIX];
__device__ bf16 g_VQlo[(size_t)NB * CI * NPIX];
__device__ bf16 g_VShi[(size_t)NB * CI * NPIX];
__device__ bf16 g_VSlo[(size_t)NB * CI * NPIX];
__device__ bf16 g_KThi[(size_t)NB * NPIX * CI];
__device__ bf16 g_KTlo[(size_t)NB * NPIX * CI];
__device__ bf16 g_QThi[(size_t)NB * NPIX * CI];
__device__ bf16 g_QTlo[(size_t)NB * NPIX * CI];
__device__ float g_ST [(size_t)NB * CI * NPIX];
__device__ float g_TQ [(size_t)NB * CI * NPIX];
__device__ float g_rowsum[NB * NPIX];
__device__ float g_colsum[NB * NPIX];
__device__ bf16 g_EQhi[(size_t)NB * CI * NPIX];
__device__ bf16 g_EQlo[(size_t)NB * CI * NPIX];
__device__ bf16 g_EShi[(size_t)NB * CI * NPIX];
__device__ bf16 g_ESlo[(size_t)NB * CI * NPIX];
__device__ bf16 g_W3hi[9 * 128 * 256];
__device__ bf16 g_W3lo[9 * 128 * 256];

// ---------------- helpers ----------------
__device__ __forceinline__ uint32_t smem_u32(const void* p) {
    uint32_t a;
    asm("{ .reg .u64 t; cvta.to.shared.u64 t, %1; cvt.u32.u64 %0, t; }" : "=r"(a) : "l"(p));
    return a;
}
__device__ __forceinline__ void cp16(uint32_t dst, const void* src) {
    asm volatile("cp.async.cg.shared.global [%0], [%1], 16;" :: "r"(dst), "l"(src));
}
#define CP_COMMIT() asm volatile("cp.async.commit_group;" ::: "memory")
#define CP_WAIT(n)  asm volatile("cp.async.wait_group %0;" :: "n"(n) : "memory")

__device__ __forceinline__ void mma_bf16(float* c, const uint32_t* a, uint32_t b0, uint32_t b1) {
    asm("mma.sync.aligned.m16n8k16.row.col.f32.bf16.bf16.f32 "
        "{%0,%1,%2,%3},{%4,%5,%6,%7},{%8,%9},{%0,%1,%2,%3};"
        : "+f"(c[0]), "+f"(c[1]), "+f"(c[2]), "+f"(c[3])
        : "r"(a[0]), "r"(a[1]), "r"(a[2]), "r"(a[3]), "r"(b0), "r"(b1));
}
__device__ __forceinline__ void ldsm_x4(uint32_t* r, uint32_t addr) {
    asm volatile("ldmatrix.sync.aligned.m8n8.x4.shared.b16 {%0,%1,%2,%3}, [%4];"
        : "=r"(r[0]), "=r"(r[1]), "=r"(r[2]), "=r"(r[3]) : "r"(addr));
}
__device__ __forceinline__ void ldsm_x2(uint32_t& r0, uint32_t& r1, uint32_t addr) {
    asm volatile("ldmatrix.sync.aligned.m8n8.x2.shared.b16 {%0,%1}, [%2];"
        : "=r"(r0), "=r"(r1) : "r"(addr));
}
__device__ __forceinline__ uint32_t pack2(float x, float y) {
    bf16 hx = __float2bfloat16(x), hy = __float2bfloat16(y);
    return (uint32_t)__bfloat16_as_ushort(hx) | ((uint32_t)__bfloat16_as_ushort(hy) << 16);
}
__device__ __forceinline__ uint32_t pack2lo(float x, float y) {
    bf16 hx = __float2bfloat16(x), hy = __float2bfloat16(y);
    bf16 lx = __float2bfloat16(x - __bfloat162float(hx));
    bf16 ly = __float2bfloat16(y - __bfloat162float(hy));
    return (uint32_t)__bfloat16_as_ushort(lx) | ((uint32_t)__bfloat16_as_ushort(ly) << 16);
}
__device__ __forceinline__ bf16 hi_of(float x) { return __float2bfloat16(x); }
__device__ __forceinline__ bf16 lo_of(float x, bf16 h) {
    return __float2bfloat16(x - __bfloat162float(h));
}

// bf16x3 step: A hi/lo, B hi/lo (128-row A-tile, 8 nt)
template<int ST>
__device__ __forceinline__ void mma_step_l(uint32_t Ahi, uint32_t Alo,
                                           uint32_t Bhi, uint32_t Blo,
                                           int kb, int wr, int wc, int lane, float c[2][8][4])
{
    const int arow = lane & 15, asel = lane >> 4;
    const int brow = lane & 7,  bsel = (lane >> 3) & 1;
    uint32_t ah[2][4], al[2][4];
    #pragma unroll
    for (int mt = 0; mt < 2; mt++) {
        uint32_t aoff = ((wr + mt * 16 + arow) * ST + kb + asel * 4) * 4;
        ldsm_x4(ah[mt], Ahi + aoff);
        ldsm_x4(al[mt], Alo + aoff);
    }
    #pragma unroll
    for (int nt = 0; nt < 8; nt++) {
        uint32_t boff = ((wc + nt * 8 + brow) * ST + kb + bsel * 4) * 4;
        uint32_t bh0, bh1, bl0, bl1;
        ldsm_x2(bh0, bh1, Bhi + boff);
        ldsm_x2(bl0, bl1, Blo + boff);
        #pragma unroll
        for (int mt = 0; mt < 2; mt++) {
            mma_bf16(c[mt][nt], ah[mt], bh0, bh1);
            mma_bf16(c[mt][nt], al[mt], bh0, bh1);
            mma_bf16(c[mt][nt], ah[mt], bl0, bl1);
        }
    }
}

// bf16x2 step (pv): A single plane
template<int ST>
__device__ __forceinline__ void mma_step_2(uint32_t Ahi, uint32_t Bhi, uint32_t Blo,
                                           int kb, int wr, int wc, int lane, float c[2][8][4])
{
    const int arow = lane & 15, asel = lane >> 4;
    const int brow = lane & 7,  bsel = (lane >> 3) & 1;
    uint32_t ah[2][4];
    #pragma unroll
    for (int mt = 0; mt < 2; mt++) {
        uint32_t aoff = ((wr + mt * 16 + arow) * ST + kb + asel * 4) * 4;
        ldsm_x4(ah[mt], Ahi + aoff);
    }
    #pragma unroll
    for (int nt = 0; nt < 8; nt++) {
        uint32_t boff = ((wc + nt * 8 + brow) * ST + kb + bsel * 4) * 4;
        uint32_t bh0, bh1, bl0, bl1;
        ldsm_x2(bh0, bh1, Bhi + boff);
        ldsm_x2(bl0, bl1, Blo + boff);
        #pragma unroll
        for (int mt = 0; mt < 2; mt++) {
            mma_bf16(c[mt][nt], ah[mt], bh0, bh1);
            mma_bf16(c[mt][nt], ah[mt], bl0, bl1);
        }
    }
}

__global__ void zero_sums() {
    int i = blockIdx.x * 256 + threadIdx.x;
    if (i < NB * NPIX) { g_rowsum[i] = 0.f; g_colsum[i] = 0.f; }
}

__global__ void w3prep(const float* __restrict__ Wc) {
    int i = blockIdx.x * 256 + threadIdx.x;
    if (i >= 9 * 128 * 256) return;
    int tap = i >> 15, oc = (i >> 8) & 127, ic = i & 255;
    float v = Wc[(size_t)oc * 2304 + ic * 9 + tap];
    bf16 h = __float2bfloat16(v);
    g_W3hi[i] = h;
    g_W3lo[i] = __float2bfloat16(v - __bfloat162float(h));
}

// ============ gemmA (unchanged from R12 best) ============
#define GA_SMEM 73728
__global__ __launch_bounds__(256, 2) void gemmA_mma()
{
    extern __shared__ char sm[];
    const int t = threadIdx.x, lane = t & 31, wid = t >> 5;
    const int g = lane >> 2, tg = lane & 3;
    const int b = blockIdx.z, n0 = blockIdx.x * 128, m0 = blockIdx.y * 128;
    const int wr = (wid & 3) * 32, wc = (wid >> 2) * 64;
    const bf16* A_hi = g_KThi + (size_t)b * NPIX * CI + (size_t)n0 * CI;
    const bf16* A_lo = g_KTlo + (size_t)b * NPIX * CI + (size_t)n0 * CI;
    const bf16* B_hi = g_QThi + (size_t)b * NPIX * CI + (size_t)m0 * CI;
    const bf16* B_lo = g_QTlo + (size_t)b * NPIX * CI + (size_t)m0 * CI;
    uint32_t sb = smem_u32(sm);

    float c[2][8][4] = {};
    #pragma unroll
    for (int kc = 0; kc < 2; kc++) {
        #pragma unroll
        for (int p = 0; p < 4; p++) {
            int i = t + p * 256;
            int row = i >> 3, seg = i & 7;
            size_t go = (size_t)row * CI + kc * 64 + seg * 8;
            uint32_t so = row * 144 + seg * 16;
            cp16(sb + so,         A_hi + go);
            cp16(sb + 18432 + so, A_lo + go);
            cp16(sb + 36864 + so, B_hi + go);
            cp16(sb + 55296 + so, B_lo + go);
        }
        CP_COMMIT();
        CP_WAIT(0);
        __syncthreads();
        #pragma unroll
        for (int kb = 0; kb < 32; kb += 8)
            mma_step_l<36>(sb, sb + 18432, sb + 36864, sb + 55296, kb, wr, wc, lane, c);
        __syncthreads();
    }

    #pragma unroll
    for (int mt = 0; mt < 2; mt++)
        #pragma unroll
        for (int nt = 0; nt < 8; nt++)
            #pragma unroll
            for (int i = 0; i < 4; i++)
                c[mt][nt][i] = __expf(c[mt][nt][i]);

    #pragma unroll
    for (int mt = 0; mt < 2; mt++)
        #pragma unroll
        for (int h = 0; h < 2; h++) {
            float v = 0.f;
            #pragma unroll
            for (int nt = 0; nt < 8; nt++) v += c[mt][nt][2 * h] + c[mt][nt][2 * h + 1];
            v += __shfl_xor_sync(0xffffffffu, v, 1);
            v += __shfl_xor_sync(0xffffffffu, v, 2);
            if (tg == 0) atomicAdd(g_rowsum + b * NPIX + n0 + wr + mt * 16 + g + 8 * h, v);
        }
    #pragma unroll
    for (int nt = 0; nt < 8; nt++)
        #pragma unroll
        for (int jj = 0; jj < 2; jj++) {
            float v = c[0][nt][jj] + c[0][nt][2 + jj] + c[1][nt][jj] + c[1][nt][2 + jj];
            v += __shfl_xor_sync(0xffffffffu, v, 4);
            v += __shfl_xor_sync(0xffffffffu, v, 8);
            v += __shfl_xor_sync(0xffffffffu, v, 16);
            if (g == 0) atomicAdd(g_colsum + b * NPIX + m0 + wc + nt * 8 + tg * 2 + jj, v);
        }

    float* Tb = (float*)sm;
    #pragma unroll
    for (int mt = 0; mt < 2; mt++)
        #pragma unroll
        for (int nt = 0; nt < 8; nt++)
            #pragma unroll
            for (int i = 0; i < 4; i++) {
                int row = wr + mt * 16 + g + (i >> 1) * 8;
                int col = wc + nt * 8 + tg * 2 + (i & 1);
                Tb[row * 128 + ((col + row) & 127)] = c[mt][nt][i];
            }
    __syncthreads();

    bf16* Ehi  = g_Ehi  + (size_t)b * NPIX * NPIX;
    bf16* EThi = g_EThi + (size_t)b * NPIX * NPIX;

    for (int i = t; i < 8192; i += 256) {
        int r = i >> 6, c2 = (i & 63) * 2;
        float v0 = Tb[r * 128 + ((c2 + r) & 127)];
        float v1 = Tb[r * 128 + ((c2 + 1 + r) & 127)];
        *(uint32_t*)(Ehi + (size_t)(n0 + r) * NPIX + m0 + c2) = pack2(v0, v1);
    }
    for (int i = t; i < 8192; i += 256) {
        int cl = i >> 6, r2 = (i & 63) * 2;
        float v0 = Tb[(r2) * 128 + ((cl + r2) & 127)];
        float v1 = Tb[(r2 + 1) * 128 + ((cl + r2 + 1) & 127)];
        *(uint32_t*)(EThi + (size_t)(m0 + cl) * NPIX + n0 + r2) = pack2(v0, v1);
    }
}

// ============ pv (unchanged from R12 best) ============
#define PV_SMEM 111104
__global__ __launch_bounds__(256, 2) void pv_mma(const float* __restrict__ scale_p,
                                                 float* __restrict__ outEq,
                                                 float* __restrict__ outEs)
{
    extern __shared__ char sm[];
    const int t = threadIdx.x, lane = t & 31, wid = t >> 5;
    const int g = lane >> 2, tg = lane & 3;
    const int r0 = blockIdx.x * 128, b = blockIdx.y, mode = blockIdx.z;
    const int wr = (wid & 3) * 32, wc = (wid >> 2) * 64;
    const bf16* A_hi = (mode ? g_EThi : g_Ehi) + (size_t)b * NPIX * NPIX + (size_t)r0 * NPIX;
    const bf16* B_hi = (mode ? g_VQhi : g_VShi) + (size_t)b * CI * NPIX;
    const bf16* B_lo = (mode ? g_VQlo : g_VSlo) + (size_t)b * CI * NPIX;
    const float* sums = (mode ? g_colsum : g_rowsum) + (size_t)b * NPIX + r0;
    const float* T = (mode ? g_TQ : g_ST) + (size_t)b * CI * NPIX;
    float* outp = (mode ? outEq : outEs) + (size_t)b * CI * NPIX;
    bf16* Fh = (mode ? g_EQhi : g_EShi) + (size_t)b * CI * NPIX;
    bf16* Fl = (mode ? g_EQlo : g_ESlo) + (size_t)b * CI * NPIX;
    uint32_t sb = smem_u32(sm);
    float* RS = (float*)(sm + 110592);
    if (t < 128) RS[t] = scale_p[0] / sums[t];

    #pragma unroll
    for (int p = 0; p < 4; p++) {
        int i = t + p * 256;
        int row = i >> 3, seg = i & 7;
        size_t go = (size_t)row * NPIX + seg * 8;
        uint32_t so = row * 144 + seg * 16;
        cp16(sb + so,         A_hi + go);
        cp16(sb + 18432 + so, B_hi + go);
        cp16(sb + 36864 + so, B_lo + go);
    }
    CP_COMMIT();

    float c[2][8][4] = {};
    for (int kc = 0; kc < 64; kc++) {
        const int st = kc & 1;
        if (kc + 1 < 64) {
            const int st2 = (kc + 1) & 1;
            #pragma unroll
            for (int p = 0; p < 4; p++) {
                int i = t + p * 256;
                int row = i >> 3, seg = i & 7;
                size_t go = (size_t)row * NPIX + (kc + 1) * 64 + seg * 8;
                uint32_t so = st2 * 55296 + row * 144 + seg * 16;
                cp16(sb + so,         A_hi + go);
                cp16(sb + 18432 + so, B_hi + go);
                cp16(sb + 36864 + so, B_lo + go);
            }
            CP_COMMIT();
            CP_WAIT(1);
        } else {
            CP_WAIT(0);
        }
        __syncthreads();
        uint32_t base = sb + st * 55296;
        #pragma unroll
        for (int kb = 0; kb < 32; kb += 8)
            mma_step_2<36>(base, base + 18432, base + 36864, kb, wr, wc, lane, c);
        __syncthreads();
    }

    float* Tb = (float*)sm;
    #pragma unroll
    for (int mt = 0; mt < 2; mt++)
        #pragma unroll
        for (int nt = 0; nt < 8; nt++)
            #pragma unroll
            for (int i = 0; i < 4; i++) {
                int row = wr + mt * 16 + g + (i >> 1) * 8;
                int col = wc + nt * 8 + tg * 2 + (i & 1);
                Tb[row * 128 + ((col + row) & 127)] = c[mt][nt][i] * RS[row];
            }
    __syncthreads();
    for (int i = t; i < 16384; i += 256) {
        int cl = i >> 7, r = i & 127;
        float v = Tb[r * 128 + ((cl + r) & 127)];
        size_t gi = (size_t)cl * NPIX + r0 + r;
        float o = v + T[gi];
        outp[gi] = o;
        bf16 h = hi_of(o);
        Fh[gi] = h;
        Fl[gi] = lo_of(o, h);
    }
}

// ============ convs via bf16x3 mma: FIXED smem layout ============
// Ahi@0 (9216 = 64 rows x 144B), Alo@9216, Bhi@18432 (18432 = 128 x 144B), Blo@36864
// SC@55296, OFF@55552. Tb [64][128] f32 (32768) aliases A/B region. Total 55808.
#define CV_SMEM 55808
__global__ __launch_bounds__(256, 2) void convs_mma(
    const float* __restrict__ q, const float* __restrict__ s,
    const float* __restrict__ w_v,  const float* __restrict__ b_v,
    const float* __restrict__ w_k1, const float* __restrict__ b_k1,
    const float* __restrict__ w_q1, const float* __restrict__ b_q1,
    const float* __restrict__ w_k2, const float* __restrict__ b_k2,
    const float* __restrict__ w_q2, const float* __restrict__ b_q2,
    const float* __restrict__ w_ts, const float* __restrict__ b_ts,
    const float* __restrict__ gts,  const float* __restrict__ bets,
    const float* __restrict__ mts,  const float* __restrict__ vts,
    const float* __restrict__ w_tq, const float* __restrict__ b_tq,
    const float* __restrict__ gtq,  const float* __restrict__ betq,
    const float* __restrict__ mtq,  const float* __restrict__ vtq)
{
    extern __shared__ char sm[];
    const int j = blockIdx.z, b = blockIdx.y, n0 = blockIdx.x * 128;
    const int t = threadIdx.x, lane = t & 31, wid = t >> 5;
    const int g = lane >> 2, tg = lane & 3;
    const int wr = (wid & 1) * 32, wc = (wid >> 1) * 32;
    const float *X, *W, *Bi, *bg = nullptr, *bbp = nullptr, *bm = nullptr, *bv = nullptr;
    bf16 *dh = nullptr, *dl = nullptr;
    float* df = nullptr;
    int ocb = 0, co = 0; bool chanmaj = true, hasbn = false;
    switch (j) {
        case 0:  X = q; W = w_v;  Bi = b_v;  dh = g_VQhi; dl = g_VQlo; ocb = 0;  co = 0;  break;
        case 1:  X = q; W = w_v;  Bi = b_v;  dh = g_VQhi; dl = g_VQlo; ocb = 64; co = 64; break;
        case 2:  X = s; W = w_v;  Bi = b_v;  dh = g_VShi; dl = g_VSlo; ocb = 0;  co = 0;  break;
        case 3:  X = s; W = w_v;  Bi = b_v;  dh = g_VShi; dl = g_VSlo; ocb = 64; co = 64; break;
        case 4:  X = q; W = w_k1; Bi = b_k1; dh = g_KThi; dl = g_KTlo; chanmaj = false; co = 0;  break;
        case 5:  X = s; W = w_k2; Bi = b_k2; dh = g_KThi; dl = g_KTlo; chanmaj = false; co = 64; break;
        case 6:  X = q; W = w_q1; Bi = b_q1; dh = g_QThi; dl = g_QTlo; chanmaj = false; co = 0;  break;
        case 7:  X = s; W = w_q2; Bi = b_q2; dh = g_QThi; dl = g_QTlo; chanmaj = false; co = 64; break;
        case 8:  X = s; W = w_ts; Bi = b_ts; df = g_ST; ocb = 0;  co = 0;  hasbn = true; bg = gts; bbp = bets; bm = mts; bv = vts; break;
        case 9:  X = s; W = w_ts; Bi = b_ts; df = g_ST; ocb = 64; co = 64; hasbn = true; bg = gts; bbp = bets; bm = mts; bv = vts; break;
        case 10: X = q; W = w_tq; Bi = b_tq; df = g_TQ; ocb = 0;  co = 0;  hasbn = true; bg = gtq; bbp = betq; bm = mtq; bv = vtq; break;
        default: X = q; W = w_tq; Bi = b_tq; df = g_TQ; ocb = 64; co = 64; hasbn = true; bg = gtq; bbp = betq; bm = mtq; bv = vtq; break;
    }
    const float* Xb = X + (size_t)b * NC * NPIX;
    uint32_t sb = smem_u32(sm);
    float* SC  = (float*)(sm + 55296);
    float* OFF = (float*)(sm + 55552);
    if (t < 64) {
        int gi = ocb + t;
        float sc = 1.f, off = Bi[gi];
        if (hasbn) {
            float inv = bg[gi] * rsqrtf(bv[gi] + EPSV);
            sc = inv; off = (Bi[gi] - bm[gi]) * inv + bbp[gi];
        }
        SC[t] = sc; OFF[t] = off;
    }

    float c[2][4][4] = {};
    for (int kc = 0; kc < 4; kc++) {
        __syncthreads();
        // stage A (weights): 64 oc x 64 ic, stride 144B
        #pragma unroll
        for (int p = 0; p < 4; p++) {
            int i = t + p * 256;
            int oc = i >> 4, seg = i & 15;      // seg: 4 floats
            float4 v = *(const float4*)(W + (size_t)(ocb + oc) * NC + kc * 64 + seg * 4);
            uint32_t off = oc * 144 + seg * 8;
            *(uint2*)(sm + off)        = make_uint2(pack2(v.x, v.y), pack2(v.z, v.w));
            *(uint2*)(sm + 9216 + off) = make_uint2(pack2lo(v.x, v.y), pack2lo(v.z, v.w));
        }
        // stage B (inputs, transposed): 128 px x 64 ic, stride 144B
        #pragma unroll
        for (int p = 0; p < 8; p++) {
            int i = t + p * 256;
            int ic = i >> 5, px4 = (i & 31) * 4;
            float4 v = *(const float4*)(Xb + (size_t)(kc * 64 + ic) * NPIX + n0 + px4);
            float vs[4] = {v.x, v.y, v.z, v.w};
            #pragma unroll
            for (int jj = 0; jj < 4; jj++) {
                uint32_t off = (px4 + jj) * 144 + ic * 2;
                bf16 h = hi_of(vs[jj]);
                *(bf16*)(sm + 18432 + off) = h;
                *(bf16*)(sm + 36864 + off) = lo_of(vs[jj], h);
            }
        }
        __syncthreads();
        const int arow = lane & 15, asel = lane >> 4;
        const int brow = lane & 7,  bsel = (lane >> 3) & 1;
        #pragma unroll
        for (int kb = 0; kb < 32; kb += 8) {
            uint32_t ah[2][4], al[2][4];
            #pragma unroll
            for (int mt = 0; mt < 2; mt++) {
                uint32_t aoff = (wr + mt * 16 + arow) * 144 + (kb + asel * 4) * 4;
                ldsm_x4(ah[mt], sb + aoff);
                ldsm_x4(al[mt], sb + 9216 + aoff);
            }
            #pragma unroll
            for (int nt = 0; nt < 4; nt++) {
                uint32_t boff = (wc + nt * 8 + brow) * 144 + (kb + bsel * 4) * 4;
                uint32_t bh0, bh1, bl0, bl1;
                ldsm_x2(bh0, bh1, sb + 18432 + boff);
                ldsm_x2(bl0, bl1, sb + 36864 + boff);
                #pragma unroll
                for (int mt = 0; mt < 2; mt++) {
                    mma_bf16(c[mt][nt], ah[mt], bh0, bh1);
                    mma_bf16(c[mt][nt], al[mt], bh0, bh1);
                    mma_bf16(c[mt][nt], ah[mt], bl0, bl1);
                }
            }
        }
    }
    __syncthreads();

    // rotated staging (64 rows x 128 cols)
    float* Tb = (float*)sm;
    #pragma unroll
    for (int mt = 0; mt < 2; mt++)
        #pragma unroll
        for (int nt = 0; nt < 4; nt++)
            #pragma unroll
            for (int i = 0; i < 4; i++) {
                int row = wr + mt * 16 + g + (i >> 1) * 8;
                int col = wc + nt * 8 + tg * 2 + (i & 1);
                Tb[row * 128 + ((col + row) & 127)] = c[mt][nt][i] * SC[row] + OFF[row];
            }
    __syncthreads();

    if (df) {                                   // f32 chan-major
        float* dst = df + ((size_t)b * CI + co) * NPIX + n0;
        for (int i = t; i < 8192; i += 256) {
            int oc = i >> 7, px = i & 127;
            dst[(size_t)oc * NPIX + px] = Tb[oc * 128 + ((px + oc) & 127)];
        }
    } else if (chanmaj) {                       // bf16 hi/lo chan-major (V)
        bf16* dsth = dh + ((size_t)b * CI + co) * NPIX + n0;
        bf16* dstl = dl + ((size_t)b * CI + co) * NPIX + n0;
        for (int i = t; i < 4096; i += 256) {
            int oc = i >> 6, px2 = (i & 63) * 2;
            float v0 = Tb[oc * 128 + ((px2 + oc) & 127)];
            float v1 = Tb[oc * 128 + ((px2 + 1 + oc) & 127)];
            *(uint32_t*)(dsth + (size_t)oc * NPIX + px2) = pack2(v0, v1);
            *(uint32_t*)(dstl + (size_t)oc * NPIX + px2) = pack2lo(v0, v1);
        }
    } else {                                    // bf16 hi/lo pixel-major (KT/QT)
        bf16* dsth = dh + ((size_t)b * NPIX + n0) * CI + co;
        bf16* dstl = dl + ((size_t)b * NPIX + n0) * CI + co;
        for (int i = t; i < 4096; i += 256) {
            int px = i >> 5, oc2 = (i & 31) * 2;
            float v0 = Tb[oc2 * 128 + ((px + oc2) & 127)];
            float v1 = Tb[(oc2 + 1) * 128 + ((px + oc2 + 1) & 127)];
            *(uint32_t*)(dsth + (size_t)px * CI + oc2) = pack2(v0, v1);
            *(uint32_t*)(dstl + (size_t)px * CI + oc2) = pack2lo(v0, v1);
        }
    }
}

// ---------------- conv3x3 via bf16x3 mma + ldmatrix (unchanged) ----------------
#define C3_SMEM 52160
__global__ __launch_bounds__(256) void conv3x3_mma(
    const float* __restrict__ bng, const float* __restrict__ bnb,
    const float* __restrict__ bnm, const float* __restrict__ bnv,
    float* __restrict__ outp_all)
{
    extern __shared__ char sm[];
    const int t = threadIdx.x, lane = t & 31, wid = t >> 5;
    const int g = lane >> 2, tg = lane & 3;
    const int y = blockIdx.x, b = blockIdx.y;
    const int wr = (wid & 3) * 32, wc = (wid >> 2) * 32;
    const bf16* EQh = g_EQhi + (size_t)b * CI * NPIX;
    const bf16* EQl = g_EQlo + (size_t)b * CI * NPIX;
    const bf16* ESh = g_EShi + (size_t)b * CI * NPIX;
    const bf16* ESl = g_ESlo + (size_t)b * CI * NPIX;
    float* outp = outp_all + (size_t)b * CI * NPIX;
    bf16* XH = (bf16*)(sm);
    bf16* XL = (bf16*)(sm + 15840);
    bf16* WHp = (bf16*)(sm + 31680);
    bf16* WLp = (bf16*)(sm + 41920);
    uint32_t sb = smem_u32(sm);
    const uint32_t aXH = sb, aXL = sb + 15840, aWH = sb + 31680, aWL = sb + 41920;

    float c[2][4][4] = {};
    for (int icc = 0; icc < 8; icc++) {
        for (int i = t; i < 32 * 198; i += 256) {
            int icl = i / 198, np = i - icl * 198;
            int r = np / 66, px = np - r * 66;
            int icg = icc * 32 + icl;
            int rg = y + r - 1, x = px - 1;
            bf16 vh = __ushort_as_bfloat16(0), vl = __ushort_as_bfloat16(0);
            if (rg >= 0 && rg < 64 && x >= 0 && x < 64) {
                size_t gi = (size_t)(icg & 127) * NPIX + rg * 64 + x;
                if (icg < 128) { vh = EQh[gi]; vl = EQl[gi]; }
                else           { vh = ESh[gi]; vl = ESl[gi]; }
            }
            XH[np * 40 + icl] = vh;
            XL[np * 40 + icl] = vl;
        }
        __syncthreads();
        for (int tap = 0; tap < 9; tap++) {
            const int dy = tap / 3, dx = tap - dy * 3;
            for (int i = t; i < 4096; i += 256) {
                int oc = i >> 5, icl = i & 31;
                size_t wi = (size_t)tap * 32768 + oc * 256 + icc * 32 + icl;
                WHp[oc * 40 + icl] = g_W3hi[wi];
                WLp[oc * 40 + icl] = g_W3lo[wi];
            }
            __syncthreads();
            const int arow = lane & 15, asel = lane >> 4;
            const int brow = lane & 7,  bsel = (lane >> 3) & 1;
            #pragma unroll
            for (int kb = 0; kb < 16; kb += 8) {
                uint32_t ah[2][4], al[2][4];
                #pragma unroll
                for (int mt = 0; mt < 2; mt++) {
                    uint32_t aoff = ((wr + mt * 16 + arow) * 20 + kb + asel * 4) * 4;
                    ldsm_x4(ah[mt], aWH + aoff);
                    ldsm_x4(al[mt], aWL + aoff);
                }
                #pragma unroll
                for (int nt = 0; nt < 4; nt++) {
                    uint32_t boff = ((dy * 66 + wc + nt * 8 + brow + dx) * 20 + kb + bsel * 4) * 4;
                    uint32_t bh0, bh1, bl0, bl1;
                    ldsm_x2(bh0, bh1, aXH + boff);
                    ldsm_x2(bl0, bl1, aXL + boff);
                    #pragma unroll
                    for (int mt = 0; mt < 2; mt++) {
                        mma_bf16(c[mt][nt], ah[mt], bh0, bh1);
                        mma_bf16(c[mt][nt], al[mt], bh0, bh1);
                        mma_bf16(c[mt][nt], ah[mt], bl0, bl1);
                    }
                }
            }
            __syncthreads();
        }
    }

    float* Tb = (float*)sm;
    #pragma unroll
    for (int mt = 0; mt < 2; mt++)
        #pragma unroll
        for (int nt = 0; nt < 4; nt++)
            #pragma unroll
            for (int i = 0; i < 4; i++) {
                int row = wr + mt * 16 + g + (i >> 1) * 8;
                int col = wc + nt * 8 + tg * 2 + (i & 1);
                Tb[row * 68 + col] = c[mt][nt][i];
            }
    __syncthreads();
    for (int i = t; i < 8192; i += 256) {
        int oc = i >> 6, n = i & 63;
        float inv = bng[oc] * rsqrtf(bnv[oc] + EPSV);
        float off = bnb[oc] - bnm[oc] * inv;
        outp[(size_t)oc * NPIX + y * 64 + n] = fmaxf(Tb[oc * 68 + n] * inv + off, 0.f);
    }
}

// ---------------- launch ----------------
extern "C" void kernel_launch(void* const* d_in, const int* in_sizes, int n_in,
                              void* d_out, int out_size)
{
    (void)in_sizes; (void)n_in; (void)out_size;
    const float* q     = (const float*)d_in[0];
    const float* s     = (const float*)d_in[1];
    const float* scale = (const float*)d_in[2];
    const float* w_v   = (const float*)d_in[3];  const float* b_v  = (const float*)d_in[4];
    const float* w_k1  = (const float*)d_in[5];  const float* b_k1 = (const float*)d_in[6];
    const float* w_q1  = (const float*)d_in[7];  const float* b_q1 = (const float*)d_in[8];
    const float* w_k2  = (const float*)d_in[9];  const float* b_k2 = (const float*)d_in[10];
    const float* w_q2  = (const float*)d_in[11]; const float* b_q2 = (const float*)d_in[12];
    const float* w_ts  = (const float*)d_in[13]; const float* b_ts = (const float*)d_in[14];
    const float* gts   = (const float*)d_in[15]; const float* bets = (const float*)d_in[16];
    const float* mts   = (const float*)d_in[17]; const float* vts  = (const float*)d_in[18];
    const float* w_tq  = (const float*)d_in[19]; const float* b_tq = (const float*)d_in[20];
    const float* gtq   = (const float*)d_in[21]; const float* betq = (const float*)d_in[22];
    const float* mtq   = (const float*)d_in[23]; const float* vtq  = (const float*)d_in[24];
    const float* w_cat = (const float*)d_in[25];
    const float* gcat  = (const float*)d_in[26]; const float* becat= (const float*)d_in[27];
    const float* mcat  = (const float*)d_in[28]; const float* vcat = (const float*)d_in[29];

    float* out  = (float*)d_out;
    float* cpam = out;
    float* Eq   = out + (size_t)NB * CI * NPIX;
    float* Es   = out + 2 * (size_t)NB * CI * NPIX;

    cudaFuncSetAttribute(gemmA_mma,   cudaFuncAttributeMaxDynamicSharedMemorySize, GA_SMEM);
    cudaFuncSetAttribute(pv_mma,      cudaFuncAttributeMaxDynamicSharedMemorySize, PV_SMEM);
    cudaFuncSetAttribute(convs_mma,   cudaFuncAttributeMaxDynamicSharedMemorySize, CV_SMEM);
    cudaFuncSetAttribute(conv3x3_mma, cudaFuncAttributeMaxDynamicSharedMemorySize, C3_SMEM);

    zero_sums<<<(NB * NPIX + 255) / 256, 256>>>();
    w3prep<<<(9 * 128 * 256 + 255) / 256, 256>>>(w_cat);
    convs_mma<<<dim3(32, NB, 12), 256, CV_SMEM>>>(q, s, w_v, b_v, w_k1, b_k1, w_q1, b_q1,
                                                  w_k2, b_k2, w_q2, b_q2, w_ts, b_ts,
                                                  gts, bets, mts, vts, w_tq, b_tq,
                                                  gtq, betq, mtq, vtq);
    gemmA_mma<<<dim3(32, 32, NB), 256, GA_SMEM>>>();
    pv_mma<<<dim3(32, NB, 2), 256, PV_SMEM>>>(scale, Eq, Es);
    conv3x3_mma<<<dim3(64, NB), 256, C3_SMEM>>>(gcat, becat, mcat, vcat, cpam);
}

// round 16
// speedup vs baseline: 1.4264x; 1.0926x over previous
#include <cuda_runtime.h>
#include <cuda_bf16.h>
#include <cstdint>

#define NB   2
#define NC   256
#define NPIX 4096
#define CI   128
#define EPSV 1e-5f

typedef __nv_bfloat16 bf16;

__device__ bf16 g_Ehi [(size_t)NB * NPIX * NPIX];
__device__ bf16 g_EThi[(size_t)NB * NPIX * NPIX];
__device__ bf16 g_VQhi[(size_t)NB * CI * NPIX];
__device__ bf16 g_VQlo[(size_t)NB * CI * NPIX];
__device__ bf16 g_VShi[(size_t)NB * CI * NPIX];
__device__ bf16 g_VSlo[(size_t)NB * CI * NPIX];
__device__ bf16 g_KThi[(size_t)NB * NPIX * CI];
__device__ bf16 g_KTlo[(size_t)NB * NPIX * CI];
__device__ bf16 g_QThi[(size_t)NB * NPIX * CI];
__device__ bf16 g_QTlo[(size_t)NB * NPIX * CI];
__device__ float g_ST [(size_t)NB * CI * NPIX];
__device__ float g_TQ [(size_t)NB * CI * NPIX];
__device__ float g_rowsum[NB * NPIX];
__device__ float g_colsum[NB * NPIX];
__device__ bf16 g_EQhi[(size_t)NB * CI * NPIX];
__device__ bf16 g_EQlo[(size_t)NB * CI * NPIX];
__device__ bf16 g_EShi[(size_t)NB * CI * NPIX];
__device__ bf16 g_ESlo[(size_t)NB * CI * NPIX];
__device__ bf16 g_W3hi[9 * 128 * 256];
__device__ bf16 g_W3lo[9 * 128 * 256];

// ---------------- helpers ----------------
__device__ __forceinline__ uint32_t smem_u32(const void* p) {
    uint32_t a;
    asm("{ .reg .u64 t; cvta.to.shared.u64 t, %1; cvt.u32.u64 %0, t; }" : "=r"(a) : "l"(p));
    return a;
}
__device__ __forceinline__ void cp16(uint32_t dst, const void* src) {
    asm volatile("cp.async.cg.shared.global [%0], [%1], 16;" :: "r"(dst), "l"(src));
}
#define CP_COMMIT() asm volatile("cp.async.commit_group;" ::: "memory")
#define CP_WAIT(n)  asm volatile("cp.async.wait_group %0;" :: "n"(n) : "memory")

__device__ __forceinline__ void mma_bf16(float* c, const uint32_t* a, uint32_t b0, uint32_t b1) {
    asm("mma.sync.aligned.m16n8k16.row.col.f32.bf16.bf16.f32 "
        "{%0,%1,%2,%3},{%4,%5,%6,%7},{%8,%9},{%0,%1,%2,%3};"
        : "+f"(c[0]), "+f"(c[1]), "+f"(c[2]), "+f"(c[3])
        : "r"(a[0]), "r"(a[1]), "r"(a[2]), "r"(a[3]), "r"(b0), "r"(b1));
}
__device__ __forceinline__ void ldsm_x4(uint32_t* r, uint32_t addr) {
    asm volatile("ldmatrix.sync.aligned.m8n8.x4.shared.b16 {%0,%1,%2,%3}, [%4];"
        : "=r"(r[0]), "=r"(r[1]), "=r"(r[2]), "=r"(r[3]) : "r"(addr));
}
__device__ __forceinline__ void ldsm_x2(uint32_t& r0, uint32_t& r1, uint32_t addr) {
    asm volatile("ldmatrix.sync.aligned.m8n8.x2.shared.b16 {%0,%1}, [%2];"
        : "=r"(r0), "=r"(r1) : "r"(addr));
}
__device__ __forceinline__ uint32_t pack2(float x, float y) {
    bf16 hx = __float2bfloat16(x), hy = __float2bfloat16(y);
    return (uint32_t)__bfloat16_as_ushort(hx) | ((uint32_t)__bfloat16_as_ushort(hy) << 16);
}
__device__ __forceinline__ uint32_t pack2lo(float x, float y) {
    bf16 hx = __float2bfloat16(x), hy = __float2bfloat16(y);
    bf16 lx = __float2bfloat16(x - __bfloat162float(hx));
    bf16 ly = __float2bfloat16(y - __bfloat162float(hy));
    return (uint32_t)__bfloat16_as_ushort(lx) | ((uint32_t)__bfloat16_as_ushort(ly) << 16);
}
__device__ __forceinline__ bf16 hi_of(float x) { return __float2bfloat16(x); }
__device__ __forceinline__ bf16 lo_of(float x, bf16 h) {
    return __float2bfloat16(x - __bfloat162float(h));
}

// bf16x3 step: A hi/lo, B hi/lo (128-row A-tile, 8 nt)
template<int ST>
__device__ __forceinline__ void mma_step_l(uint32_t Ahi, uint32_t Alo,
                                           uint32_t Bhi, uint32_t Blo,
                                           int kb, int wr, int wc, int lane, float c[2][8][4])
{
    const int arow = lane & 15, asel = lane >> 4;
    const int brow = lane & 7,  bsel = (lane >> 3) & 1;
    uint32_t ah[2][4], al[2][4];
    #pragma unroll
    for (int mt = 0; mt < 2; mt++) {
        uint32_t aoff = ((wr + mt * 16 + arow) * ST + kb + asel * 4) * 4;
        ldsm_x4(ah[mt], Ahi + aoff);
        ldsm_x4(al[mt], Alo + aoff);
    }
    #pragma unroll
    for (int nt = 0; nt < 8; nt++) {
        uint32_t boff = ((wc + nt * 8 + brow) * ST + kb + bsel * 4) * 4;
        uint32_t bh0, bh1, bl0, bl1;
        ldsm_x2(bh0, bh1, Bhi + boff);
        ldsm_x2(bl0, bl1, Blo + boff);
        #pragma unroll
        for (int mt = 0; mt < 2; mt++) {
            mma_bf16(c[mt][nt], ah[mt], bh0, bh1);
            mma_bf16(c[mt][nt], al[mt], bh0, bh1);
            mma_bf16(c[mt][nt], ah[mt], bl0, bl1);
        }
    }
}

__global__ void zero_sums() {
    int i = blockIdx.x * 256 + threadIdx.x;
    if (i < NB * NPIX) { g_rowsum[i] = 0.f; g_colsum[i] = 0.f; }
}

__global__ void w3prep(const float* __restrict__ Wc) {
    int i = blockIdx.x * 256 + threadIdx.x;
    if (i >= 9 * 128 * 256) return;
    int tap = i >> 15, oc = (i >> 8) & 127, ic = i & 255;
    float v = Wc[(size_t)oc * 2304 + ic * 9 + tap];
    bf16 h = __float2bfloat16(v);
    g_W3hi[i] = h;
    g_W3lo[i] = __float2bfloat16(v - __bfloat162float(h));
}

// ============ gemmA (unchanged from R14 best) ============
#define GA_SMEM 73728
__global__ __launch_bounds__(256, 2) void gemmA_mma()
{
    extern __shared__ char sm[];
    const int t = threadIdx.x, lane = t & 31, wid = t >> 5;
    const int g = lane >> 2, tg = lane & 3;
    const int b = blockIdx.z, n0 = blockIdx.x * 128, m0 = blockIdx.y * 128;
    const int wr = (wid & 3) * 32, wc = (wid >> 2) * 64;
    const bf16* A_hi = g_KThi + (size_t)b * NPIX * CI + (size_t)n0 * CI;
    const bf16* A_lo = g_KTlo + (size_t)b * NPIX * CI + (size_t)n0 * CI;
    const bf16* B_hi = g_QThi + (size_t)b * NPIX * CI + (size_t)m0 * CI;
    const bf16* B_lo = g_QTlo + (size_t)b * NPIX * CI + (size_t)m0 * CI;
    uint32_t sb = smem_u32(sm);

    float c[2][8][4] = {};
    #pragma unroll
    for (int kc = 0; kc < 2; kc++) {
        #pragma unroll
        for (int p = 0; p < 4; p++) {
            int i = t + p * 256;
            int row = i >> 3, seg = i & 7;
            size_t go = (size_t)row * CI + kc * 64 + seg * 8;
            uint32_t so = row * 144 + seg * 16;
            cp16(sb + so,         A_hi + go);
            cp16(sb + 18432 + so, A_lo + go);
            cp16(sb + 36864 + so, B_hi + go);
            cp16(sb + 55296 + so, B_lo + go);
        }
        CP_COMMIT();
        CP_WAIT(0);
        __syncthreads();
        #pragma unroll
        for (int kb = 0; kb < 32; kb += 8)
            mma_step_l<36>(sb, sb + 18432, sb + 36864, sb + 55296, kb, wr, wc, lane, c);
        __syncthreads();
    }

    #pragma unroll
    for (int mt = 0; mt < 2; mt++)
        #pragma unroll
        for (int nt = 0; nt < 8; nt++)
            #pragma unroll
            for (int i = 0; i < 4; i++)
                c[mt][nt][i] = __expf(c[mt][nt][i]);

    #pragma unroll
    for (int mt = 0; mt < 2; mt++)
        #pragma unroll
        for (int h = 0; h < 2; h++) {
            float v = 0.f;
            #pragma unroll
            for (int nt = 0; nt < 8; nt++) v += c[mt][nt][2 * h] + c[mt][nt][2 * h + 1];
            v += __shfl_xor_sync(0xffffffffu, v, 1);
            v += __shfl_xor_sync(0xffffffffu, v, 2);
            if (tg == 0) atomicAdd(g_rowsum + b * NPIX + n0 + wr + mt * 16 + g + 8 * h, v);
        }
    #pragma unroll
    for (int nt = 0; nt < 8; nt++)
        #pragma unroll
        for (int jj = 0; jj < 2; jj++) {
            float v = c[0][nt][jj] + c[0][nt][2 + jj] + c[1][nt][jj] + c[1][nt][2 + jj];
            v += __shfl_xor_sync(0xffffffffu, v, 4);
            v += __shfl_xor_sync(0xffffffffu, v, 8);
            v += __shfl_xor_sync(0xffffffffu, v, 16);
            if (g == 0) atomicAdd(g_colsum + b * NPIX + m0 + wc + nt * 8 + tg * 2 + jj, v);
        }

    float* Tb = (float*)sm;
    #pragma unroll
    for (int mt = 0; mt < 2; mt++)
        #pragma unroll
        for (int nt = 0; nt < 8; nt++)
            #pragma unroll
            for (int i = 0; i < 4; i++) {
                int row = wr + mt * 16 + g + (i >> 1) * 8;
                int col = wc + nt * 8 + tg * 2 + (i & 1);
                Tb[row * 128 + ((col + row) & 127)] = c[mt][nt][i];
            }
    __syncthreads();

    bf16* Ehi  = g_Ehi  + (size_t)b * NPIX * NPIX;
    bf16* EThi = g_EThi + (size_t)b * NPIX * NPIX;

    for (int i = t; i < 8192; i += 256) {
        int r = i >> 6, c2 = (i & 63) * 2;
        float v0 = Tb[r * 128 + ((c2 + r) & 127)];
        float v1 = Tb[r * 128 + ((c2 + 1 + r) & 127)];
        *(uint32_t*)(Ehi + (size_t)(n0 + r) * NPIX + m0 + c2) = pack2(v0, v1);
    }
    for (int i = t; i < 8192; i += 256) {
        int cl = i >> 6, r2 = (i & 63) * 2;
        float v0 = Tb[(r2) * 128 + ((cl + r2) & 127)];
        float v1 = Tb[(r2 + 1) * 128 + ((cl + r2 + 1) & 127)];
        *(uint32_t*)(EThi + (size_t)(m0 + cl) * NPIX + n0 + r2) = pack2(v0, v1);
    }
}

// ============ pv: M=64 tiles, 256 blocks, single-plane E and V, 1-term MMA ============
// stage: Ahi@0 (64 x 144 = 9216), Bhi@9216 (128 x 144 = 18432) -> 27648/stage; 2 stages; RS@55296
#define PV_SMEM 55552
__global__ __launch_bounds__(256, 2) void pv_mma(const float* __restrict__ scale_p,
                                                 float* __restrict__ outEq,
                                                 float* __restrict__ outEs)
{
    extern __shared__ char sm[];
    const int t = threadIdx.x, lane = t & 31, wid = t >> 5;
    const int g = lane >> 2, tg = lane & 3;
    const int r0 = blockIdx.x * 64, b = blockIdx.y, mode = blockIdx.z;
    const int wr = (wid & 1) * 32, wc = (wid >> 1) * 32;
    const bf16* A_hi = (mode ? g_EThi : g_Ehi) + (size_t)b * NPIX * NPIX + (size_t)r0 * NPIX;
    const bf16* B_hi = (mode ? g_VQhi : g_VShi) + (size_t)b * CI * NPIX;
    const float* sums = (mode ? g_colsum : g_rowsum) + (size_t)b * NPIX + r0;
    const float* T = (mode ? g_TQ : g_ST) + (size_t)b * CI * NPIX;
    float* outp = (mode ? outEq : outEs) + (size_t)b * CI * NPIX;
    bf16* Fh = (mode ? g_EQhi : g_EShi) + (size_t)b * CI * NPIX;
    bf16* Fl = (mode ? g_EQlo : g_ESlo) + (size_t)b * CI * NPIX;
    uint32_t sb = smem_u32(sm);
    float* RS = (float*)(sm + 55296);
    if (t < 64) RS[t] = scale_p[0] / sums[t];

    // preload stage 0 (K chunk 0, 64 wide): A = 512 cp16, B = 1024 cp16
    #pragma unroll
    for (int p = 0; p < 2; p++) {
        int i = t + p * 256;               // 0..511
        int row = i >> 3, seg = i & 7;     // 8 x 16B = 128B per row
        cp16(sb + row * 144 + seg * 16, A_hi + (size_t)row * NPIX + seg * 8);
    }
    #pragma unroll
    for (int p = 0; p < 4; p++) {
        int i = t + p * 256;               // 0..1023
        int row = i >> 3, seg = i & 7;
        cp16(sb + 9216 + row * 144 + seg * 16, B_hi + (size_t)row * NPIX + seg * 8);
    }
    CP_COMMIT();

    float c[2][4][4] = {};
    for (int kc = 0; kc < 64; kc++) {
        const int st = kc & 1;
        if (kc + 1 < 64) {
            const int st2 = (kc + 1) & 1;
            #pragma unroll
            for (int p = 0; p < 2; p++) {
                int i = t + p * 256;
                int row = i >> 3, seg = i & 7;
                cp16(sb + st2 * 27648 + row * 144 + seg * 16,
                     A_hi + (size_t)row * NPIX + (kc + 1) * 64 + seg * 8);
            }
            #pragma unroll
            for (int p = 0; p < 4; p++) {
                int i = t + p * 256;
                int row = i >> 3, seg = i & 7;
                cp16(sb + st2 * 27648 + 9216 + row * 144 + seg * 16,
                     B_hi + (size_t)row * NPIX + (kc + 1) * 64 + seg * 8);
            }
            CP_COMMIT();
            CP_WAIT(1);
        } else {
            CP_WAIT(0);
        }
        __syncthreads();
        uint32_t base = sb + st * 27648;
        const int arow = lane & 15, asel = lane >> 4;
        const int brow = lane & 7,  bsel = (lane >> 3) & 1;
        #pragma unroll
        for (int kb = 0; kb < 32; kb += 8) {
            uint32_t ah[2][4];
            #pragma unroll
            for (int mt = 0; mt < 2; mt++) {
                uint32_t aoff = ((wr + mt * 16 + arow) * 36 + kb + asel * 4) * 4;
                ldsm_x4(ah[mt], base + aoff);
            }
            #pragma unroll
            for (int nt = 0; nt < 4; nt++) {
                uint32_t boff = 9216 + ((wc + nt * 8 + brow) * 36 + kb + bsel * 4) * 4;
                uint32_t bh0, bh1;
                ldsm_x2(bh0, bh1, base + boff);
                #pragma unroll
                for (int mt = 0; mt < 2; mt++)
                    mma_bf16(c[mt][nt], ah[mt], bh0, bh1);
            }
        }
        __syncthreads();
    }

    float* Tb = (float*)sm;    // rotated [64][128]
    #pragma unroll
    for (int mt = 0; mt < 2; mt++)
        #pragma unroll
        for (int nt = 0; nt < 4; nt++)
            #pragma unroll
            for (int i = 0; i < 4; i++) {
                int row = wr + mt * 16 + g + (i >> 1) * 8;
                int col = wc + nt * 8 + tg * 2 + (i & 1);
                Tb[row * 128 + ((col + row) & 127)] = c[mt][nt][i] * RS[row];
            }
    __syncthreads();
    for (int i = t; i < 8192; i += 256) {
        int cl = i >> 6, r = i & 63;
        float v = Tb[r * 128 + ((cl + r) & 127)];
        size_t gi = (size_t)cl * NPIX + r0 + r;
        float o = v + T[gi];
        outp[gi] = o;
        bf16 h = hi_of(o);
        Fh[gi] = h;
        Fl[gi] = lo_of(o, h);
    }
}

// ============ convs via bf16x3 mma (unchanged from R14) ============
#define CV_SMEM 55808
__global__ __launch_bounds__(256, 2) void convs_mma(
    const float* __restrict__ q, const float* __restrict__ s,
    const float* __restrict__ w_v,  const float* __restrict__ b_v,
    const float* __restrict__ w_k1, const float* __restrict__ b_k1,
    const float* __restrict__ w_q1, const float* __restrict__ b_q1,
    const float* __restrict__ w_k2, const float* __restrict__ b_k2,
    const float* __restrict__ w_q2, const float* __restrict__ b_q2,
    const float* __restrict__ w_ts, const float* __restrict__ b_ts,
    const float* __restrict__ gts,  const float* __restrict__ bets,
    const float* __restrict__ mts,  const float* __restrict__ vts,
    const float* __restrict__ w_tq, const float* __restrict__ b_tq,
    const float* __restrict__ gtq,  const float* __restrict__ betq,
    const float* __restrict__ mtq,  const float* __restrict__ vtq)
{
    extern __shared__ char sm[];
    const int j = blockIdx.z, b = blockIdx.y, n0 = blockIdx.x * 128;
    const int t = threadIdx.x, lane = t & 31, wid = t >> 5;
    const int g = lane >> 2, tg = lane & 3;
    const int wr = (wid & 1) * 32, wc = (wid >> 1) * 32;
    const float *X, *W, *Bi, *bg = nullptr, *bbp = nullptr, *bm = nullptr, *bv = nullptr;
    bf16 *dh = nullptr, *dl = nullptr;
    float* df = nullptr;
    int ocb = 0, co = 0; bool chanmaj = true, hasbn = false;
    switch (j) {
        case 0:  X = q; W = w_v;  Bi = b_v;  dh = g_VQhi; dl = g_VQlo; ocb = 0;  co = 0;  break;
        case 1:  X = q; W = w_v;  Bi = b_v;  dh = g_VQhi; dl = g_VQlo; ocb = 64; co = 64; break;
        case 2:  X = s; W = w_v;  Bi = b_v;  dh = g_VShi; dl = g_VSlo; ocb = 0;  co = 0;  break;
        case 3:  X = s; W = w_v;  Bi = b_v;  dh = g_VShi; dl = g_VSlo; ocb = 64; co = 64; break;
        case 4:  X = q; W = w_k1; Bi = b_k1; dh = g_KThi; dl = g_KTlo; chanmaj = false; co = 0;  break;
        case 5:  X = s; W = w_k2; Bi = b_k2; dh = g_KThi; dl = g_KTlo; chanmaj = false; co = 64; break;
        case 6:  X = q; W = w_q1; Bi = b_q1; dh = g_QThi; dl = g_QTlo; chanmaj = false; co = 0;  break;
        case 7:  X = s; W = w_q2; Bi = b_q2; dh = g_QThi; dl = g_QTlo; chanmaj = false; co = 64; break;
        case 8:  X = s; W = w_ts; Bi = b_ts; df = g_ST; ocb = 0;  co = 0;  hasbn = true; bg = gts; bbp = bets; bm = mts; bv = vts; break;
        case 9:  X = s; W = w_ts; Bi = b_ts; df = g_ST; ocb = 64; co = 64; hasbn = true; bg = gts; bbp = bets; bm = mts; bv = vts; break;
        case 10: X = q; W = w_tq; Bi = b_tq; df = g_TQ; ocb = 0;  co = 0;  hasbn = true; bg = gtq; bbp = betq; bm = mtq; bv = vtq; break;
        default: X = q; W = w_tq; Bi = b_tq; df = g_TQ; ocb = 64; co = 64; hasbn = true; bg = gtq; bbp = betq; bm = mtq; bv = vtq; break;
    }
    const float* Xb = X + (size_t)b * NC * NPIX;
    uint32_t sb = smem_u32(sm);
    float* SC  = (float*)(sm + 55296);
    float* OFF = (float*)(sm + 55552);
    if (t < 64) {
        int gi = ocb + t;
        float sc = 1.f, off = Bi[gi];
        if (hasbn) {
            float inv = bg[gi] * rsqrtf(bv[gi] + EPSV);
            sc = inv; off = (Bi[gi] - bm[gi]) * inv + bbp[gi];
        }
        SC[t] = sc; OFF[t] = off;
    }

    float c[2][4][4] = {};
    for (int kc = 0; kc < 4; kc++) {
        __syncthreads();
        #pragma unroll
        for (int p = 0; p < 4; p++) {
            int i = t + p * 256;
            int oc = i >> 4, seg = i & 15;
            float4 v = *(const float4*)(W + (size_t)(ocb + oc) * NC + kc * 64 + seg * 4);
            uint32_t off = oc * 144 + seg * 8;
            *(uint2*)(sm + off)        = make_uint2(pack2(v.x, v.y), pack2(v.z, v.w));
            *(uint2*)(sm + 9216 + off) = make_uint2(pack2lo(v.x, v.y), pack2lo(v.z, v.w));
        }
        #pragma unroll
        for (int p = 0; p < 8; p++) {
            int i = t + p * 256;
            int ic = i >> 5, px4 = (i & 31) * 4;
            float4 v = *(const float4*)(Xb + (size_t)(kc * 64 + ic) * NPIX + n0 + px4);
            float vs[4] = {v.x, v.y, v.z, v.w};
            #pragma unroll
            for (int jj = 0; jj < 4; jj++) {
                uint32_t off = (px4 + jj) * 144 + ic * 2;
                bf16 h = hi_of(vs[jj]);
                *(bf16*)(sm + 18432 + off) = h;
                *(bf16*)(sm + 36864 + off) = lo_of(vs[jj], h);
            }
        }
        __syncthreads();
        const int arow = lane & 15, asel = lane >> 4;
        const int brow = lane & 7,  bsel = (lane >> 3) & 1;
        #pragma unroll
        for (int kb = 0; kb < 32; kb += 8) {
            uint32_t ah[2][4], al[2][4];
            #pragma unroll
            for (int mt = 0; mt < 2; mt++) {
                uint32_t aoff = (wr + mt * 16 + arow) * 144 + (kb + asel * 4) * 4;
                ldsm_x4(ah[mt], sb + aoff);
                ldsm_x4(al[mt], sb + 9216 + aoff);
            }
            #pragma unroll
            for (int nt = 0; nt < 4; nt++) {
                uint32_t boff = (wc + nt * 8 + brow) * 144 + (kb + bsel * 4) * 4;
                uint32_t bh0, bh1, bl0, bl1;
                ldsm_x2(bh0, bh1, sb + 18432 + boff);
                ldsm_x2(bl0, bl1, sb + 36864 + boff);
                #pragma unroll
                for (int mt = 0; mt < 2; mt++) {
                    mma_bf16(c[mt][nt], ah[mt], bh0, bh1);
                    mma_bf16(c[mt][nt], al[mt], bh0, bh1);
                    mma_bf16(c[mt][nt], ah[mt], bl0, bl1);
                }
            }
        }
    }
    __syncthreads();

    float* Tb = (float*)sm;
    #pragma unroll
    for (int mt = 0; mt < 2; mt++)
        #pragma unroll
        for (int nt = 0; nt < 4; nt++)
            #pragma unroll
            for (int i = 0; i < 4; i++) {
                int row = wr + mt * 16 + g + (i >> 1) * 8;
                int col = wc + nt * 8 + tg * 2 + (i & 1);
                Tb[row * 128 + ((col + row) & 127)] = c[mt][nt][i] * SC[row] + OFF[row];
            }
    __syncthreads();

    if (df) {
        float* dst = df + ((size_t)b * CI + co) * NPIX + n0;
        for (int i = t; i < 8192; i += 256) {
            int oc = i >> 7, px = i & 127;
            dst[(size_t)oc * NPIX + px] = Tb[oc * 128 + ((px + oc) & 127)];
        }
    } else if (chanmaj) {
        bf16* dsth = dh + ((size_t)b * CI + co) * NPIX + n0;
        bf16* dstl = dl + ((size_t)b * CI + co) * NPIX + n0;
        for (int i = t; i < 4096; i += 256) {
            int oc = i >> 6, px2 = (i & 63) * 2;
            float v0 = Tb[oc * 128 + ((px2 + oc) & 127)];
            float v1 = Tb[oc * 128 + ((px2 + 1 + oc) & 127)];
            *(uint32_t*)(dsth + (size_t)oc * NPIX + px2) = pack2(v0, v1);
            *(uint32_t*)(dstl + (size_t)oc * NPIX + px2) = pack2lo(v0, v1);
        }
    } else {
        bf16* dsth = dh + ((size_t)b * NPIX + n0) * CI + co;
        bf16* dstl = dl + ((size_t)b * NPIX + n0) * CI + co;
        for (int i = t; i < 4096; i += 256) {
            int px = i >> 5, oc2 = (i & 31) * 2;
            float v0 = Tb[oc2 * 128 + ((px + oc2) & 127)];
            float v1 = Tb[(oc2 + 1) * 128 + ((px + oc2 + 1) & 127)];
            *(uint32_t*)(dsth + (size_t)px * CI + oc2) = pack2(v0, v1);
            *(uint32_t*)(dstl + (size_t)px * CI + oc2) = pack2lo(v0, v1);
        }
    }
}

// ---------------- conv3x3 via bf16x3 mma + ldmatrix (unchanged) ----------------
#define C3_SMEM 52160
__global__ __launch_bounds__(256) void conv3x3_mma(
    const float* __restrict__ bng, const float* __restrict__ bnb,
    const float* __restrict__ bnm, const float* __restrict__ bnv,
    float* __restrict__ outp_all)
{
    extern __shared__ char sm[];
    const int t = threadIdx.x, lane = t & 31, wid = t >> 5;
    const int g = lane >> 2, tg = lane & 3;
    const int y = blockIdx.x, b = blockIdx.y;
    const int wr = (wid & 3) * 32, wc = (wid >> 2) * 32;
    const bf16* EQh = g_EQhi + (size_t)b * CI * NPIX;
    const bf16* EQl = g_EQlo + (size_t)b * CI * NPIX;
    const bf16* ESh = g_EShi + (size_t)b * CI * NPIX;
    const bf16* ESl = g_ESlo + (size_t)b * CI * NPIX;
    float* outp = outp_all + (size_t)b * CI * NPIX;
    bf16* XH = (bf16*)(sm);
    bf16* XL = (bf16*)(sm + 15840);
    bf16* WHp = (bf16*)(sm + 31680);
    bf16* WLp = (bf16*)(sm + 41920);
    uint32_t sb = smem_u32(sm);
    const uint32_t aXH = sb, aXL = sb + 15840, aWH = sb + 31680, aWL = sb + 41920;

    float c[2][4][4] = {};
    for (int icc = 0; icc < 8; icc++) {
        for (int i = t; i < 32 * 198; i += 256) {
            int icl = i / 198, np = i - icl * 198;
            int r = np / 66, px = np - r * 66;
            int icg = icc * 32 + icl;
            int rg = y + r - 1, x = px - 1;
            bf16 vh = __ushort_as_bfloat16(0), vl = __ushort_as_bfloat16(0);
            if (rg >= 0 && rg < 64 && x >= 0 && x < 64) {
                size_t gi = (size_t)(icg & 127) * NPIX + rg * 64 + x;
                if (icg < 128) { vh = EQh[gi]; vl = EQl[gi]; }
                else           { vh = ESh[gi]; vl = ESl[gi]; }
            }
            XH[np * 40 + icl] = vh;
            XL[np * 40 + icl] = vl;
        }
        __syncthreads();
        for (int tap = 0; tap < 9; tap++) {
            const int dy = tap / 3, dx = tap - dy * 3;
            for (int i = t; i < 4096; i += 256) {
                int oc = i >> 5, icl = i & 31;
                size_t wi = (size_t)tap * 32768 + oc * 256 + icc * 32 + icl;
                WHp[oc * 40 + icl] = g_W3hi[wi];
                WLp[oc * 40 + icl] = g_W3lo[wi];
            }
            __syncthreads();
            const int arow = lane & 15, asel = lane >> 4;
            const int brow = lane & 7,  bsel = (lane >> 3) & 1;
            #pragma unroll
            for (int kb = 0; kb < 16; kb += 8) {
                uint32_t ah[2][4], al[2][4];
                #pragma unroll
                for (int mt = 0; mt < 2; mt++) {
                    uint32_t aoff = ((wr + mt * 16 + arow) * 20 + kb + asel * 4) * 4;
                    ldsm_x4(ah[mt], aWH + aoff);
                    ldsm_x4(al[mt], aWL + aoff);
                }
                #pragma unroll
                for (int nt = 0; nt < 4; nt++) {
                    uint32_t boff = ((dy * 66 + wc + nt * 8 + brow + dx) * 20 + kb + bsel * 4) * 4;
                    uint32_t bh0, bh1, bl0, bl1;
                    ldsm_x2(bh0, bh1, aXH + boff);
                    ldsm_x2(bl0, bl1, aXL + boff);
                    #pragma unroll
                    for (int mt = 0; mt < 2; mt++) {
                        mma_bf16(c[mt][nt], ah[mt], bh0, bh1);
                        mma_bf16(c[mt][nt], al[mt], bh0, bh1);
                        mma_bf16(c[mt][nt], ah[mt], bl0, bl1);
                    }
                }
            }
            __syncthreads();
        }
    }

    float* Tb = (float*)sm;
    #pragma unroll
    for (int mt = 0; mt < 2; mt++)
        #pragma unroll
        for (int nt = 0; nt < 4; nt++)
            #pragma unroll
            for (int i = 0; i < 4; i++) {
                int row = wr + mt * 16 + g + (i >> 1) * 8;
                int col = wc + nt * 8 + tg * 2 + (i & 1);
                Tb[row * 68 + col] = c[mt][nt][i];
            }
    __syncthreads();
    for (int i = t; i < 8192; i += 256) {
        int oc = i >> 6, n = i & 63;
        float inv = bng[oc] * rsqrtf(bnv[oc] + EPSV);
        float off = bnb[oc] - bnm[oc] * inv;
        outp[(size_t)oc * NPIX + y * 64 + n] = fmaxf(Tb[oc * 68 + n] * inv + off, 0.f);
    }
}

// ---------------- launch ----------------
extern "C" void kernel_launch(void* const* d_in, const int* in_sizes, int n_in,
                              void* d_out, int out_size)
{
    (void)in_sizes; (void)n_in; (void)out_size;
    const float* q     = (const float*)d_in[0];
    const float* s     = (const float*)d_in[1];
    const float* scale = (const float*)d_in[2];
    const float* w_v   = (const float*)d_in[3];  const float* b_v  = (const float*)d_in[4];
    const float* w_k1  = (const float*)d_in[5];  const float* b_k1 = (const float*)d_in[6];
    const float* w_q1  = (const float*)d_in[7];  const float* b_q1 = (const float*)d_in[8];
    const float* w_k2  = (const float*)d_in[9];  const float* b_k2 = (const float*)d_in[10];
    const float* w_q2  = (const float*)d_in[11]; const float* b_q2 = (const float*)d_in[12];
    const float* w_ts  = (const float*)d_in[13]; const float* b_ts = (const float*)d_in[14];
    const float* gts   = (const float*)d_in[15]; const float* bets = (const float*)d_in[16];
    const float* mts   = (const float*)d_in[17]; const float* vts  = (const float*)d_in[18];
    const float* w_tq  = (const float*)d_in[19]; const float* b_tq = (const float*)d_in[20];
    const float* gtq   = (const float*)d_in[21]; const float* betq = (const float*)d_in[22];
    const float* mtq   = (const float*)d_in[23]; const float* vtq  = (const float*)d_in[24];
    const float* w_cat = (const float*)d_in[25];
    const float* gcat  = (const float*)d_in[26]; const float* becat= (const float*)d_in[27];
    const float* mcat  = (const float*)d_in[28]; const float* vcat = (const float*)d_in[29];

    float* out  = (float*)d_out;
    float* cpam = out;
    float* Eq   = out + (size_t)NB * CI * NPIX;
    float* Es   = out + 2 * (size_t)NB * CI * NPIX;

    cudaFuncSetAttribute(gemmA_mma,   cudaFuncAttributeMaxDynamicSharedMemorySize, GA_SMEM);
    cudaFuncSetAttribute(pv_mma,      cudaFuncAttributeMaxDynamicSharedMemorySize, PV_SMEM);
    cudaFuncSetAttribute(convs_mma,   cudaFuncAttributeMaxDynamicSharedMemorySize, CV_SMEM);
    cudaFuncSetAttribute(conv3x3_mma, cudaFuncAttributeMaxDynamicSharedMemorySize, C3_SMEM);

    zero_sums<<<(NB * NPIX + 255) / 256, 256>>>();
    w3prep<<<(9 * 128 * 256 + 255) / 256, 256>>>(w_cat);
    convs_mma<<<dim3(32, NB, 12), 256, CV_SMEM>>>(q, s, w_v, b_v, w_k1, b_k1, w_q1, b_q1,
                                                  w_k2, b_k2, w_q2, b_q2, w_ts, b_ts,
                                                  gts, bets, mts, vts, w_tq, b_tq,
                                                  gtq, betq, mtq, vtq);
    gemmA_mma<<<dim3(32, 32, NB), 256, GA_SMEM>>>();
    pv_mma<<<dim3(64, NB, 2), 256, PV_SMEM>>>(scale, Eq, Es);
    conv3x3_mma<<<dim3(64, NB), 256, C3_SMEM>>>(gcat, becat, mcat, vcat, cpam);
}

// round 17
// speedup vs baseline: 1.6169x; 1.1335x over previous
#include <cuda_runtime.h>
#include <cuda_bf16.h>
#include <cstdint>

#define NB   2
#define NC   256
#define NPIX 4096
#define CI   128
#define EPSV 1e-5f

typedef __nv_bfloat16 bf16;

__device__ bf16 g_Ehi [(size_t)NB * NPIX * NPIX];
__device__ bf16 g_EThi[(size_t)NB * NPIX * NPIX];
__device__ bf16 g_VQhi[(size_t)NB * CI * NPIX];
__device__ bf16 g_VQlo[(size_t)NB * CI * NPIX];
__device__ bf16 g_VShi[(size_t)NB * CI * NPIX];
__device__ bf16 g_VSlo[(size_t)NB * CI * NPIX];
__device__ bf16 g_KThi[(size_t)NB * NPIX * CI];
__device__ bf16 g_KTlo[(size_t)NB * NPIX * CI];
__device__ bf16 g_QThi[(size_t)NB * NPIX * CI];
__device__ bf16 g_QTlo[(size_t)NB * NPIX * CI];
__device__ float g_ST [(size_t)NB * CI * NPIX];
__device__ float g_TQ [(size_t)NB * CI * NPIX];
__device__ float g_rowsum[NB * NPIX];
__device__ float g_colsum[NB * NPIX];
__device__ bf16 g_EQhi[(size_t)NB * CI * NPIX];
__device__ bf16 g_EQlo[(size_t)NB * CI * NPIX];
__device__ bf16 g_EShi[(size_t)NB * CI * NPIX];
__device__ bf16 g_ESlo[(size_t)NB * CI * NPIX];
__device__ bf16 g_W3hi[9 * 128 * 256];
__device__ bf16 g_W3lo[9 * 128 * 256];

// ---------------- helpers ----------------
__device__ __forceinline__ uint32_t smem_u32(const void* p) {
    uint32_t a;
    asm("{ .reg .u64 t; cvta.to.shared.u64 t, %1; cvt.u32.u64 %0, t; }" : "=r"(a) : "l"(p));
    return a;
}
__device__ __forceinline__ void cp16(uint32_t dst, const void* src) {
    asm volatile("cp.async.cg.shared.global [%0], [%1], 16;" :: "r"(dst), "l"(src));
}
#define CP_COMMIT() asm volatile("cp.async.commit_group;" ::: "memory")
#define CP_WAIT(n)  asm volatile("cp.async.wait_group %0;" :: "n"(n) : "memory")

__device__ __forceinline__ void mma_bf16(float* c, const uint32_t* a, uint32_t b0, uint32_t b1) {
    asm("mma.sync.aligned.m16n8k16.row.col.f32.bf16.bf16.f32 "
        "{%0,%1,%2,%3},{%4,%5,%6,%7},{%8,%9},{%0,%1,%2,%3};"
        : "+f"(c[0]), "+f"(c[1]), "+f"(c[2]), "+f"(c[3])
        : "r"(a[0]), "r"(a[1]), "r"(a[2]), "r"(a[3]), "r"(b0), "r"(b1));
}
__device__ __forceinline__ void ldsm_x4(uint32_t* r, uint32_t addr) {
    asm volatile("ldmatrix.sync.aligned.m8n8.x4.shared.b16 {%0,%1,%2,%3}, [%4];"
        : "=r"(r[0]), "=r"(r[1]), "=r"(r[2]), "=r"(r[3]) : "r"(addr));
}
__device__ __forceinline__ void ldsm_x2(uint32_t& r0, uint32_t& r1, uint32_t addr) {
    asm volatile("ldmatrix.sync.aligned.m8n8.x2.shared.b16 {%0,%1}, [%2];"
        : "=r"(r0), "=r"(r1) : "r"(addr));
}
__device__ __forceinline__ uint32_t pack2(float x, float y) {
    bf16 hx = __float2bfloat16(x), hy = __float2bfloat16(y);
    return (uint32_t)__bfloat16_as_ushort(hx) | ((uint32_t)__bfloat16_as_ushort(hy) << 16);
}
__device__ __forceinline__ uint32_t pack2lo(float x, float y) {
    bf16 hx = __float2bfloat16(x), hy = __float2bfloat16(y);
    bf16 lx = __float2bfloat16(x - __bfloat162float(hx));
    bf16 ly = __float2bfloat16(y - __bfloat162float(hy));
    return (uint32_t)__bfloat16_as_ushort(lx) | ((uint32_t)__bfloat16_as_ushort(ly) << 16);
}
__device__ __forceinline__ bf16 hi_of(float x) { return __float2bfloat16(x); }
__device__ __forceinline__ bf16 lo_of(float x, bf16 h) {
    return __float2bfloat16(x - __bfloat162float(h));
}

// bf16x3 step with x4 B-fragment loads: A hi/lo, B hi/lo, 8 nt
template<int ST>
__device__ __forceinline__ void mma_step_l3(uint32_t Ahi, uint32_t Alo,
                                            uint32_t Bhi, uint32_t Blo,
                                            int kb, int wr, int wc, int lane, float c[2][8][4])
{
    const int arow = lane & 15, asel = lane >> 4;
    const int brow = lane & 7,  bm = lane >> 3;   // 0..3
    uint32_t ah[2][4], al[2][4];
    #pragma unroll
    for (int mt = 0; mt < 2; mt++) {
        uint32_t aoff = ((wr + mt * 16 + arow) * ST + kb + asel * 4) * 4;
        ldsm_x4(ah[mt], Ahi + aoff);
        ldsm_x4(al[mt], Alo + aoff);
    }
    #pragma unroll
    for (int np = 0; np < 4; np++) {
        uint32_t boff = ((wc + (np * 2 + (bm >> 1)) * 8 + brow) * ST + kb + (bm & 1) * 4) * 4;
        uint32_t bh[4], bl[4];
        ldsm_x4(bh, Bhi + boff);
        ldsm_x4(bl, Blo + boff);
        #pragma unroll
        for (int mt = 0; mt < 2; mt++) {
            mma_bf16(c[mt][2 * np],     ah[mt], bh[0], bh[1]);
            mma_bf16(c[mt][2 * np],     al[mt], bh[0], bh[1]);
            mma_bf16(c[mt][2 * np],     ah[mt], bl[0], bl[1]);
            mma_bf16(c[mt][2 * np + 1], ah[mt], bh[2], bh[3]);
            mma_bf16(c[mt][2 * np + 1], al[mt], bh[2], bh[3]);
            mma_bf16(c[mt][2 * np + 1], ah[mt], bl[2], bl[3]);
        }
    }
}

__global__ void zero_sums() {
    int i = blockIdx.x * 256 + threadIdx.x;
    if (i < NB * NPIX) { g_rowsum[i] = 0.f; g_colsum[i] = 0.f; }
}

__global__ void w3prep(const float* __restrict__ Wc) {
    int i = blockIdx.x * 256 + threadIdx.x;
    if (i >= 9 * 128 * 256) return;
    int tap = i >> 15, oc = (i >> 8) & 127, ic = i & 255;
    float v = Wc[(size_t)oc * 2304 + ic * 9 + tap];
    bf16 h = __float2bfloat16(v);
    g_W3hi[i] = h;
    g_W3lo[i] = __float2bfloat16(v - __bfloat162float(h));
}

// ============ gemmA: x4 B-loads, direct E stores ============
#define GA_SMEM 73728
__global__ __launch_bounds__(256, 2) void gemmA_mma()
{
    extern __shared__ char sm[];
    const int t = threadIdx.x, lane = t & 31, wid = t >> 5;
    const int g = lane >> 2, tg = lane & 3;
    const int b = blockIdx.z, n0 = blockIdx.x * 128, m0 = blockIdx.y * 128;
    const int wr = (wid & 3) * 32, wc = (wid >> 2) * 64;
    const bf16* A_hi = g_KThi + (size_t)b * NPIX * CI + (size_t)n0 * CI;
    const bf16* A_lo = g_KTlo + (size_t)b * NPIX * CI + (size_t)n0 * CI;
    const bf16* B_hi = g_QThi + (size_t)b * NPIX * CI + (size_t)m0 * CI;
    const bf16* B_lo = g_QTlo + (size_t)b * NPIX * CI + (size_t)m0 * CI;
    uint32_t sb = smem_u32(sm);

    float c[2][8][4] = {};
    #pragma unroll
    for (int kc = 0; kc < 2; kc++) {
        #pragma unroll
        for (int p = 0; p < 4; p++) {
            int i = t + p * 256;
            int row = i >> 3, seg = i & 7;
            size_t go = (size_t)row * CI + kc * 64 + seg * 8;
            uint32_t so = row * 144 + seg * 16;
            cp16(sb + so,         A_hi + go);
            cp16(sb + 18432 + so, A_lo + go);
            cp16(sb + 36864 + so, B_hi + go);
            cp16(sb + 55296 + so, B_lo + go);
        }
        CP_COMMIT();
        CP_WAIT(0);
        __syncthreads();
        #pragma unroll
        for (int kb = 0; kb < 32; kb += 8)
            mma_step_l3<36>(sb, sb + 18432, sb + 36864, sb + 55296, kb, wr, wc, lane, c);
        __syncthreads();
    }

    #pragma unroll
    for (int mt = 0; mt < 2; mt++)
        #pragma unroll
        for (int nt = 0; nt < 8; nt++)
            #pragma unroll
            for (int i = 0; i < 4; i++)
                c[mt][nt][i] = __expf(c[mt][nt][i]);

    #pragma unroll
    for (int mt = 0; mt < 2; mt++)
        #pragma unroll
        for (int h = 0; h < 2; h++) {
            float v = 0.f;
            #pragma unroll
            for (int nt = 0; nt < 8; nt++) v += c[mt][nt][2 * h] + c[mt][nt][2 * h + 1];
            v += __shfl_xor_sync(0xffffffffu, v, 1);
            v += __shfl_xor_sync(0xffffffffu, v, 2);
            if (tg == 0) atomicAdd(g_rowsum + b * NPIX + n0 + wr + mt * 16 + g + 8 * h, v);
        }
    #pragma unroll
    for (int nt = 0; nt < 8; nt++)
        #pragma unroll
        for (int jj = 0; jj < 2; jj++) {
            float v = c[0][nt][jj] + c[0][nt][2 + jj] + c[1][nt][jj] + c[1][nt][2 + jj];
            v += __shfl_xor_sync(0xffffffffu, v, 4);
            v += __shfl_xor_sync(0xffffffffu, v, 8);
            v += __shfl_xor_sync(0xffffffffu, v, 16);
            if (g == 0) atomicAdd(g_colsum + b * NPIX + m0 + wc + nt * 8 + tg * 2 + jj, v);
        }

    // direct E stores from registers (adjacent col pairs)
    bf16* Ehi  = g_Ehi  + (size_t)b * NPIX * NPIX;
    bf16* EThi = g_EThi + (size_t)b * NPIX * NPIX;
    #pragma unroll
    for (int mt = 0; mt < 2; mt++)
        #pragma unroll
        for (int nt = 0; nt < 8; nt++) {
            int row = wr + mt * 16 + g;
            int col = wc + nt * 8 + tg * 2;
            *(uint32_t*)(Ehi + (size_t)(n0 + row) * NPIX + m0 + col) =
                pack2(c[mt][nt][0], c[mt][nt][1]);
            *(uint32_t*)(Ehi + (size_t)(n0 + row + 8) * NPIX + m0 + col) =
                pack2(c[mt][nt][2], c[mt][nt][3]);
        }

    // ET via rotated f32 staging
    float* Tb = (float*)sm;
    #pragma unroll
    for (int mt = 0; mt < 2; mt++)
        #pragma unroll
        for (int nt = 0; nt < 8; nt++)
            #pragma unroll
            for (int i = 0; i < 4; i++) {
                int row = wr + mt * 16 + g + (i >> 1) * 8;
                int col = wc + nt * 8 + tg * 2 + (i & 1);
                Tb[row * 128 + ((col + row) & 127)] = c[mt][nt][i];
            }
    __syncthreads();
    for (int i = t; i < 8192; i += 256) {
        int cl = i >> 6, r2 = (i & 63) * 2;
        float v0 = Tb[(r2) * 128 + ((cl + r2) & 127)];
        float v1 = Tb[(r2 + 1) * 128 + ((cl + r2 + 1) & 127)];
        *(uint32_t*)(EThi + (size_t)(m0 + cl) * NPIX + n0 + r2) = pack2(v0, v1);
    }
}

// ============ pv (unchanged from R16 best) ============
#define PV_SMEM 55552
__global__ __launch_bounds__(256, 2) void pv_mma(const float* __restrict__ scale_p,
                                                 float* __restrict__ outEq,
                                                 float* __restrict__ outEs)
{
    extern __shared__ char sm[];
    const int t = threadIdx.x, lane = t & 31, wid = t >> 5;
    const int g = lane >> 2, tg = lane & 3;
    const int r0 = blockIdx.x * 64, b = blockIdx.y, mode = blockIdx.z;
    const int wr = (wid & 1) * 32, wc = (wid >> 1) * 32;
    const bf16* A_hi = (mode ? g_EThi : g_Ehi) + (size_t)b * NPIX * NPIX + (size_t)r0 * NPIX;
    const bf16* B_hi = (mode ? g_VQhi : g_VShi) + (size_t)b * CI * NPIX;
    const float* sums = (mode ? g_colsum : g_rowsum) + (size_t)b * NPIX + r0;
    const float* T = (mode ? g_TQ : g_ST) + (size_t)b * CI * NPIX;
    float* outp = (mode ? outEq : outEs) + (size_t)b * CI * NPIX;
    bf16* Fh = (mode ? g_EQhi : g_EShi) + (size_t)b * CI * NPIX;
    bf16* Fl = (mode ? g_EQlo : g_ESlo) + (size_t)b * CI * NPIX;
    uint32_t sb = smem_u32(sm);
    float* RS = (float*)(sm + 55296);
    if (t < 64) RS[t] = scale_p[0] / sums[t];

    #pragma unroll
    for (int p = 0; p < 2; p++) {
        int i = t + p * 256;
        int row = i >> 3, seg = i & 7;
        cp16(sb + row * 144 + seg * 16, A_hi + (size_t)row * NPIX + seg * 8);
    }
    #pragma unroll
    for (int p = 0; p < 4; p++) {
        int i = t + p * 256;
        int row = i >> 3, seg = i & 7;
        cp16(sb + 9216 + row * 144 + seg * 16, B_hi + (size_t)row * NPIX + seg * 8);
    }
    CP_COMMIT();

    float c[2][4][4] = {};
    for (int kc = 0; kc < 64; kc++) {
        const int st = kc & 1;
        if (kc + 1 < 64) {
            const int st2 = (kc + 1) & 1;
            #pragma unroll
            for (int p = 0; p < 2; p++) {
                int i = t + p * 256;
                int row = i >> 3, seg = i & 7;
                cp16(sb + st2 * 27648 + row * 144 + seg * 16,
                     A_hi + (size_t)row * NPIX + (kc + 1) * 64 + seg * 8);
            }
            #pragma unroll
            for (int p = 0; p < 4; p++) {
                int i = t + p * 256;
                int row = i >> 3, seg = i & 7;
                cp16(sb + st2 * 27648 + 9216 + row * 144 + seg * 16,
                     B_hi + (size_t)row * NPIX + (kc + 1) * 64 + seg * 8);
            }
            CP_COMMIT();
            CP_WAIT(1);
        } else {
            CP_WAIT(0);
        }
        __syncthreads();
        uint32_t base = sb + st * 27648;
        const int arow = lane & 15, asel = lane >> 4;
        const int brow = lane & 7,  bsel = (lane >> 3) & 1;
        #pragma unroll
        for (int kb = 0; kb < 32; kb += 8) {
            uint32_t ah[2][4];
            #pragma unroll
            for (int mt = 0; mt < 2; mt++) {
                uint32_t aoff = ((wr + mt * 16 + arow) * 36 + kb + asel * 4) * 4;
                ldsm_x4(ah[mt], base + aoff);
            }
            #pragma unroll
            for (int nt = 0; nt < 4; nt++) {
                uint32_t boff = 9216 + ((wc + nt * 8 + brow) * 36 + kb + bsel * 4) * 4;
                uint32_t bh0, bh1;
                ldsm_x2(bh0, bh1, base + boff);
                #pragma unroll
                for (int mt = 0; mt < 2; mt++)
                    mma_bf16(c[mt][nt], ah[mt], bh0, bh1);
            }
        }
        __syncthreads();
    }

    float* Tb = (float*)sm;
    #pragma unroll
    for (int mt = 0; mt < 2; mt++)
        #pragma unroll
        for (int nt = 0; nt < 4; nt++)
            #pragma unroll
            for (int i = 0; i < 4; i++) {
                int row = wr + mt * 16 + g + (i >> 1) * 8;
                int col = wc + nt * 8 + tg * 2 + (i & 1);
                Tb[row * 128 + ((col + row) & 127)] = c[mt][nt][i] * RS[row];
            }
    __syncthreads();
    for (int i = t; i < 8192; i += 256) {
        int cl = i >> 6, r = i & 63;
        float v = Tb[r * 128 + ((cl + r) & 127)];
        size_t gi = (size_t)cl * NPIX + r0 + r;
        float o = v + T[gi];
        outp[gi] = o;
        bf16 h = hi_of(o);
        Fh[gi] = h;
        Fl[gi] = lo_of(o, h);
    }
}

// ============ convs (unchanged from R16) ============
#define CV_SMEM 55808
__global__ __launch_bounds__(256, 2) void convs_mma(
    const float* __restrict__ q, const float* __restrict__ s,
    const float* __restrict__ w_v,  const float* __restrict__ b_v,
    const float* __restrict__ w_k1, const float* __restrict__ b_k1,
    const float* __restrict__ w_q1, const float* __restrict__ b_q1,
    const float* __restrict__ w_k2, const float* __restrict__ b_k2,
    const float* __restrict__ w_q2, const float* __restrict__ b_q2,
    const float* __restrict__ w_ts, const float* __restrict__ b_ts,
    const float* __restrict__ gts,  const float* __restrict__ bets,
    const float* __restrict__ mts,  const float* __restrict__ vts,
    const float* __restrict__ w_tq, const float* __restrict__ b_tq,
    const float* __restrict__ gtq,  const float* __restrict__ betq,
    const float* __restrict__ mtq,  const float* __restrict__ vtq)
{
    extern __shared__ char sm[];
    const int j = blockIdx.z, b = blockIdx.y, n0 = blockIdx.x * 128;
    const int t = threadIdx.x, lane = t & 31, wid = t >> 5;
    const int g = lane >> 2, tg = lane & 3;
    const int wr = (wid & 1) * 32, wc = (wid >> 1) * 32;
    const float *X, *W, *Bi, *bg = nullptr, *bbp = nullptr, *bm = nullptr, *bv = nullptr;
    bf16 *dh = nullptr, *dl = nullptr;
    float* df = nullptr;
    int ocb = 0, co = 0; bool chanmaj = true, hasbn = false;
    switch (j) {
        case 0:  X = q; W = w_v;  Bi = b_v;  dh = g_VQhi; dl = g_VQlo; ocb = 0;  co = 0;  break;
        case 1:  X = q; W = w_v;  Bi = b_v;  dh = g_VQhi; dl = g_VQlo; ocb = 64; co = 64; break;
        case 2:  X = s; W = w_v;  Bi = b_v;  dh = g_VShi; dl = g_VSlo; ocb = 0;  co = 0;  break;
        case 3:  X = s; W = w_v;  Bi = b_v;  dh = g_VShi; dl = g_VSlo; ocb = 64; co = 64; break;
        case 4:  X = q; W = w_k1; Bi = b_k1; dh = g_KThi; dl = g_KTlo; chanmaj = false; co = 0;  break;
        case 5:  X = s; W = w_k2; Bi = b_k2; dh = g_KThi; dl = g_KTlo; chanmaj = false; co = 64; break;
        case 6:  X = q; W = w_q1; Bi = b_q1; dh = g_QThi; dl = g_QTlo; chanmaj = false; co = 0;  break;
        case 7:  X = s; W = w_q2; Bi = b_q2; dh = g_QThi; dl = g_QTlo; chanmaj = false; co = 64; break;
        case 8:  X = s; W = w_ts; Bi = b_ts; df = g_ST; ocb = 0;  co = 0;  hasbn = true; bg = gts; bbp = bets; bm = mts; bv = vts; break;
        case 9:  X = s; W = w_ts; Bi = b_ts; df = g_ST; ocb = 64; co = 64; hasbn = true; bg = gts; bbp = bets; bm = mts; bv = vts; break;
        case 10: X = q; W = w_tq; Bi = b_tq; df = g_TQ; ocb = 0;  co = 0;  hasbn = true; bg = gtq; bbp = betq; bm = mtq; bv = vtq; break;
        default: X = q; W = w_tq; Bi = b_tq; df = g_TQ; ocb = 64; co = 64; hasbn = true; bg = gtq; bbp = betq; bm = mtq; bv = vtq; break;
    }
    const float* Xb = X + (size_t)b * NC * NPIX;
    uint32_t sb = smem_u32(sm);
    float* SC  = (float*)(sm + 55296);
    float* OFF = (float*)(sm + 55552);
    if (t < 64) {
        int gi = ocb + t;
        float sc = 1.f, off = Bi[gi];
        if (hasbn) {
            float inv = bg[gi] * rsqrtf(bv[gi] + EPSV);
            sc = inv; off = (Bi[gi] - bm[gi]) * inv + bbp[gi];
        }
        SC[t] = sc; OFF[t] = off;
    }

    float c[2][4][4] = {};
    for (int kc = 0; kc < 4; kc++) {
        __syncthreads();
        #pragma unroll
        for (int p = 0; p < 4; p++) {
            int i = t + p * 256;
            int oc = i >> 4, seg = i & 15;
            float4 v = *(const float4*)(W + (size_t)(ocb + oc) * NC + kc * 64 + seg * 4);
            uint32_t off = oc * 144 + seg * 8;
            *(uint2*)(sm + off)        = make_uint2(pack2(v.x, v.y), pack2(v.z, v.w));
            *(uint2*)(sm + 9216 + off) = make_uint2(pack2lo(v.x, v.y), pack2lo(v.z, v.w));
        }
        #pragma unroll
        for (int p = 0; p < 8; p++) {
            int i = t + p * 256;
            int ic = i >> 5, px4 = (i & 31) * 4;
            float4 v = *(const float4*)(Xb + (size_t)(kc * 64 + ic) * NPIX + n0 + px4);
            float vs[4] = {v.x, v.y, v.z, v.w};
            #pragma unroll
            for (int jj = 0; jj < 4; jj++) {
                uint32_t off = (px4 + jj) * 144 + ic * 2;
                bf16 h = hi_of(vs[jj]);
                *(bf16*)(sm + 18432 + off) = h;
                *(bf16*)(sm + 36864 + off) = lo_of(vs[jj], h);
            }
        }
        __syncthreads();
        const int arow = lane & 15, asel = lane >> 4;
        const int brow = lane & 7,  bsel = (lane >> 3) & 1;
        #pragma unroll
        for (int kb = 0; kb < 32; kb += 8) {
            uint32_t ah[2][4], al[2][4];
            #pragma unroll
            for (int mt = 0; mt < 2; mt++) {
                uint32_t aoff = (wr + mt * 16 + arow) * 144 + (kb + asel * 4) * 4;
                ldsm_x4(ah[mt], sb + aoff);
                ldsm_x4(al[mt], sb + 9216 + aoff);
            }
            #pragma unroll
            for (int nt = 0; nt < 4; nt++) {
                uint32_t boff = (wc + nt * 8 + brow) * 144 + (kb + bsel * 4) * 4;
                uint32_t bh0, bh1, bl0, bl1;
                ldsm_x2(bh0, bh1, sb + 18432 + boff);
                ldsm_x2(bl0, bl1, sb + 36864 + boff);
                #pragma unroll
                for (int mt = 0; mt < 2; mt++) {
                    mma_bf16(c[mt][nt], ah[mt], bh0, bh1);
                    mma_bf16(c[mt][nt], al[mt], bh0, bh1);
                    mma_bf16(c[mt][nt], ah[mt], bl0, bl1);
                }
            }
        }
    }
    __syncthreads();

    float* Tb = (float*)sm;
    #pragma unroll
    for (int mt = 0; mt < 2; mt++)
        #pragma unroll
        for (int nt = 0; nt < 4; nt++)
            #pragma unroll
            for (int i = 0; i < 4; i++) {
                int row = wr + mt * 16 + g + (i >> 1) * 8;
                int col = wc + nt * 8 + tg * 2 + (i & 1);
                Tb[row * 128 + ((col + row) & 127)] = c[mt][nt][i] * SC[row] + OFF[row];
            }
    __syncthreads();

    if (df) {
        float* dst = df + ((size_t)b * CI + co) * NPIX + n0;
        for (int i = t; i < 8192; i += 256) {
            int oc = i >> 7, px = i & 127;
            dst[(size_t)oc * NPIX + px] = Tb[oc * 128 + ((px + oc) & 127)];
        }
    } else if (chanmaj) {
        bf16* dsth = dh + ((size_t)b * CI + co) * NPIX + n0;
        bf16* dstl = dl + ((size_t)b * CI + co) * NPIX + n0;
        for (int i = t; i < 4096; i += 256) {
            int oc = i >> 6, px2 = (i & 63) * 2;
            float v0 = Tb[oc * 128 + ((px2 + oc) & 127)];
            float v1 = Tb[oc * 128 + ((px2 + 1 + oc) & 127)];
            *(uint32_t*)(dsth + (size_t)oc * NPIX + px2) = pack2(v0, v1);
            *(uint32_t*)(dstl + (size_t)oc * NPIX + px2) = pack2lo(v0, v1);
        }
    } else {
        bf16* dsth = dh + ((size_t)b * NPIX + n0) * CI + co;
        bf16* dstl = dl + ((size_t)b * NPIX + n0) * CI + co;
        for (int i = t; i < 4096; i += 256) {
            int px = i >> 5, oc2 = (i & 31) * 2;
            float v0 = Tb[oc2 * 128 + ((px + oc2) & 127)];
            float v1 = Tb[(oc2 + 1) * 128 + ((px + oc2 + 1) & 127)];
            *(uint32_t*)(dsth + (size_t)px * CI + oc2) = pack2(v0, v1);
            *(uint32_t*)(dstl + (size_t)px * CI + oc2) = pack2lo(v0, v1);
        }
    }
}

// ---------------- conv3x3: oc-split (M=64), 256 blocks, 2/SM ----------------
// XH@0 (15840), XL@15840, WH@31680 (5120), WL@36800; total 41920; Tb[64][68] aliases
#define C3_SMEM 41984
__global__ __launch_bounds__(256, 2) void conv3x3_mma(
    const float* __restrict__ bng, const float* __restrict__ bnb,
    const float* __restrict__ bnm, const float* __restrict__ bnv,
    float* __restrict__ outp_all)
{
    extern __shared__ char sm[];
    const int t = threadIdx.x, lane = t & 31, wid = t >> 5;
    const int g = lane >> 2, tg = lane & 3;
    const int y = blockIdx.x, b = blockIdx.y, zh = blockIdx.z;
    const int wr = (wid & 1) * 32, wc = (wid >> 1) * 16;
    const bf16* EQh = g_EQhi + (size_t)b * CI * NPIX;
    const bf16* EQl = g_EQlo + (size_t)b * CI * NPIX;
    const bf16* ESh = g_EShi + (size_t)b * CI * NPIX;
    const bf16* ESl = g_ESlo + (size_t)b * CI * NPIX;
    float* outp = outp_all + (size_t)b * CI * NPIX;
    bf16* XH = (bf16*)(sm);
    bf16* XL = (bf16*)(sm + 15840);
    bf16* WHp = (bf16*)(sm + 31680);
    bf16* WLp = (bf16*)(sm + 36800);
    uint32_t sb = smem_u32(sm);
    const uint32_t aXH = sb, aXL = sb + 15840, aWH = sb + 31680, aWL = sb + 36800;

    float c[2][2][4] = {};
    for (int icc = 0; icc < 8; icc++) {
        for (int i = t; i < 32 * 198; i += 256) {
            int icl = i / 198, np = i - icl * 198;
            int r = np / 66, px = np - r * 66;
            int icg = icc * 32 + icl;
            int rg = y + r - 1, x = px - 1;
            bf16 vh = __ushort_as_bfloat16(0), vl = __ushort_as_bfloat16(0);
            if (rg >= 0 && rg < 64 && x >= 0 && x < 64) {
                size_t gi = (size_t)(icg & 127) * NPIX + rg * 64 + x;
                if (icg < 128) { vh = EQh[gi]; vl = EQl[gi]; }
                else           { vh = ESh[gi]; vl = ESl[gi]; }
            }
            XH[np * 40 + icl] = vh;
            XL[np * 40 + icl] = vl;
        }
        __syncthreads();
        for (int tap = 0; tap < 9; tap++) {
            const int dy = tap / 3, dx = tap - dy * 3;
            for (int i = t; i < 2048; i += 256) {
                int oc = i >> 5, icl = i & 31;
                size_t wi = (size_t)tap * 32768 + (zh * 64 + oc) * 256 + icc * 32 + icl;
                WHp[oc * 40 + icl] = g_W3hi[wi];
                WLp[oc * 40 + icl] = g_W3lo[wi];
            }
            __syncthreads();
            const int arow = lane & 15, asel = lane >> 4;
            const int brow = lane & 7,  bsel = (lane >> 3) & 1;
            #pragma unroll
            for (int kb = 0; kb < 16; kb += 8) {
                uint32_t ah[2][4], al[2][4];
                #pragma unroll
                for (int mt = 0; mt < 2; mt++) {
                    uint32_t aoff = ((wr + mt * 16 + arow) * 20 + kb + asel * 4) * 4;
                    ldsm_x4(ah[mt], aWH + aoff);
                    ldsm_x4(al[mt], aWL + aoff);
                }
                #pragma unroll
                for (int nt = 0; nt < 2; nt++) {
                    uint32_t boff = ((dy * 66 + wc + nt * 8 + brow + dx) * 20 + kb + bsel * 4) * 4;
                    uint32_t bh0, bh1, bl0, bl1;
                    ldsm_x2(bh0, bh1, aXH + boff);
                    ldsm_x2(bl0, bl1, aXL + boff);
                    #pragma unroll
                    for (int mt = 0; mt < 2; mt++) {
                        mma_bf16(c[mt][nt], ah[mt], bh0, bh1);
                        mma_bf16(c[mt][nt], al[mt], bh0, bh1);
                        mma_bf16(c[mt][nt], ah[mt], bl0, bl1);
                    }
                }
            }
            __syncthreads();
        }
    }

    float* Tb = (float*)sm;   // [64][68]
    #pragma unroll
    for (int mt = 0; mt < 2; mt++)
        #pragma unroll
        for (int nt = 0; nt < 2; nt++)
            #pragma unroll
            for (int i = 0; i < 4; i++) {
                int row = wr + mt * 16 + g + (i >> 1) * 8;
                int col = wc + nt * 8 + tg * 2 + (i & 1);
                Tb[row * 68 + col] = c[mt][nt][i];
            }
    __syncthreads();
    for (int i = t; i < 4096; i += 256) {
        int oc = i >> 6, n = i & 63;
        int go = zh * 64 + oc;
        float inv = bng[go] * rsqrtf(bnv[go] + EPSV);
        float off = bnb[go] - bnm[go] * inv;
        outp[(size_t)go * NPIX + y * 64 + n] = fmaxf(Tb[oc * 68 + n] * inv + off, 0.f);
    }
}

// ---------------- launch ----------------
extern "C" void kernel_launch(void* const* d_in, const int* in_sizes, int n_in,
                              void* d_out, int out_size)
{
    (void)in_sizes; (void)n_in; (void)out_size;
    const float* q     = (const float*)d_in[0];
    const float* s     = (const float*)d_in[1];
    const float* scale = (const float*)d_in[2];
    const float* w_v   = (const float*)d_in[3];  const float* b_v  = (const float*)d_in[4];
    const float* w_k1  = (const float*)d_in[5];  const float* b_k1 = (const float*)d_in[6];
    const float* w_q1  = (const float*)d_in[7];  const float* b_q1 = (const float*)d_in[8];
    const float* w_k2  = (const float*)d_in[9];  const float* b_k2 = (const float*)d_in[10];
    const float* w_q2  = (const float*)d_in[11]; const float* b_q2 = (const float*)d_in[12];
    const float* w_ts  = (const float*)d_in[13]; const float* b_ts = (const float*)d_in[14];
    const float* gts   = (const float*)d_in[15]; const float* bets = (const float*)d_in[16];
    const float* mts   = (const float*)d_in[17]; const float* vts  = (const float*)d_in[18];
    const float* w_tq  = (const float*)d_in[19]; const float* b_tq = (const float*)d_in[20];
    const float* gtq   = (const float*)d_in[21]; const float* betq = (const float*)d_in[22];
    const float* mtq   = (const float*)d_in[23]; const float* vtq  = (const float*)d_in[24];
    const float* w_cat = (const float*)d_in[25];
    const float* gcat  = (const float*)d_in[26]; const float* becat= (const float*)d_in[27];
    const float* mcat  = (const float*)d_in[28]; const float* vcat = (const float*)d_in[29];

    float* out  = (float*)d_out;
    float* cpam = out;
    float* Eq   = out + (size_t)NB * CI * NPIX;
    float* Es   = out + 2 * (size_t)NB * CI * NPIX;

    cudaFuncSetAttribute(gemmA_mma,   cudaFuncAttributeMaxDynamicSharedMemorySize, GA_SMEM);
    cudaFuncSetAttribute(pv_mma,      cudaFuncAttributeMaxDynamicSharedMemorySize, PV_SMEM);
    cudaFuncSetAttribute(convs_mma,   cudaFuncAttributeMaxDynamicSharedMemorySize, CV_SMEM);
    cudaFuncSetAttribute(conv3x3_mma, cudaFuncAttributeMaxDynamicSharedMemorySize, C3_SMEM);

    zero_sums<<<(NB * NPIX + 255) / 256, 256>>>();
    w3prep<<<(9 * 128 * 256 + 255) / 256, 256>>>(w_cat);
    convs_mma<<<dim3(32, NB, 12), 256, CV_SMEM>>>(q, s, w_v, b_v, w_k1, b_k1, w_q1, b_q1,
                                                  w_k2, b_k2, w_q2, b_q2, w_ts, b_ts,
                                                  gts, bets, mts, vts, w_tq, b_tq,
                                                  gtq, betq, mtq, vtq);
    gemmA_mma<<<dim3(32, 32, NB), 256, GA_SMEM>>>();
    pv_mma<<<dim3(64, NB, 2), 256, PV_SMEM>>>(scale, Eq, Es);
    conv3x3_mma<<<dim3(64, NB, 2), 256, C3_SMEM>>>(gcat, becat, mcat, vcat, cpam);
}